// round 1
// baseline (speedup 1.0000x reference)
#include <cuda_runtime.h>
#include <math.h>

#define HH 96
#define WW 96
#define HW (HH*WW)

// Scratch (device globals; no allocation allowed)
__device__ float g_t1[2*128*HW];       // conv1 out
__device__ float g_t2[2*128*HW];       // conv2 out
__device__ float g_om[2*216*HW];       // offset/mask raw
__device__ float g_wt[8*9*16*128];     // dcn weights relayout [g][k][c][co]
__device__ float g_fea[2*128*HW];      // dcn out

// ---------------------------------------------------------------------------
// Generic 3x3 conv, pad=1. MODE: 0 = A, 1 = A-B, 2 = concat(A[0:128], B[0:128])
// Tile: 32 out-ch x 16x16 pixels per 256-thread block. ci chunks of 8.
// Thread: 2 co x 16 x-pixels (register sliding window over x).
// ---------------------------------------------------------------------------
template<int MODE, bool RELU>
__global__ __launch_bounds__(256)
void conv3x3_k(const float* __restrict__ A, const float* __restrict__ Bp,
               const float* __restrict__ w, const float* __restrict__ bias,
               float* __restrict__ out, int CIN, int COUT, int nCoT)
{
    __shared__ float s_in[8][18][18];   // [ci][y][x]
    __shared__ float s_w[32][8][9];     // [co][ci][k]

    const int tid = threadIdx.x;
    const int cg  = tid >> 4;           // 0..15 (co pair group)
    const int ty  = tid & 15;           // 0..15 (row)
    const int x0  = blockIdx.x * 16;
    const int y0  = blockIdx.y * 16;
    const int b   = blockIdx.z / nCoT;
    const int cot = blockIdx.z % nCoT;
    const int co0 = cot * 32;

    float acc0[16], acc1[16];
#pragma unroll
    for (int i = 0; i < 16; i++) { acc0[i] = 0.f; acc1[i] = 0.f; }

    for (int cb = 0; cb < CIN; cb += 8) {
        __syncthreads();
        // ---- load input patch 8 x 18 x 18 ----
        for (int idx = tid; idx < 8*18*18; idx += 256) {
            int cil = idx / 324;
            int rem = idx - cil * 324;
            int yy = rem / 18;
            int xx = rem - yy * 18;
            int gy = y0 - 1 + yy;
            int gx = x0 - 1 + xx;
            float v = 0.f;
            if ((unsigned)gy < (unsigned)HH && (unsigned)gx < (unsigned)WW) {
                int ci = cb + cil;
                if (MODE == 1) {
                    int o = ((b*CIN + ci)*HH + gy)*WW + gx;
                    v = A[o] - Bp[o];
                } else if (MODE == 2) {
                    if (ci < 128) v = A[((b*128 + ci)*HH + gy)*WW + gx];
                    else          v = Bp[((b*128 + (ci-128))*HH + gy)*WW + gx];
                } else {
                    v = A[((b*CIN + ci)*HH + gy)*WW + gx];
                }
            }
            ((float*)s_in)[idx] = v;
        }
        // ---- load weights 32 x 8 x 9 ----
        for (int idx = tid; idx < 32*8*9; idx += 256) {
            int col = idx / 72;
            int rem = idx - col * 72;
            int cil = rem / 9;
            int kk  = rem - cil * 9;
            int co  = co0 + col;
            float v = 0.f;
            if (co < COUT) v = w[(co*CIN + (cb + cil))*9 + kk];
            ((float*)s_w)[idx] = v;
        }
        __syncthreads();
        // ---- compute ----
#pragma unroll 2
        for (int cil = 0; cil < 8; cil++) {
#pragma unroll
            for (int ky = 0; ky < 3; ky++) {
                float r[18];
#pragma unroll
                for (int xx = 0; xx < 18; xx++) r[xx] = s_in[cil][ty + ky][xx];
#pragma unroll
                for (int kx = 0; kx < 3; kx++) {
                    float wa = s_w[cg*2 + 0][cil][ky*3 + kx];
                    float wb = s_w[cg*2 + 1][cil][ky*3 + kx];
#pragma unroll
                    for (int x = 0; x < 16; x++) {
                        acc0[x] = fmaf(wa, r[x + kx], acc0[x]);
                        acc1[x] = fmaf(wb, r[x + kx], acc1[x]);
                    }
                }
            }
        }
    }
    // ---- store ----
    const int y = y0 + ty;
    const int co_a = co0 + cg*2;
    const int co_b = co_a + 1;
    if (co_a < COUT) {
        float bv = bias[co_a];
        float* op = &out[((b*COUT + co_a)*HH + y)*WW + x0];
#pragma unroll
        for (int x = 0; x < 16; x++) {
            float v = acc0[x] + bv;
            if (RELU) v = fmaxf(v, 0.f);
            op[x] = v;
        }
    }
    if (co_b < COUT) {
        float bv = bias[co_b];
        float* op = &out[((b*COUT + co_b)*HH + y)*WW + x0];
#pragma unroll
        for (int x = 0; x < 16; x++) {
            float v = acc1[x] + bv;
            if (RELU) v = fmaxf(v, 0.f);
            op[x] = v;
        }
    }
}

// ---------------------------------------------------------------------------
// Relayout DCN weights w[co][g*16+c][k] -> wt[g][k][c][co] (contiguous tiles)
// ---------------------------------------------------------------------------
__global__ void wtrans_k(const float* __restrict__ wd, float* __restrict__ wt)
{
    int idx = blockIdx.x * 256 + threadIdx.x;
    if (idx >= 8*9*16*128) return;
    int co = idx & 127;
    int t  = idx >> 7;        // (g*9+k)*16 + c
    int c  = t & 15;
    int t2 = t >> 4;          // g*9+k
    int k  = t2 % 9;
    int g  = t2 / 9;
    wt[idx] = wd[(co*128 + g*16 + c)*9 + k];
}

// ---------------------------------------------------------------------------
// Fused DCNv2 + bias + relu.
// Block: 256 threads, tile = 32 x-pixels of one row, all 128 out channels.
// Per (g,k): sample 16 channels x 32 pixels into smem, FMA vs smem weights.
// ---------------------------------------------------------------------------
__global__ __launch_bounds__(256)
void dcn_k(const float* __restrict__ R1, const float* __restrict__ om,
           const float* __restrict__ wt, const float* __restrict__ bias,
           float* __restrict__ out)
{
    __shared__ float s_wk[2048];        // [c][co=128]
    __shared__ float sval[16][36];      // [c][px] (pad to 36 for LDS.128 alignment)

    const int tid    = threadIdx.x;
    const int x0     = blockIdx.x * 32;
    const int h      = blockIdx.y;
    const int b      = blockIdx.z;
    const int px_s   = tid & 31;        // sampling pixel
    const int cpair  = tid >> 5;        // sampling channel pair (0..7)
    const int co_grp = tid >> 3;        // 0..31 -> co = co_grp*4..+3
    const int px_grp = tid & 7;         // 0..7  -> px = px_grp*4..+3
    const int gx     = x0 + px_s;

    float acc[4][4];
#pragma unroll
    for (int i = 0; i < 4; i++)
#pragma unroll
        for (int j = 0; j < 4; j++) acc[i][j] = 0.f;

    for (int g = 0; g < 8; g++) {
        for (int k = 0; k < 9; k++) {
            __syncthreads();
            // ---- weights for this (g,k): contiguous 2048 floats ----
            const float* wsrc = &wt[(g*9 + k) * 2048];
#pragma unroll
            for (int i = 0; i < 8; i++) s_wk[tid + i*256] = wsrc[tid + i*256];

            // ---- bilinear sampling: this thread -> 2 channels at pixel px_s ----
            {
                const int ky = k / 3, kx = k % 3;
                const int obase = (b*216*HH + h)*WW + gx;
                float dy = om[obase + (18*g + 2*k    ) * HW];
                float dx = om[obase + (18*g + 2*k + 1) * HW];
                float mr = om[obase + (144 + 9*g + k ) * HW];
                float m  = 1.f / (1.f + expf(-mr));
                float py  = dy + (float)(ky + h - 1);
                float pxx = dx + (float)(kx + gx - 1);
                float fy = floorf(py), fx = floorf(pxx);
                float ly = py - fy,  lx = pxx - fx;
                int   yi = (int)fy,  xi = (int)fx;
                float w00 = (1.f-ly)*(1.f-lx)*m;
                float w01 = (1.f-ly)*lx*m;
                float w10 = ly*(1.f-lx)*m;
                float w11 = ly*lx*m;
                bool iy0 = (unsigned)yi     < (unsigned)HH;
                bool iy1 = (unsigned)(yi+1) < (unsigned)HH;
                bool ix0 = (unsigned)xi     < (unsigned)WW;
                bool ix1 = (unsigned)(xi+1) < (unsigned)WW;
#pragma unroll
                for (int j = 0; j < 2; j++) {
                    int c = cpair*2 + j;
                    const float* base = &R1[(b*128 + g*16 + c) * HW];
                    float v = 0.f;
                    if (iy0 && ix0) v = fmaf(w00, base[yi*WW + xi],         v);
                    if (iy0 && ix1) v = fmaf(w01, base[yi*WW + xi + 1],     v);
                    if (iy1 && ix0) v = fmaf(w10, base[(yi+1)*WW + xi],     v);
                    if (iy1 && ix1) v = fmaf(w11, base[(yi+1)*WW + xi + 1], v);
                    sval[c][px_s] = v;
                }
            }
            __syncthreads();
            // ---- accumulate: acc[co][px] += w[co] * v[px] over 16 channels ----
#pragma unroll
            for (int c = 0; c < 16; c++) {
                float4 wv = *(const float4*)&s_wk[c*128 + co_grp*4];
                float4 vv = *(const float4*)&sval[c][px_grp*4];
                acc[0][0] = fmaf(wv.x, vv.x, acc[0][0]);
                acc[0][1] = fmaf(wv.x, vv.y, acc[0][1]);
                acc[0][2] = fmaf(wv.x, vv.z, acc[0][2]);
                acc[0][3] = fmaf(wv.x, vv.w, acc[0][3]);
                acc[1][0] = fmaf(wv.y, vv.x, acc[1][0]);
                acc[1][1] = fmaf(wv.y, vv.y, acc[1][1]);
                acc[1][2] = fmaf(wv.y, vv.z, acc[1][2]);
                acc[1][3] = fmaf(wv.y, vv.w, acc[1][3]);
                acc[2][0] = fmaf(wv.z, vv.x, acc[2][0]);
                acc[2][1] = fmaf(wv.z, vv.y, acc[2][1]);
                acc[2][2] = fmaf(wv.z, vv.z, acc[2][2]);
                acc[2][3] = fmaf(wv.z, vv.w, acc[2][3]);
                acc[3][0] = fmaf(wv.w, vv.x, acc[3][0]);
                acc[3][1] = fmaf(wv.w, vv.y, acc[3][1]);
                acc[3][2] = fmaf(wv.w, vv.z, acc[3][2]);
                acc[3][3] = fmaf(wv.w, vv.w, acc[3][3]);
            }
        }
    }
    // ---- bias + relu + store ----
#pragma unroll
    for (int ci = 0; ci < 4; ci++) {
        int co = co_grp*4 + ci;
        float bv = bias[co];
#pragma unroll
        for (int pj = 0; pj < 4; pj++) {
            int px = px_grp*4 + pj;
            out[(b*128 + co)*HW + h*WW + x0 + px] = fmaxf(acc[ci][pj] + bv, 0.f);
        }
    }
}

// ---------------------------------------------------------------------------
extern "C" void kernel_launch(void* const* d_in, const int* in_sizes, int n_in,
                              void* d_out, int out_size)
{
    (void)in_sizes; (void)n_in; (void)out_size;
    const float* R1    = (const float*)d_in[0];
    const float* Q0    = (const float*)d_in[1];
    const float* w1    = (const float*)d_in[2];
    const float* b1    = (const float*)d_in[3];
    const float* w2    = (const float*)d_in[4];
    const float* b2    = (const float*)d_in[5];
    const float* w_om  = (const float*)d_in[6];
    const float* b_om  = (const float*)d_in[7];
    const float* w_dcn = (const float*)d_in[8];
    const float* b_dcn = (const float*)d_in[9];
    const float* w_rq  = (const float*)d_in[10];
    const float* b_rq  = (const float*)d_in[11];
    float* out = (float*)d_out;

    float *t1, *t2, *om, *wt, *fea;
    cudaGetSymbolAddress((void**)&t1,  g_t1);
    cudaGetSymbolAddress((void**)&t2,  g_t2);
    cudaGetSymbolAddress((void**)&om,  g_om);
    cudaGetSymbolAddress((void**)&wt,  g_wt);
    cudaGetSymbolAddress((void**)&fea, g_fea);

    dim3 blk(256);
    // conv1: relu(conv(R1-Q0))          128 -> 128
    conv3x3_k<1, true ><<<dim3(6, 6,  8), blk>>>(R1, Q0, w1, b1, t1, 128, 128, 4);
    // conv2: relu(conv(t1))             128 -> 128
    conv3x3_k<0, true ><<<dim3(6, 6,  8), blk>>>(t1, nullptr, w2, b2, t2, 128, 128, 4);
    // conv_om: conv(t2)                 128 -> 216
    conv3x3_k<0, false><<<dim3(6, 6, 14), blk>>>(t2, nullptr, w_om, b_om, om, 128, 216, 7);
    // dcn weight relayout
    wtrans_k<<<576, blk>>>(w_dcn, wt);
    // deformable conv v2 + relu
    dcn_k<<<dim3(3, 96, 2), blk>>>(R1, om, wt, b_dcn, fea);
    // conv_rq: relu(conv(concat(fea, Q0)))  256 -> 128
    conv3x3_k<2, true ><<<dim3(6, 6,  8), blk>>>(fea, Q0, w_rq, b_rq, out, 256, 128, 4);
}

// round 3
// speedup vs baseline: 1.5729x; 1.5729x over previous
#include <cuda_runtime.h>
#include <cuda_bf16.h>
#include <math.h>
#include <cstdint>

#define HH 96
#define WW 96
#define HW (HH*WW)

// ======================= helpers =======================
__device__ __forceinline__ uint32_t smem_u32(const void* p) {
    uint32_t a;
    asm("{ .reg .u64 t; cvta.to.shared.u64 t, %1; cvt.u32.u64 %0, t; }" : "=r"(a) : "l"(p));
    return a;
}
__device__ __forceinline__ void cp_async16(uint32_t saddr, const void* g) {
    asm volatile("cp.async.cg.shared.global [%0], [%1], 16;" :: "r"(saddr), "l"(g));
}
__device__ __forceinline__ uint32_t lds32(uint32_t a) {
    uint32_t v; asm volatile("ld.shared.b32 %0, [%1];" : "=r"(v) : "r"(a)); return v;
}
__device__ __forceinline__ void mma_bf16(float* c, const uint32_t* a, const uint32_t* b) {
    asm volatile("mma.sync.aligned.m16n8k16.row.col.f32.bf16.bf16.f32 "
        "{%0,%1,%2,%3}, {%4,%5,%6,%7}, {%8,%9}, {%0,%1,%2,%3};"
        : "+f"(c[0]), "+f"(c[1]), "+f"(c[2]), "+f"(c[3])
        : "r"(a[0]), "r"(a[1]), "r"(a[2]), "r"(a[3]), "r"(b[0]), "r"(b[1]));
}

// ======================= scratch globals =======================
__device__ float g_t1[2*128*HW];
__device__ float g_t2[2*128*HW];
__device__ float g_om[2*216*HW];
__device__ float g_wt[8*9*16*128];                  // DCN weights [g][k][c][co]
__device__ float g_fea[2*128*HW];
// packed conv weights: per (chunk,tap) block of 18432 bytes = 4608 floats
// block layout: [hi: 128co x 36ci bf16][lo: 128co x 36ci bf16] (ci 32 real + 4 pad)
__device__ __align__(128) float g_wp1[36*4608];
__device__ __align__(128) float g_wp2[36*4608];
__device__ __align__(128) float g_wpom[72*4608];    // 2 co-tiles x 36 blocks
__device__ __align__(128) float g_wprq[72*4608];    // 8 chunks x 9 taps

// ============================================================================
// Weight prepack: w[co][ci][9] -> per (chunk,tap) bf16 hi/lo B-tile image.
// ============================================================================
__global__ void prepack_k(const float* __restrict__ w, float* __restrict__ dst,
                          int CIN, int COUT, int co0)
{
    const int blk = blockIdx.x;
    const int cb  = blk / 9;
    const int tap = blk % 9;
    char* d = (char*)dst + (size_t)blk * 18432;
    for (int e = threadIdx.x; e < 4608; e += 256) {
        int co = e / 36;
        int cl = e - co * 36;
        float v = 0.f;
        if (cl < 32 && (co0 + co) < COUT)
            v = w[((size_t)(co0 + co) * CIN + cb * 32 + cl) * 9 + tap];
        __nv_bfloat16 hi = __float2bfloat16(v);
        __nv_bfloat16 lo = __float2bfloat16(v - __bfloat162float(hi));
        *(__nv_bfloat16*)(d + co * 72 + cl * 2)        = hi;
        *(__nv_bfloat16*)(d + 9216 + co * 72 + cl * 2) = lo;
    }
}

// ============================================================================
// Tensor-core 3x3 conv via mma.sync bf16 (3-term hi/lo split, fp32 accum).
// CTA: 256 thr, tile M=128 px (16x8) x N=128 co. Warp tile 64x32.
// MODE: 0 = A, 1 = A-B, 2 = concat(A[0:128], B[0:128])
// ============================================================================
#define SM_HI    0
#define SM_LO    23328
#define SM_B     46656
#define SM_STAGE 18432
#define CONV_SMEM (46656 + 3*18432)   // 101952

template<int MODE, bool RELU>
__global__ __launch_bounds__(256, 1)
void convMMA_k(const float* __restrict__ A, const float* __restrict__ Bp,
               const float* __restrict__ wpack, const float* __restrict__ bias,
               float* __restrict__ out, int CIN, int COUT, int co0, int nchunk)
{
    extern __shared__ char sm[];
    const int tid    = threadIdx.x;
    const int lane   = tid & 31;
    const int wid    = tid >> 5;
    const int warp_m = wid & 1;        // 2 M-halves of 64 px
    const int warp_n = wid >> 1;       // 4 N-quarters of 32 co
    const int qr     = lane >> 2;      // 0..7
    const int qc     = lane & 3;       // 0..3
    const int x0     = blockIdx.x * 16;
    const int y0     = blockIdx.y * 8;
    const int b      = blockIdx.z;

    const uint32_t sbase = smem_u32(sm);

    float acc[4][4][4];
#pragma unroll
    for (int i = 0; i < 4; i++)
#pragma unroll
        for (int j = 0; j < 4; j++)
#pragma unroll
            for (int k = 0; k < 4; k++) acc[i][j][k] = 0.f;

    const int niter = nchunk * 9;

    // prefetch B blocks for iters 0 and 1
#pragma unroll
    for (int it = 0; it < 2; it++) {
        const char* src = (const char*)wpack + (size_t)it * 18432;
        uint32_t dstb = sbase + SM_B + (uint32_t)it * SM_STAGE;
#pragma unroll
        for (int i = 0; i < 5; i++) {
            int idx = tid + i * 256;
            if (idx < 1152) cp_async16(dstb + idx * 16, src + idx * 16);
        }
        asm volatile("cp.async.commit_group;");
    }

    for (int iter = 0; iter < niter; iter++) {
        const int cb  = iter / 9;
        const int tap = iter - cb * 9;

        asm volatile("cp.async.wait_group 1;");
        __syncthreads();

        // ---- load A halo chunk (32 ci) at chunk boundary ----
        if (tap == 0) {
            for (int idx = tid; idx < 32*18*18; idx += 256) {
                int ci  = idx / 324;
                int rem = idx - ci * 324;
                int yy  = rem / 18;
                int xx  = rem - yy * 18;
                int gy  = y0 - 1 + yy;
                int gx  = x0 - 1 + xx;
                float v = 0.f;
                if ((unsigned)gy < (unsigned)HH && (unsigned)gx < (unsigned)WW) {
                    if (MODE == 1) {
                        size_t o = ((size_t)(b*CIN + cb*32 + ci))*HW + gy*WW + gx;
                        v = A[o] - Bp[o];
                    } else if (MODE == 2) {
                        int cg = cb*32 + ci;
                        if (cg < 128) v = A[((size_t)(b*128 + cg))*HW + gy*WW + gx];
                        else          v = Bp[((size_t)(b*128 + cg - 128))*HW + gy*WW + gx];
                    } else {
                        v = A[((size_t)(b*CIN + cb*32 + ci))*HW + gy*WW + gx];
                    }
                }
                __nv_bfloat16 hi = __float2bfloat16(v);
                __nv_bfloat16 lo = __float2bfloat16(v - __bfloat162float(hi));
                int off = ((yy*18 + xx)*36 + ci)*2;
                *(__nv_bfloat16*)(sm + SM_HI + off) = hi;
                *(__nv_bfloat16*)(sm + SM_LO + off) = lo;
            }
            __syncthreads();
        }

        // ---- prefetch B for iter+2 ----
        if (iter + 2 < niter) {
            const char* src = (const char*)wpack + (size_t)(iter + 2) * 18432;
            uint32_t dstb = sbase + SM_B + (uint32_t)((iter + 2) % 3) * SM_STAGE;
#pragma unroll
            for (int i = 0; i < 5; i++) {
                int idx = tid + i * 256;
                if (idx < 1152) cp_async16(dstb + idx * 16, src + idx * 16);
            }
        }
        asm volatile("cp.async.commit_group;");

        // ---- compute ----
        const int ky = tap / 3, kx = tap % 3;
        const uint32_t bbase = sbase + SM_B + (uint32_t)(iter % 3) * SM_STAGE;
        const uint32_t hbase = sbase + SM_HI;
        const uint32_t lbase = sbase + SM_LO;

#pragma unroll
        for (int ks = 0; ks < 2; ks++) {
            const int k0 = ks * 16 + qc * 2;
            uint32_t bh[4][2], bl[4][2];
#pragma unroll
            for (int nf = 0; nf < 4; nf++) {
                uint32_t ba = bbase + (uint32_t)(warp_n*32 + nf*8 + qr)*72 + k0*2;
                bh[nf][0] = lds32(ba);
                bh[nf][1] = lds32(ba + 16);
                bl[nf][0] = lds32(ba + 9216);
                bl[nf][1] = lds32(ba + 9216 + 16);
            }
#pragma unroll
            for (int mf = 0; mf < 4; mf++) {
                const int y  = warp_m*4 + mf;
                const uint32_t r1 = (uint32_t)(((y+ky)*18 + qr + kx)*72 + k0*2);
                const uint32_t r2 = r1 + 8*72;
                uint32_t ah[4], al[4];
                ah[0] = lds32(hbase + r1);  ah[1] = lds32(hbase + r2);
                ah[2] = lds32(hbase + r1 + 16); ah[3] = lds32(hbase + r2 + 16);
                al[0] = lds32(lbase + r1);  al[1] = lds32(lbase + r2);
                al[2] = lds32(lbase + r1 + 16); al[3] = lds32(lbase + r2 + 16);
#pragma unroll
                for (int nf = 0; nf < 4; nf++) {
                    mma_bf16(acc[mf][nf], ah, bh[nf]);
                    mma_bf16(acc[mf][nf], ah, bl[nf]);
                    mma_bf16(acc[mf][nf], al, bh[nf]);
                }
            }
        }
    }

    // ---- epilogue: direct store ----
#pragma unroll
    for (int nf = 0; nf < 4; nf++) {
        const int co_a = co0 + warp_n*32 + nf*8 + qc*2;
        const int co_b = co_a + 1;
        float ba_ = (co_a < COUT) ? bias[co_a] : 0.f;
        float bb_ = (co_b < COUT) ? bias[co_b] : 0.f;
#pragma unroll
        for (int mf = 0; mf < 4; mf++) {
            const int y  = y0 + warp_m*4 + mf;
            const int x1 = x0 + qr;
            const int x2 = x1 + 8;
            float v0 = acc[mf][nf][0] + ba_;
            float v1 = acc[mf][nf][1] + bb_;
            float v2 = acc[mf][nf][2] + ba_;
            float v3 = acc[mf][nf][3] + bb_;
            if (RELU) {
                v0 = fmaxf(v0, 0.f); v1 = fmaxf(v1, 0.f);
                v2 = fmaxf(v2, 0.f); v3 = fmaxf(v3, 0.f);
            }
            if (co_a < COUT) {
                out[((size_t)(b*COUT + co_a)*HH + y)*WW + x1] = v0;
                out[((size_t)(b*COUT + co_a)*HH + y)*WW + x2] = v2;
            }
            if (co_b < COUT) {
                out[((size_t)(b*COUT + co_b)*HH + y)*WW + x1] = v1;
                out[((size_t)(b*COUT + co_b)*HH + y)*WW + x2] = v3;
            }
        }
    }
}

// ============================================================================
// DCN weight relayout w[co][g*16+c][k] -> wt[g][k][c][co]
// ============================================================================
__global__ void wtrans_k(const float* __restrict__ wd, float* __restrict__ wt)
{
    int idx = blockIdx.x * 256 + threadIdx.x;
    if (idx >= 8*9*16*128) return;
    int co = idx & 127;
    int t  = idx >> 7;
    int c  = t & 15;
    int t2 = t >> 4;
    int k  = t2 % 9;
    int g  = t2 / 9;
    wt[idx] = wd[(co*128 + g*16 + c)*9 + k];
}

// ============================================================================
// Fused DCNv2 + bias + relu (scalar fp32)
// ============================================================================
__global__ __launch_bounds__(256)
void dcn_k(const float* __restrict__ R1, const float* __restrict__ om,
           const float* __restrict__ wt, const float* __restrict__ bias,
           float* __restrict__ out)
{
    __shared__ float s_wk[2048];
    __shared__ float sval[16][36];

    const int tid    = threadIdx.x;
    const int x0     = blockIdx.x * 32;
    const int h      = blockIdx.y;
    const int b      = blockIdx.z;
    const int px_s   = tid & 31;
    const int cpair  = tid >> 5;
    const int co_grp = tid >> 3;
    const int px_grp = tid & 7;
    const int gx     = x0 + px_s;

    float acc[4][4];
#pragma unroll
    for (int i = 0; i < 4; i++)
#pragma unroll
        for (int j = 0; j < 4; j++) acc[i][j] = 0.f;

    for (int g = 0; g < 8; g++) {
        for (int k = 0; k < 9; k++) {
            __syncthreads();
            const float* wsrc = &wt[(g*9 + k) * 2048];
#pragma unroll
            for (int i = 0; i < 8; i++) s_wk[tid + i*256] = wsrc[tid + i*256];
            {
                const int ky = k / 3, kx = k % 3;
                const int obase = (b*216*HH + h)*WW + gx;
                float dy = om[obase + (18*g + 2*k    ) * HW];
                float dx = om[obase + (18*g + 2*k + 1) * HW];
                float mr = om[obase + (144 + 9*g + k ) * HW];
                float m  = 1.f / (1.f + expf(-mr));
                float py  = dy + (float)(ky + h - 1);
                float pxx = dx + (float)(kx + gx - 1);
                float fy = floorf(py), fx = floorf(pxx);
                float ly = py - fy,  lx = pxx - fx;
                int   yi = (int)fy,  xi = (int)fx;
                float w00 = (1.f-ly)*(1.f-lx)*m;
                float w01 = (1.f-ly)*lx*m;
                float w10 = ly*(1.f-lx)*m;
                float w11 = ly*lx*m;
                bool iy0 = (unsigned)yi     < (unsigned)HH;
                bool iy1 = (unsigned)(yi+1) < (unsigned)HH;
                bool ix0 = (unsigned)xi     < (unsigned)WW;
                bool ix1 = (unsigned)(xi+1) < (unsigned)WW;
#pragma unroll
                for (int j = 0; j < 2; j++) {
                    int c = cpair*2 + j;
                    const float* base = &R1[(b*128 + g*16 + c) * HW];
                    float v = 0.f;
                    if (iy0 && ix0) v = fmaf(w00, base[yi*WW + xi],         v);
                    if (iy0 && ix1) v = fmaf(w01, base[yi*WW + xi + 1],     v);
                    if (iy1 && ix0) v = fmaf(w10, base[(yi+1)*WW + xi],     v);
                    if (iy1 && ix1) v = fmaf(w11, base[(yi+1)*WW + xi + 1], v);
                    sval[c][px_s] = v;
                }
            }
            __syncthreads();
#pragma unroll
            for (int c = 0; c < 16; c++) {
                float4 wv = *(const float4*)&s_wk[c*128 + co_grp*4];
                float4 vv = *(const float4*)&sval[c][px_grp*4];
                acc[0][0] = fmaf(wv.x, vv.x, acc[0][0]);
                acc[0][1] = fmaf(wv.x, vv.y, acc[0][1]);
                acc[0][2] = fmaf(wv.x, vv.z, acc[0][2]);
                acc[0][3] = fmaf(wv.x, vv.w, acc[0][3]);
                acc[1][0] = fmaf(wv.y, vv.x, acc[1][0]);
                acc[1][1] = fmaf(wv.y, vv.y, acc[1][1]);
                acc[1][2] = fmaf(wv.y, vv.z, acc[1][2]);
                acc[1][3] = fmaf(wv.y, vv.w, acc[1][3]);
                acc[2][0] = fmaf(wv.z, vv.x, acc[2][0]);
                acc[2][1] = fmaf(wv.z, vv.y, acc[2][1]);
                acc[2][2] = fmaf(wv.z, vv.z, acc[2][2]);
                acc[2][3] = fmaf(wv.z, vv.w, acc[2][3]);
                acc[3][0] = fmaf(wv.w, vv.x, acc[3][0]);
                acc[3][1] = fmaf(wv.w, vv.y, acc[3][1]);
                acc[3][2] = fmaf(wv.w, vv.z, acc[3][2]);
                acc[3][3] = fmaf(wv.w, vv.w, acc[3][3]);
            }
        }
    }
#pragma unroll
    for (int ci = 0; ci < 4; ci++) {
        int co = co_grp*4 + ci;
        float bv = bias[co];
#pragma unroll
        for (int pj = 0; pj < 4; pj++) {
            int px = px_grp*4 + pj;
            out[(b*128 + co)*HW + h*WW + x0 + px] = fmaxf(acc[ci][pj] + bv, 0.f);
        }
    }
}

// ============================================================================
extern "C" void kernel_launch(void* const* d_in, const int* in_sizes, int n_in,
                              void* d_out, int out_size)
{
    (void)in_sizes; (void)n_in; (void)out_size;
    const float* R1    = (const float*)d_in[0];
    const float* Q0    = (const float*)d_in[1];
    const float* w1    = (const float*)d_in[2];
    const float* b1    = (const float*)d_in[3];
    const float* w2    = (const float*)d_in[4];
    const float* b2    = (const float*)d_in[5];
    const float* w_om  = (const float*)d_in[6];
    const float* b_om  = (const float*)d_in[7];
    const float* w_dcn = (const float*)d_in[8];
    const float* b_dcn = (const float*)d_in[9];
    const float* w_rq  = (const float*)d_in[10];
    const float* b_rq  = (const float*)d_in[11];
    float* out = (float*)d_out;

    float *t1, *t2, *om, *wt, *fea, *wp1, *wp2, *wpom, *wprq;
    cudaGetSymbolAddress((void**)&t1,   g_t1);
    cudaGetSymbolAddress((void**)&t2,   g_t2);
    cudaGetSymbolAddress((void**)&om,   g_om);
    cudaGetSymbolAddress((void**)&wt,   g_wt);
    cudaGetSymbolAddress((void**)&fea,  g_fea);
    cudaGetSymbolAddress((void**)&wp1,  g_wp1);
    cudaGetSymbolAddress((void**)&wp2,  g_wp2);
    cudaGetSymbolAddress((void**)&wpom, g_wpom);
    cudaGetSymbolAddress((void**)&wprq, g_wprq);

    cudaFuncSetAttribute(convMMA_k<0,true >, cudaFuncAttributeMaxDynamicSharedMemorySize, CONV_SMEM);
    cudaFuncSetAttribute(convMMA_k<0,false>, cudaFuncAttributeMaxDynamicSharedMemorySize, CONV_SMEM);
    cudaFuncSetAttribute(convMMA_k<1,true >, cudaFuncAttributeMaxDynamicSharedMemorySize, CONV_SMEM);
    cudaFuncSetAttribute(convMMA_k<2,true >, cudaFuncAttributeMaxDynamicSharedMemorySize, CONV_SMEM);

    // ---- weight prepacks ----
    prepack_k<<<36, 256>>>(w1,   wp1,          128, 128, 0);
    prepack_k<<<36, 256>>>(w2,   wp2,          128, 128, 0);
    prepack_k<<<36, 256>>>(w_om, wpom,         128, 216, 0);
    prepack_k<<<36, 256>>>(w_om, wpom+36*4608, 128, 216, 128);
    prepack_k<<<72, 256>>>(w_rq, wprq,         256, 128, 0);
    wtrans_k<<<576, 256>>>(w_dcn, wt);

    dim3 cgrid(6, 12, 2);
    // conv1: relu(conv(R1-Q0))  128->128
    convMMA_k<1,true ><<<cgrid, 256, CONV_SMEM>>>(R1, Q0, wp1, b1, t1, 128, 128, 0, 4);
    // conv2: relu(conv(t1))     128->128
    convMMA_k<0,true ><<<cgrid, 256, CONV_SMEM>>>(t1, nullptr, wp2, b2, t2, 128, 128, 0, 4);
    // conv_om: conv(t2)         128->216 (two co tiles)
    convMMA_k<0,false><<<cgrid, 256, CONV_SMEM>>>(t2, nullptr, wpom,          b_om, om, 128, 216, 0,   4);
    convMMA_k<0,false><<<cgrid, 256, CONV_SMEM>>>(t2, nullptr, wpom+36*4608,  b_om, om, 128, 216, 128, 4);
    // deformable conv v2 + relu
    dcn_k<<<dim3(3, 96, 2), 256>>>(R1, om, wt, b_dcn, fea);
    // conv_rq: relu(conv(concat(fea, Q0)))  256->128
    convMMA_k<2,true ><<<cgrid, 256, CONV_SMEM>>>(fea, Q0, wprq, b_rq, out, 256, 128, 0, 8);
}

// round 5
// speedup vs baseline: 2.1646x; 1.3762x over previous
#include <cuda_runtime.h>
#include <cuda_bf16.h>
#include <math.h>
#include <cstdint>

#define HH 96
#define WW 96
#define HW (HH*WW)

// ======================= helpers =======================
__device__ __forceinline__ uint32_t smem_u32(const void* p) {
    uint32_t a;
    asm("{ .reg .u64 t; cvta.to.shared.u64 t, %1; cvt.u32.u64 %0, t; }" : "=r"(a) : "l"(p));
    return a;
}
__device__ __forceinline__ void cp_async16(uint32_t saddr, const void* g) {
    asm volatile("cp.async.cg.shared.global [%0], [%1], 16;" :: "r"(saddr), "l"(g));
}
__device__ __forceinline__ void ldsm_x4(uint32_t* r, uint32_t a) {
    asm volatile("ldmatrix.sync.aligned.m8n8.x4.shared.b16 {%0,%1,%2,%3}, [%4];"
        : "=r"(r[0]), "=r"(r[1]), "=r"(r[2]), "=r"(r[3]) : "r"(a));
}
__device__ __forceinline__ void mma_bf16(float* c, const uint32_t* a, const uint32_t* b) {
    asm volatile("mma.sync.aligned.m16n8k16.row.col.f32.bf16.bf16.f32 "
        "{%0,%1,%2,%3}, {%4,%5,%6,%7}, {%8,%9}, {%0,%1,%2,%3};"
        : "+f"(c[0]), "+f"(c[1]), "+f"(c[2]), "+f"(c[3])
        : "r"(a[0]), "r"(a[1]), "r"(a[2]), "r"(a[3]), "r"(b[0]), "r"(b[1]));
}

// ======================= scratch globals =======================
__device__ float g_t1[2*128*HW];
__device__ float g_t2[2*128*HW];
__device__ float g_om[2*216*HW];
__device__ float g_wt[8*9*16*128];                  // DCN weights [g][k][c][co]
__device__ float g_fea[2*128*HW];
// packed conv weights: per (chunk,tap) block 20480 B = 5120 floats
// block: [hi: 128co x 40ci bf16 (ci 32 real + 8 pad)][lo: same]
__device__ __align__(128) float g_wp1[36*5120];
__device__ __align__(128) float g_wp2[36*5120];
__device__ __align__(128) float g_wpom[72*5120];    // 2 co-tiles x 36 blocks
__device__ __align__(128) float g_wprq[72*5120];    // 8 chunks x 9 taps

// ============================================================================
// Merged prepack: all conv weight packs + DCN weight relayout in ONE launch.
// ============================================================================
__device__ __forceinline__ void pack_block(const float* __restrict__ w,
                                           float* __restrict__ dst,
                                           int CIN, int COUT, int co0,
                                           int cb, int tap)
{
    char* d = (char*)dst;
    for (int e = threadIdx.x; e < 128*40; e += 256) {
        int co = e / 40;
        int cl = e - co * 40;
        float v = 0.f;
        if (cl < 32 && (co0 + co) < COUT)
            v = w[((size_t)(co0 + co) * CIN + cb * 32 + cl) * 9 + tap];
        __nv_bfloat16 hi = __float2bfloat16(v);
        __nv_bfloat16 lo = __float2bfloat16(v - __bfloat162float(hi));
        *(__nv_bfloat16*)(d +         co * 80 + cl * 2) = hi;
        *(__nv_bfloat16*)(d + 10240 + co * 80 + cl * 2) = lo;
    }
}

__global__ void prepack_all_k(const float* __restrict__ w1,
                              const float* __restrict__ w2,
                              const float* __restrict__ w_om,
                              const float* __restrict__ w_rq,
                              const float* __restrict__ w_dcn,
                              float* __restrict__ wp1, float* __restrict__ wp2,
                              float* __restrict__ wpom, float* __restrict__ wprq,
                              float* __restrict__ wt)
{
    const int blk = blockIdx.x;
    if (blk < 36) {
        pack_block(w1, wp1 + (size_t)blk*5120, 128, 128, 0, blk/9, blk%9);
    } else if (blk < 72) {
        int b2 = blk - 36;
        pack_block(w2, wp2 + (size_t)b2*5120, 128, 128, 0, b2/9, b2%9);
    } else if (blk < 108) {
        int b2 = blk - 72;
        pack_block(w_om, wpom + (size_t)b2*5120, 128, 216, 0, b2/9, b2%9);
    } else if (blk < 144) {
        int b2 = blk - 108;
        pack_block(w_om, wpom + (size_t)(36 + b2)*5120, 128, 216, 128, b2/9, b2%9);
    } else if (blk < 216) {
        int b2 = blk - 144;
        pack_block(w_rq, wprq + (size_t)b2*5120, 256, 128, 0, b2/9, b2%9);
    } else {
        int base = (blk - 216) * 4096;
        for (int i = threadIdx.x; i < 4096; i += 256) {
            int idx = base + i;
            int co = idx & 127;
            int t  = idx >> 7;
            int c  = t & 15;
            int t2 = t >> 4;
            int k  = t2 % 9;
            int g  = t2 / 9;
            wt[idx] = w_dcn[(co*128 + g*16 + c)*9 + k];
        }
    }
}

// ============================================================================
// Tensor-core 3x3 conv via mma.sync bf16 (3-term hi/lo, fp32 accum), ldmatrix.
// CTA: 256 thr, tile M=64 px (8x8) x N=128 co. Warp tile 32px x 32co.
// smem: A hi [100px][40ci] bf16 (8000B) | A lo (8000B) | B ring 2 x 20480B
// MODE: 0 = A, 1 = A-B, 2 = concat(A[0:128], B[0:128])
// grid.z encodes (b, cot): z = b*ncot + cot ; co0 = cot*128
// ============================================================================
#define SMA_LO   8000
#define SMB      16000
#define SMB_ST   20480
#define CONV_SMEM (16000 + 2*20480)   // 56960

template<int MODE, bool RELU>
__global__ __launch_bounds__(256, 2)
void convMMA_k(const float* __restrict__ A, const float* __restrict__ Bp,
               const float* __restrict__ wpack0, const float* __restrict__ bias,
               float* __restrict__ out, int CIN, int COUT, int ncot, int nchunk)
{
    extern __shared__ char sm[];
    const int tid    = threadIdx.x;
    const int lane   = tid & 31;
    const int wid    = tid >> 5;
    const int warp_m = wid & 1;        // 2 M-halves of 32 px
    const int warp_n = wid >> 1;       // 4 N-quarters of 32 co
    const int x0     = blockIdx.x * 8;
    const int y0     = blockIdx.y * 8;
    const int b      = blockIdx.z / ncot;
    const int cot    = blockIdx.z % ncot;
    const int co0    = cot * 128;
    const float* wpack = wpack0 + (size_t)cot * nchunk * 9 * 5120;

    const uint32_t sbase = smem_u32(sm);
    const uint32_t smA   = sbase;
    const uint32_t smAlo = sbase + SMA_LO;
    const uint32_t smB   = sbase + SMB;

    // per-lane ldmatrix address components
    // A (row-major 16x16): m0 rows0-7/k0-7, m1 rows8-15/k0-7, m2 rows0-7/k8-15, m3 rows8-15/k8-15
    const int dyL  = (lane >> 3) & 1;
    const int xL   = lane & 7;
    const int kAL  = (lane & 16) ? 16 : 0;
    const uint32_t aoffL = (uint32_t)((dyL*10 + xL)*80 + kAL) + (uint32_t)warp_m*3200u;
    // B ([n][k] rows, non-trans): m0 n0-7/k0-7, m1 n0-7/k8-15, m2 n8-15/k0-7, m3 n8-15/k8-15
    const int colL = (lane & 7) + ((lane & 16) ? 8 : 0);
    const int kBL  = (lane & 8) ? 16 : 0;
    const uint32_t boffL = (uint32_t)((warp_n*32 + colL)*80 + kBL);

    float acc[2][4][4];
#pragma unroll
    for (int i = 0; i < 2; i++)
#pragma unroll
        for (int j = 0; j < 4; j++)
#pragma unroll
            for (int k = 0; k < 4; k++) acc[i][j][k] = 0.f;

    const int niter = nchunk * 9;

    // prefetch B block 0 into stage 0
    {
        const char* src = (const char*)wpack;
#pragma unroll
        for (int i = 0; i < 5; i++)
            cp_async16(smB + (uint32_t)(tid + i*256)*16u, src + (tid + i*256)*16);
        asm volatile("cp.async.commit_group;");
    }

    for (int iter = 0; iter < niter; iter++) {
        const int cb  = iter / 9;
        const int tap = iter - cb * 9;
        const int ky  = tap / 3, kx = tap % 3;

        __syncthreads();   // all warps done with stage (iter+1)&1 and A (prev chunk)

        // prefetch next B block
        if (iter + 1 < niter) {
            const char* src = (const char*)wpack + (size_t)(iter + 1) * 20480;
            uint32_t dstb = smB + (uint32_t)((iter + 1) & 1) * SMB_ST;
#pragma unroll
            for (int i = 0; i < 5; i++)
                cp_async16(dstb + (uint32_t)(tid + i*256)*16u, src + (tid + i*256)*16);
        }
        asm volatile("cp.async.commit_group;");

        // halo load (32 ci x 10 x 10) at chunk boundary
        if (tap == 0) {
            for (int idx = tid; idx < 3200; idx += 256) {
                int ci  = idx / 100;
                int rem = idx - ci * 100;
                int yy  = rem / 10;
                int xx  = rem - yy * 10;
                int gy  = y0 - 1 + yy;
                int gx  = x0 - 1 + xx;
                float v = 0.f;
                if ((unsigned)gy < (unsigned)HH && (unsigned)gx < (unsigned)WW) {
                    if (MODE == 1) {
                        size_t o = ((size_t)(b*CIN + cb*32 + ci))*HW + gy*WW + gx;
                        v = A[o] - Bp[o];
                    } else if (MODE == 2) {
                        int cg = cb*32 + ci;
                        if (cg < 128) v = A[((size_t)(b*128 + cg))*HW + gy*WW + gx];
                        else          v = Bp[((size_t)(b*128 + cg - 128))*HW + gy*WW + gx];
                    } else {
                        v = A[((size_t)(b*CIN + cb*32 + ci))*HW + gy*WW + gx];
                    }
                }
                __nv_bfloat16 hi = __float2bfloat16(v);
                __nv_bfloat16 lo = __float2bfloat16(v - __bfloat162float(hi));
                int off = (yy*10 + xx)*80 + ci*2;
                *(__nv_bfloat16*)(sm + off)          = hi;
                *(__nv_bfloat16*)(sm + SMA_LO + off) = lo;
            }
        }

        asm volatile("cp.async.wait_group 1;");
        __syncthreads();   // stage(iter) + halo visible to all

        // ---- compute ----
        const uint32_t bstage = smB + (uint32_t)(iter & 1) * SMB_ST;
        const uint32_t atap   = aoffL + (uint32_t)((ky*10 + kx)*80);

#pragma unroll
        for (int ks = 0; ks < 2; ks++) {
            uint32_t bh[2][4], bl[2][4];
#pragma unroll
            for (int nfp = 0; nfp < 2; nfp++) {
                uint32_t ba = bstage + boffL + (uint32_t)(nfp*16*80 + ks*32);
                ldsm_x4(bh[nfp], ba);
                ldsm_x4(bl[nfp], ba + 10240u);
            }
#pragma unroll
            for (int mf = 0; mf < 2; mf++) {
                uint32_t ar = atap + (uint32_t)(mf*1600 + ks*32);
                uint32_t ah[4], al[4];
                ldsm_x4(ah, smA   + ar);
                ldsm_x4(al, smAlo + ar);
#pragma unroll
                for (int nf = 0; nf < 4; nf++) {
                    const uint32_t* bhp = &bh[nf >> 1][(nf & 1) * 2];
                    const uint32_t* blp = &bl[nf >> 1][(nf & 1) * 2];
                    mma_bf16(acc[mf][nf], ah, bhp);
                    mma_bf16(acc[mf][nf], ah, blp);
                    mma_bf16(acc[mf][nf], al, bhp);
                }
            }
        }
    }

    // ---- epilogue ----
    const int xr = lane >> 2;                // 0..7
#pragma unroll
    for (int nf = 0; nf < 4; nf++) {
        const int co_a = co0 + warp_n*32 + nf*8 + (lane & 3)*2;
        const int co_b = co_a + 1;
        float ba_ = (co_a < COUT) ? bias[co_a] : 0.f;
        float bb_ = (co_b < COUT) ? bias[co_b] : 0.f;
#pragma unroll
        for (int mf = 0; mf < 2; mf++) {
            const int ya = y0 + warp_m*4 + mf*2;
            float v0 = acc[mf][nf][0] + ba_;
            float v1 = acc[mf][nf][1] + bb_;
            float v2 = acc[mf][nf][2] + ba_;
            float v3 = acc[mf][nf][3] + bb_;
            if (RELU) {
                v0 = fmaxf(v0, 0.f); v1 = fmaxf(v1, 0.f);
                v2 = fmaxf(v2, 0.f); v3 = fmaxf(v3, 0.f);
            }
            if (co_a < COUT) {
                out[((size_t)(b*COUT + co_a)*HH + ya    )*WW + x0 + xr] = v0;
                out[((size_t)(b*COUT + co_a)*HH + ya + 1)*WW + x0 + xr] = v2;
            }
            if (co_b < COUT) {
                out[((size_t)(b*COUT + co_b)*HH + ya    )*WW + x0 + xr] = v1;
                out[((size_t)(b*COUT + co_b)*HH + ya + 1)*WW + x0 + xr] = v3;
            }
        }
    }
}

// ============================================================================
// Fused DCNv2 + bias + relu (scalar fp32)
// ============================================================================
__global__ __launch_bounds__(256)
void dcn_k(const float* __restrict__ R1, const float* __restrict__ om,
           const float* __restrict__ wt, const float* __restrict__ bias,
           float* __restrict__ out)
{
    __shared__ float s_wk[2048];
    __shared__ float sval[16][36];

    const int tid    = threadIdx.x;
    const int x0     = blockIdx.x * 32;
    const int h      = blockIdx.y;
    const int b      = blockIdx.z;
    const int px_s   = tid & 31;
    const int cpair  = tid >> 5;
    const int co_grp = tid >> 3;
    const int px_grp = tid & 7;
    const int gx     = x0 + px_s;

    float acc[4][4];
#pragma unroll
    for (int i = 0; i < 4; i++)
#pragma unroll
        for (int j = 0; j < 4; j++) acc[i][j] = 0.f;

    for (int g = 0; g < 8; g++) {
        for (int k = 0; k < 9; k++) {
            __syncthreads();
            const float* wsrc = &wt[(g*9 + k) * 2048];
#pragma unroll
            for (int i = 0; i < 8; i++) s_wk[tid + i*256] = wsrc[tid + i*256];
            {
                const int ky = k / 3, kx = k % 3;
                const int obase = (b*216*HH + h)*WW + gx;
                float dy = om[obase + (18*g + 2*k    ) * HW];
                float dx = om[obase + (18*g + 2*k + 1) * HW];
                float mr = om[obase + (144 + 9*g + k ) * HW];
                float m  = 1.f / (1.f + expf(-mr));
                float py  = dy + (float)(ky + h - 1);
                float pxx = dx + (float)(kx + gx - 1);
                float fy = floorf(py), fx = floorf(pxx);
                float ly = py - fy,  lx = pxx - fx;
                int   yi = (int)fy,  xi = (int)fx;
                float w00 = (1.f-ly)*(1.f-lx)*m;
                float w01 = (1.f-ly)*lx*m;
                float w10 = ly*(1.f-lx)*m;
                float w11 = ly*lx*m;
                bool iy0 = (unsigned)yi     < (unsigned)HH;
                bool iy1 = (unsigned)(yi+1) < (unsigned)HH;
                bool ix0 = (unsigned)xi     < (unsigned)WW;
                bool ix1 = (unsigned)(xi+1) < (unsigned)WW;
#pragma unroll
                for (int j = 0; j < 2; j++) {
                    int c = cpair*2 + j;
                    const float* base = &R1[(b*128 + g*16 + c) * HW];
                    float v = 0.f;
                    if (iy0 && ix0) v = fmaf(w00, base[yi*WW + xi],         v);
                    if (iy0 && ix1) v = fmaf(w01, base[yi*WW + xi + 1],     v);
                    if (iy1 && ix0) v = fmaf(w10, base[(yi+1)*WW + xi],     v);
                    if (iy1 && ix1) v = fmaf(w11, base[(yi+1)*WW + xi + 1], v);
                    sval[c][px_s] = v;
                }
            }
            __syncthreads();
#pragma unroll
            for (int c = 0; c < 16; c++) {
                float4 wv = *(const float4*)&s_wk[c*128 + co_grp*4];
                float4 vv = *(const float4*)&sval[c][px_grp*4];
                acc[0][0] = fmaf(wv.x, vv.x, acc[0][0]);
                acc[0][1] = fmaf(wv.x, vv.y, acc[0][1]);
                acc[0][2] = fmaf(wv.x, vv.z, acc[0][2]);
                acc[0][3] = fmaf(wv.x, vv.w, acc[0][3]);
                acc[1][0] = fmaf(wv.y, vv.x, acc[1][0]);
                acc[1][1] = fmaf(wv.y, vv.y, acc[1][1]);
                acc[1][2] = fmaf(wv.y, vv.z, acc[1][2]);
                acc[1][3] = fmaf(wv.y, vv.w, acc[1][3]);
                acc[2][0] = fmaf(wv.z, vv.x, acc[2][0]);
                acc[2][1] = fmaf(wv.z, vv.y, acc[2][1]);
                acc[2][2] = fmaf(wv.z, vv.z, acc[2][2]);
                acc[2][3] = fmaf(wv.z, vv.w, acc[2][3]);
                acc[3][0] = fmaf(wv.w, vv.x, acc[3][0]);
                acc[3][1] = fmaf(wv.w, vv.y, acc[3][1]);
                acc[3][2] = fmaf(wv.w, vv.z, acc[3][2]);
                acc[3][3] = fmaf(wv.w, vv.w, acc[3][3]);
            }
        }
    }
#pragma unroll
    for (int ci = 0; ci < 4; ci++) {
        int co = co_grp*4 + ci;
        float bv = bias[co];
#pragma unroll
        for (int pj = 0; pj < 4; pj++) {
            int px = px_grp*4 + pj;
            out[(b*128 + co)*HW + h*WW + x0 + px] = fmaxf(acc[ci][pj] + bv, 0.f);
        }
    }
}

// ============================================================================
extern "C" void kernel_launch(void* const* d_in, const int* in_sizes, int n_in,
                              void* d_out, int out_size)
{
    (void)in_sizes; (void)n_in; (void)out_size;
    const float* R1    = (const float*)d_in[0];
    const float* Q0    = (const float*)d_in[1];
    const float* w1    = (const float*)d_in[2];
    const float* b1    = (const float*)d_in[3];
    const float* w2    = (const float*)d_in[4];
    const float* b2    = (const float*)d_in[5];
    const float* w_om  = (const float*)d_in[6];
    const float* b_om  = (const float*)d_in[7];
    const float* w_dcn = (const float*)d_in[8];
    const float* b_dcn = (const float*)d_in[9];
    const float* w_rq  = (const float*)d_in[10];
    const float* b_rq  = (const float*)d_in[11];
    float* out = (float*)d_out;

    float *t1, *t2, *om, *wt, *fea, *wp1, *wp2, *wpom, *wprq;
    cudaGetSymbolAddress((void**)&t1,   g_t1);
    cudaGetSymbolAddress((void**)&t2,   g_t2);
    cudaGetSymbolAddress((void**)&om,   g_om);
    cudaGetSymbolAddress((void**)&wt,   g_wt);
    cudaGetSymbolAddress((void**)&fea,  g_fea);
    cudaGetSymbolAddress((void**)&wp1,  g_wp1);
    cudaGetSymbolAddress((void**)&wp2,  g_wp2);
    cudaGetSymbolAddress((void**)&wpom, g_wpom);
    cudaGetSymbolAddress((void**)&wprq, g_wprq);

    cudaFuncSetAttribute(convMMA_k<0,true >, cudaFuncAttributeMaxDynamicSharedMemorySize, CONV_SMEM);
    cudaFuncSetAttribute(convMMA_k<0,false>, cudaFuncAttributeMaxDynamicSharedMemorySize, CONV_SMEM);
    cudaFuncSetAttribute(convMMA_k<1,true >, cudaFuncAttributeMaxDynamicSharedMemorySize, CONV_SMEM);
    cudaFuncSetAttribute(convMMA_k<2,true >, cudaFuncAttributeMaxDynamicSharedMemorySize, CONV_SMEM);

    // ---- all weight prep in one launch ----
    prepack_all_k<<<252, 256>>>(w1, w2, w_om, w_rq, w_dcn,
                                wp1, wp2, wpom, wprq, wt);

    // conv1: relu(conv(R1-Q0))  128->128
    convMMA_k<1,true ><<<dim3(12,12,2), 256, CONV_SMEM>>>(R1, Q0, wp1, b1, t1, 128, 128, 1, 4);
    // conv2: relu(conv(t1))     128->128
    convMMA_k<0,true ><<<dim3(12,12,2), 256, CONV_SMEM>>>(t1, nullptr, wp2, b2, t2, 128, 128, 1, 4);
    // conv_om: conv(t2)         128->216 (both co tiles in one launch)
    convMMA_k<0,false><<<dim3(12,12,4), 256, CONV_SMEM>>>(t2, nullptr, wpom, b_om, om, 128, 216, 2, 4);
    // deformable conv v2 + relu
    dcn_k<<<dim3(3, 96, 2), 256>>>(R1, om, wt, b_dcn, fea);
    // conv_rq: relu(conv(concat(fea, Q0)))  256->128
    convMMA_k<2,true ><<<dim3(12,12,2), 256, CONV_SMEM>>>(fea, Q0, wprq, b_rq, out, 256, 128, 1, 8);
}

// round 6
// speedup vs baseline: 2.3747x; 1.0971x over previous
#include <cuda_runtime.h>
#include <cuda_bf16.h>
#include <math.h>
#include <cstdint>

#define HH 96
#define WW 96
#define HW (HH*WW)

// ======================= helpers =======================
__device__ __forceinline__ uint32_t smem_u32(const void* p) {
    uint32_t a;
    asm("{ .reg .u64 t; cvta.to.shared.u64 t, %1; cvt.u32.u64 %0, t; }" : "=r"(a) : "l"(p));
    return a;
}
__device__ __forceinline__ void cp_async16(uint32_t saddr, const void* g) {
    asm volatile("cp.async.cg.shared.global [%0], [%1], 16;" :: "r"(saddr), "l"(g));
}
__device__ __forceinline__ void ldsm_x4(uint32_t* r, uint32_t a) {
    asm volatile("ldmatrix.sync.aligned.m8n8.x4.shared.b16 {%0,%1,%2,%3}, [%4];"
        : "=r"(r[0]), "=r"(r[1]), "=r"(r[2]), "=r"(r[3]) : "r"(a));
}
__device__ __forceinline__ void mma_bf16(float* c, const uint32_t* a, const uint32_t* b) {
    asm volatile("mma.sync.aligned.m16n8k16.row.col.f32.bf16.bf16.f32 "
        "{%0,%1,%2,%3}, {%4,%5,%6,%7}, {%8,%9}, {%0,%1,%2,%3};"
        : "+f"(c[0]), "+f"(c[1]), "+f"(c[2]), "+f"(c[3])
        : "r"(a[0]), "r"(a[1]), "r"(a[2]), "r"(a[3]), "r"(b[0]), "r"(b[1]));
}

// ======================= scratch globals =======================
__device__ float g_t1[2*128*HW];
__device__ float g_t2[2*128*HW];
__device__ float g_om[2*216*HW];
__device__ float g_fea[2*128*HW];
// packed conv weights: per (chunk,tap) block 20480 B
// block: [hi: 128co x 40ci bf16 (ci 32 real + 8 pad)][lo: same]
__device__ __align__(128) float g_wp1[36*5120];
__device__ __align__(128) float g_wp2[36*5120];
__device__ __align__(128) float g_wpom[72*5120];    // 2 co-tiles x 36 blocks
__device__ __align__(128) float g_wprq[72*5120];    // 8 chunks x 9 taps
// packed DCN weights: per (g,k) block 12288 B:
//   [hi: 128co rows x 48B (16c bf16 + 16B pad)][lo: same at +6144]
__device__ __align__(128) float g_wtp[72*3072];

// ============================================================================
// Merged prepack: conv weight packs + DCN weight pack, ONE launch (288 blocks)
// ============================================================================
__device__ __forceinline__ void pack_block(const float* __restrict__ w,
                                           float* __restrict__ dst,
                                           int CIN, int COUT, int co0,
                                           int cb, int tap)
{
    char* d = (char*)dst;
    for (int e = threadIdx.x; e < 128*40; e += 256) {
        int co = e / 40;
        int cl = e - co * 40;
        float v = 0.f;
        if (cl < 32 && (co0 + co) < COUT)
            v = w[((size_t)(co0 + co) * CIN + cb * 32 + cl) * 9 + tap];
        __nv_bfloat16 hi = __float2bfloat16(v);
        __nv_bfloat16 lo = __float2bfloat16(v - __bfloat162float(hi));
        *(__nv_bfloat16*)(d +         co * 80 + cl * 2) = hi;
        *(__nv_bfloat16*)(d + 10240 + co * 80 + cl * 2) = lo;
    }
}

__global__ void prepack_all_k(const float* __restrict__ w1,
                              const float* __restrict__ w2,
                              const float* __restrict__ w_om,
                              const float* __restrict__ w_rq,
                              const float* __restrict__ w_dcn,
                              float* __restrict__ wp1, float* __restrict__ wp2,
                              float* __restrict__ wpom, float* __restrict__ wprq,
                              float* __restrict__ wtp)
{
    const int blk = blockIdx.x;
    if (blk < 36) {
        pack_block(w1, wp1 + (size_t)blk*5120, 128, 128, 0, blk/9, blk%9);
    } else if (blk < 72) {
        int b2 = blk - 36;
        pack_block(w2, wp2 + (size_t)b2*5120, 128, 128, 0, b2/9, b2%9);
    } else if (blk < 108) {
        int b2 = blk - 72;
        pack_block(w_om, wpom + (size_t)b2*5120, 128, 216, 0, b2/9, b2%9);
    } else if (blk < 144) {
        int b2 = blk - 108;
        pack_block(w_om, wpom + (size_t)(36 + b2)*5120, 128, 216, 128, b2/9, b2%9);
    } else if (blk < 216) {
        int b2 = blk - 144;
        pack_block(w_rq, wprq + (size_t)b2*5120, 256, 128, 0, b2/9, b2%9);
    } else {
        // DCN: block b2 = g*9+k -> [128co][48B] hi + lo
        int b2 = blk - 216;
        int g = b2 / 9, k = b2 % 9;
        char* d = (char*)wtp + (size_t)b2 * 12288;
        for (int e = threadIdx.x; e < 2048; e += 256) {
            int co = e >> 4;
            int c  = e & 15;
            float v = w_dcn[(co*128 + g*16 + c)*9 + k];
            __nv_bfloat16 hi = __float2bfloat16(v);
            __nv_bfloat16 lo = __float2bfloat16(v - __bfloat162float(hi));
            *(__nv_bfloat16*)(d +        co * 48 + c * 2) = hi;
            *(__nv_bfloat16*)(d + 6144 + co * 48 + c * 2) = lo;
        }
    }
}

// ============================================================================
// Tensor-core 3x3 conv via mma.sync bf16 (3-term hi/lo, fp32 accum), ldmatrix.
// CTA: 256 thr, tile M=64 px (8x8) x N=128 co. Warp tile 32px x 32co.
// 3-stage B ring (2-iteration prefetch lead), single barrier per tap.
// ============================================================================
#define SMA_LO   8000
#define SMB      16000
#define SMB_ST   20480
#define CONV_SMEM (16000 + 3*20480)   // 77440

template<int MODE, bool RELU>
__global__ __launch_bounds__(256, 2)
void convMMA_k(const float* __restrict__ A, const float* __restrict__ Bp,
               const float* __restrict__ wpack0, const float* __restrict__ bias,
               float* __restrict__ out, int CIN, int COUT, int ncot, int nchunk)
{
    extern __shared__ char sm[];
    const int tid    = threadIdx.x;
    const int lane   = tid & 31;
    const int wid    = tid >> 5;
    const int warp_m = wid & 1;
    const int warp_n = wid >> 1;
    const int x0     = blockIdx.x * 8;
    const int y0     = blockIdx.y * 8;
    const int b      = blockIdx.z / ncot;
    const int cot    = blockIdx.z % ncot;
    const int co0    = cot * 128;
    const float* wpack = wpack0 + (size_t)cot * nchunk * 9 * 5120;

    const uint32_t sbase = smem_u32(sm);
    const uint32_t smA   = sbase;
    const uint32_t smAlo = sbase + SMA_LO;
    const uint32_t smB   = sbase + SMB;

    // A (row-major 16x16 frags)
    const int dyL  = (lane >> 3) & 1;
    const int xL   = lane & 7;
    const int kAL  = (lane & 16) ? 16 : 0;
    const uint32_t aoffL = (uint32_t)((dyL*10 + xL)*80 + kAL) + (uint32_t)warp_m*3200u;
    // B ([n][k] rows, non-trans)
    const int colL = (lane & 7) + ((lane & 16) ? 8 : 0);
    const int kBL  = (lane & 8) ? 16 : 0;
    const uint32_t boffL = (uint32_t)((warp_n*32 + colL)*80 + kBL);

    float acc[2][4][4];
#pragma unroll
    for (int i = 0; i < 2; i++)
#pragma unroll
        for (int j = 0; j < 4; j++)
#pragma unroll
            for (int k = 0; k < 4; k++) acc[i][j][k] = 0.f;

    const int niter = nchunk * 9;

    // prologue: prefetch blocks 0,1 into stages 0,1 (one commit each)
#pragma unroll
    for (int it = 0; it < 2; it++) {
        const char* src = (const char*)wpack + (size_t)it * 20480;
        uint32_t dstb = smB + (uint32_t)it * SMB_ST;
#pragma unroll
        for (int i = 0; i < 5; i++)
            cp_async16(dstb + (uint32_t)(tid + i*256)*16u, src + (tid + i*256)*16);
        asm volatile("cp.async.commit_group;");
    }

    for (int iter = 0; iter < niter; iter++) {
        const int cb  = iter / 9;
        const int tap = iter - cb * 9;
        const int ky  = tap / 3, kx = tap % 3;

        __syncthreads();   // all warps done with iter-1 compute (B stage + A reads)

        // halo load (32 ci x 10 x 10) at chunk boundary
        if (tap == 0) {
            for (int idx = tid; idx < 3200; idx += 256) {
                int ci  = idx / 100;
                int rem = idx - ci * 100;
                int yy  = rem / 10;
                int xx  = rem - yy * 10;
                int gy  = y0 - 1 + yy;
                int gx  = x0 - 1 + xx;
                float v = 0.f;
                if ((unsigned)gy < (unsigned)HH && (unsigned)gx < (unsigned)WW) {
                    if (MODE == 1) {
                        size_t o = ((size_t)(b*CIN + cb*32 + ci))*HW + gy*WW + gx;
                        v = A[o] - Bp[o];
                    } else if (MODE == 2) {
                        int cg = cb*32 + ci;
                        if (cg < 128) v = A[((size_t)(b*128 + cg))*HW + gy*WW + gx];
                        else          v = Bp[((size_t)(b*128 + cg - 128))*HW + gy*WW + gx];
                    } else {
                        v = A[((size_t)(b*CIN + cb*32 + ci))*HW + gy*WW + gx];
                    }
                }
                __nv_bfloat16 hi = __float2bfloat16(v);
                __nv_bfloat16 lo = __float2bfloat16(v - __bfloat162float(hi));
                int off = (yy*10 + xx)*80 + ci*2;
                *(__nv_bfloat16*)(sm + off)          = hi;
                *(__nv_bfloat16*)(sm + SMA_LO + off) = lo;
            }
            __syncthreads();
        }

        // prefetch block iter+2 into stage (iter+2)%3
        if (iter + 2 < niter) {
            const char* src = (const char*)wpack + (size_t)(iter + 2) * 20480;
            uint32_t dstb = smB + (uint32_t)((iter + 2) % 3) * SMB_ST;
#pragma unroll
            for (int i = 0; i < 5; i++)
                cp_async16(dstb + (uint32_t)(tid + i*256)*16u, src + (tid + i*256)*16);
        }
        asm volatile("cp.async.commit_group;");
        asm volatile("cp.async.wait_group 2;");   // block `iter` arrived

        // ---- compute ----
        const uint32_t bstage = smB + (uint32_t)(iter % 3) * SMB_ST;
        const uint32_t atap   = aoffL + (uint32_t)((ky*10 + kx)*80);

#pragma unroll
        for (int ks = 0; ks < 2; ks++) {
            uint32_t bh[2][4], bl[2][4];
#pragma unroll
            for (int nfp = 0; nfp < 2; nfp++) {
                uint32_t ba = bstage + boffL + (uint32_t)(nfp*16*80 + ks*32);
                ldsm_x4(bh[nfp], ba);
                ldsm_x4(bl[nfp], ba + 10240u);
            }
#pragma unroll
            for (int mf = 0; mf < 2; mf++) {
                uint32_t ar = atap + (uint32_t)(mf*1600 + ks*32);
                uint32_t ah[4], al[4];
                ldsm_x4(ah, smA   + ar);
                ldsm_x4(al, smAlo + ar);
#pragma unroll
                for (int nf = 0; nf < 4; nf++) {
                    const uint32_t* bhp = &bh[nf >> 1][(nf & 1) * 2];
                    const uint32_t* blp = &bl[nf >> 1][(nf & 1) * 2];
                    mma_bf16(acc[mf][nf], ah, bhp);
                    mma_bf16(acc[mf][nf], ah, blp);
                    mma_bf16(acc[mf][nf], al, bhp);
                }
            }
        }
    }

    // ---- epilogue ----
    const int xr = lane >> 2;
#pragma unroll
    for (int nf = 0; nf < 4; nf++) {
        const int co_a = co0 + warp_n*32 + nf*8 + (lane & 3)*2;
        const int co_b = co_a + 1;
        float ba_ = (co_a < COUT) ? bias[co_a] : 0.f;
        float bb_ = (co_b < COUT) ? bias[co_b] : 0.f;
#pragma unroll
        for (int mf = 0; mf < 2; mf++) {
            const int ya = y0 + warp_m*4 + mf*2;
            float v0 = acc[mf][nf][0] + ba_;
            float v1 = acc[mf][nf][1] + bb_;
            float v2 = acc[mf][nf][2] + ba_;
            float v3 = acc[mf][nf][3] + bb_;
            if (RELU) {
                v0 = fmaxf(v0, 0.f); v1 = fmaxf(v1, 0.f);
                v2 = fmaxf(v2, 0.f); v3 = fmaxf(v3, 0.f);
            }
            if (co_a < COUT) {
                out[((size_t)(b*COUT + co_a)*HH + ya    )*WW + x0 + xr] = v0;
                out[((size_t)(b*COUT + co_a)*HH + ya + 1)*WW + x0 + xr] = v2;
            }
            if (co_b < COUT) {
                out[((size_t)(b*COUT + co_b)*HH + ya    )*WW + x0 + xr] = v1;
                out[((size_t)(b*COUT + co_b)*HH + ya + 1)*WW + x0 + xr] = v3;
            }
        }
    }
}

// ============================================================================
// DCNv2 via mma.sync: per (g,k) a rank-16 GEMM update.
// CTA: 256 thr, tile M=64 px (8x8) x N=128 co. Warp tile 32px x 32co.
// A = sampled values [64px][48B rows: 16c bf16 + pad], hi/lo, double-buffered.
// B = packed weights [128co][48B rows: 16c bf16 + pad], hi/lo, 3-stage ring.
// smem: A stages 2 x (3072 hi + 3072 lo) = 12288 | wt ring 3 x 12288 = 36864
// ============================================================================
#define DCN_A_ST  6144
#define DCN_WT    12288
#define DCN_WT_ST 12288
#define DCN_SMEM  (12288 + 3*12288)   // 49152

__global__ __launch_bounds__(256, 2)
void dcnMMA_k(const float* __restrict__ R1, const float* __restrict__ om,
              const float* __restrict__ wtp, const float* __restrict__ bias,
              float* __restrict__ out)
{
    extern __shared__ char sm[];
    const int tid    = threadIdx.x;
    const int lane   = tid & 31;
    const int wid    = tid >> 5;
    const int warp_m = wid & 1;
    const int warp_n = wid >> 1;
    const int x0     = blockIdx.x * 8;
    const int y0     = blockIdx.y * 8;
    const int b      = blockIdx.z;

    const uint32_t sbase = smem_u32(sm);
    const uint32_t smWT  = sbase + DCN_WT;

    // sampling thread mapping: px = tid>>2 (0..63), cq = tid&3 (4 channels)
    const int px_s = tid >> 2;
    const int cq   = tid & 3;
    const int hs   = y0 + (px_s >> 3);
    const int gxs  = x0 + (px_s & 7);

    // ldmatrix lane addressing (same conventions as conv, 48B rows)
    const uint32_t aoffL = (uint32_t)((lane & 15) * 48 + ((lane & 16) ? 16 : 0))
                         + (uint32_t)warp_m * (32*48);
    const int colL = (lane & 7) + ((lane & 16) ? 8 : 0);
    const int kBL  = (lane & 8) ? 16 : 0;
    const uint32_t boffL = (uint32_t)((warp_n*32 + colL)*48 + kBL);

    float acc[2][4][4];
#pragma unroll
    for (int i = 0; i < 2; i++)
#pragma unroll
        for (int j = 0; j < 4; j++)
#pragma unroll
            for (int k = 0; k < 4; k++) acc[i][j][k] = 0.f;

    // prologue: prefetch wt blocks 0,1
#pragma unroll
    for (int it = 0; it < 2; it++) {
        const char* src = (const char*)wtp + (size_t)it * 12288;
        uint32_t dstb = smWT + (uint32_t)it * DCN_WT_ST;
#pragma unroll
        for (int i = 0; i < 3; i++)
            cp_async16(dstb + (uint32_t)(tid + i*256)*16u, src + (tid + i*256)*16);
        asm volatile("cp.async.commit_group;");
    }

    for (int iter = 0; iter < 72; iter++) {
        const int g = iter / 9;
        const int k = iter - g * 9;
        const int ky = k / 3, kx = k % 3;

        // ---- sample 4 channels at px_s into A stage iter&1 ----
        {
            const int obase = (b*216 + 0)*HW + hs*WW + gxs;
            float dy = om[obase + (18*g + 2*k    ) * HW];
            float dx = om[obase + (18*g + 2*k + 1) * HW];
            float mr = om[obase + (144 + 9*g + k ) * HW];
            float m  = 1.f / (1.f + __expf(-mr));
            float py  = dy + (float)(ky + hs - 1);
            float pxx = dx + (float)(kx + gxs - 1);
            float fy = floorf(py), fx = floorf(pxx);
            float ly = py - fy,  lx = pxx - fx;
            int   yi = (int)fy,  xi = (int)fx;
            float w00 = (1.f-ly)*(1.f-lx)*m;
            float w01 = (1.f-ly)*lx*m;
            float w10 = ly*(1.f-lx)*m;
            float w11 = ly*lx*m;
            bool iy0 = (unsigned)yi     < (unsigned)HH;
            bool iy1 = (unsigned)(yi+1) < (unsigned)HH;
            bool ix0 = (unsigned)xi     < (unsigned)WW;
            bool ix1 = (unsigned)(xi+1) < (unsigned)WW;
            uint32_t hp[2], lp[2];
#pragma unroll
            for (int jp = 0; jp < 2; jp++) {
                __nv_bfloat16 h2[2], l2[2];
#pragma unroll
                for (int jj = 0; jj < 2; jj++) {
                    int c = cq*4 + jp*2 + jj;
                    const float* base = &R1[((size_t)(b*128 + g*16 + c)) * HW];
                    float v = 0.f;
                    if (iy0 && ix0) v = fmaf(w00, base[yi*WW + xi],         v);
                    if (iy0 && ix1) v = fmaf(w01, base[yi*WW + xi + 1],     v);
                    if (iy1 && ix0) v = fmaf(w10, base[(yi+1)*WW + xi],     v);
                    if (iy1 && ix1) v = fmaf(w11, base[(yi+1)*WW + xi + 1], v);
                    __nv_bfloat16 hi = __float2bfloat16(v);
                    h2[jj] = hi;
                    l2[jj] = __float2bfloat16(v - __bfloat162float(hi));
                }
                hp[jp] = (uint32_t)*(uint16_t*)&h2[0] | ((uint32_t)*(uint16_t*)&h2[1] << 16);
                lp[jp] = (uint32_t)*(uint16_t*)&l2[0] | ((uint32_t)*(uint16_t*)&l2[1] << 16);
            }
            char* asb = sm + (iter & 1) * DCN_A_ST;
            *(uint2*)(asb +        px_s*48 + cq*8) = make_uint2(hp[0], hp[1]);
            *(uint2*)(asb + 3072 + px_s*48 + cq*8) = make_uint2(lp[0], lp[1]);
        }

        __syncthreads();   // A stage ready; all warps done with iter-1 compute

        // prefetch wt block iter+2
        if (iter + 2 < 72) {
            const char* src = (const char*)wtp + (size_t)(iter + 2) * 12288;
            uint32_t dstb = smWT + (uint32_t)((iter + 2) % 3) * DCN_WT_ST;
#pragma unroll
            for (int i = 0; i < 3; i++)
                cp_async16(dstb + (uint32_t)(tid + i*256)*16u, src + (tid + i*256)*16);
        }
        asm volatile("cp.async.commit_group;");
        asm volatile("cp.async.wait_group 2;");   // block `iter` arrived

        // ---- MMA: K=16, one k-step ----
        const uint32_t astage = sbase + (uint32_t)(iter & 1) * DCN_A_ST;
        const uint32_t wstage = smWT + (uint32_t)(iter % 3) * DCN_WT_ST;

        uint32_t bh[2][4], bl[2][4];
#pragma unroll
        for (int nfp = 0; nfp < 2; nfp++) {
            uint32_t ba = wstage + boffL + (uint32_t)(nfp*16*48);
            ldsm_x4(bh[nfp], ba);
            ldsm_x4(bl[nfp], ba + 6144u);
        }
#pragma unroll
        for (int mf = 0; mf < 2; mf++) {
            uint32_t ar = aoffL + astage + (uint32_t)(mf*16*48);
            uint32_t ah[4], al[4];
            ldsm_x4(ah, ar);
            ldsm_x4(al, ar + 3072u);
#pragma unroll
            for (int nf = 0; nf < 4; nf++) {
                const uint32_t* bhp = &bh[nf >> 1][(nf & 1) * 2];
                const uint32_t* blp = &bl[nf >> 1][(nf & 1) * 2];
                mma_bf16(acc[mf][nf], ah, bhp);
                mma_bf16(acc[mf][nf], ah, blp);
                mma_bf16(acc[mf][nf], al, bhp);
            }
        }
    }

    // ---- epilogue: bias + relu + store ----
    const int r0 = warp_m*32 + (lane >> 2);
#pragma unroll
    for (int nf = 0; nf < 4; nf++) {
        const int co_a = warp_n*32 + nf*8 + (lane & 3)*2;
        const int co_b = co_a + 1;
        const float ba_ = bias[co_a];
        const float bb_ = bias[co_b];
#pragma unroll
        for (int mf = 0; mf < 2; mf++) {
            const int p1 = r0 + mf*16;
            const int p2 = p1 + 8;
            const int o1 = (y0 + (p1 >> 3))*WW + x0 + (p1 & 7);
            const int o2 = (y0 + (p2 >> 3))*WW + x0 + (p2 & 7);
            out[((size_t)(b*128 + co_a))*HW + o1] = fmaxf(acc[mf][nf][0] + ba_, 0.f);
            out[((size_t)(b*128 + co_b))*HW + o1] = fmaxf(acc[mf][nf][1] + bb_, 0.f);
            out[((size_t)(b*128 + co_a))*HW + o2] = fmaxf(acc[mf][nf][2] + ba_, 0.f);
            out[((size_t)(b*128 + co_b))*HW + o2] = fmaxf(acc[mf][nf][3] + bb_, 0.f);
        }
    }
}

// ============================================================================
extern "C" void kernel_launch(void* const* d_in, const int* in_sizes, int n_in,
                              void* d_out, int out_size)
{
    (void)in_sizes; (void)n_in; (void)out_size;
    const float* R1    = (const float*)d_in[0];
    const float* Q0    = (const float*)d_in[1];
    const float* w1    = (const float*)d_in[2];
    const float* b1    = (const float*)d_in[3];
    const float* w2    = (const float*)d_in[4];
    const float* b2    = (const float*)d_in[5];
    const float* w_om  = (const float*)d_in[6];
    const float* b_om  = (const float*)d_in[7];
    const float* w_dcn = (const float*)d_in[8];
    const float* b_dcn = (const float*)d_in[9];
    const float* w_rq  = (const float*)d_in[10];
    const float* b_rq  = (const float*)d_in[11];
    float* out = (float*)d_out;

    float *t1, *t2, *om, *fea, *wp1, *wp2, *wpom, *wprq, *wtp;
    cudaGetSymbolAddress((void**)&t1,   g_t1);
    cudaGetSymbolAddress((void**)&t2,   g_t2);
    cudaGetSymbolAddress((void**)&om,   g_om);
    cudaGetSymbolAddress((void**)&fea,  g_fea);
    cudaGetSymbolAddress((void**)&wp1,  g_wp1);
    cudaGetSymbolAddress((void**)&wp2,  g_wp2);
    cudaGetSymbolAddress((void**)&wpom, g_wpom);
    cudaGetSymbolAddress((void**)&wprq, g_wprq);
    cudaGetSymbolAddress((void**)&wtp,  g_wtp);

    cudaFuncSetAttribute(convMMA_k<0,true >, cudaFuncAttributeMaxDynamicSharedMemorySize, CONV_SMEM);
    cudaFuncSetAttribute(convMMA_k<0,false>, cudaFuncAttributeMaxDynamicSharedMemorySize, CONV_SMEM);
    cudaFuncSetAttribute(convMMA_k<1,true >, cudaFuncAttributeMaxDynamicSharedMemorySize, CONV_SMEM);
    cudaFuncSetAttribute(convMMA_k<2,true >, cudaFuncAttributeMaxDynamicSharedMemorySize, CONV_SMEM);
    cudaFuncSetAttribute(dcnMMA_k, cudaFuncAttributeMaxDynamicSharedMemorySize, DCN_SMEM);

    // ---- all weight prep in one launch ----
    prepack_all_k<<<288, 256>>>(w1, w2, w_om, w_rq, w_dcn,
                                wp1, wp2, wpom, wprq, wtp);

    // conv1: relu(conv(R1-Q0))  128->128
    convMMA_k<1,true ><<<dim3(12,12,2), 256, CONV_SMEM>>>(R1, Q0, wp1, b1, t1, 128, 128, 1, 4);
    // conv2: relu(conv(t1))     128->128
    convMMA_k<0,true ><<<dim3(12,12,2), 256, CONV_SMEM>>>(t1, nullptr, wp2, b2, t2, 128, 128, 1, 4);
    // conv_om: conv(t2)         128->216
    convMMA_k<0,false><<<dim3(12,12,4), 256, CONV_SMEM>>>(t2, nullptr, wpom, b_om, om, 128, 216, 2, 4);
    // deformable conv v2 + relu (tensor cores)
    dcnMMA_k<<<dim3(12,12,2), 256, DCN_SMEM>>>(R1, om, wtp, b_dcn, fea);
    // conv_rq: relu(conv(concat(fea, Q0)))  256->128
    convMMA_k<2,true ><<<dim3(12,12,2), 256, CONV_SMEM>>>(fea, Q0, wprq, b_rq, out, 256, 128, 1, 8);
}

// round 9
// speedup vs baseline: 2.4045x; 1.0125x over previous
#include <cuda_runtime.h>
#include <cuda_bf16.h>
#include <math.h>
#include <cstdint>

#define HH 96
#define WW 96
#define HW (HH*WW)

// padded pixel-major bf16 tensor: [b][plane(hi/lo)][98*98 px][128 ch]
// padded px index = (y+1)*98 + (x+1); border px are zero.
#define PLANE98 (9604*128)          // bf16 elems per plane
#define PXB98   (2*PLANE98)         // bf16 elems per batch (hi+lo)

// ======================= helpers =======================
__device__ __forceinline__ uint32_t smem_u32(const void* p) {
    uint32_t a;
    asm("{ .reg .u64 t; cvta.to.shared.u64 t, %1; cvt.u32.u64 %0, t; }" : "=r"(a) : "l"(p));
    return a;
}
__device__ __forceinline__ void cp_async16(uint32_t saddr, const void* g) {
    asm volatile("cp.async.cg.shared.global [%0], [%1], 16;" :: "r"(saddr), "l"(g));
}
__device__ __forceinline__ void ldsm_x4(uint32_t* r, uint32_t a) {
    asm volatile("ldmatrix.sync.aligned.m8n8.x4.shared.b16 {%0,%1,%2,%3}, [%4];"
        : "=r"(r[0]), "=r"(r[1]), "=r"(r[2]), "=r"(r[3]) : "r"(a));
}
__device__ __forceinline__ void mma_bf16(float* c, const uint32_t* a, const uint32_t* b) {
    asm volatile("mma.sync.aligned.m16n8k16.row.col.f32.bf16.bf16.f32 "
        "{%0,%1,%2,%3}, {%4,%5,%6,%7}, {%8,%9}, {%0,%1,%2,%3};"
        : "+f"(c[0]), "+f"(c[1]), "+f"(c[2]), "+f"(c[3])
        : "r"(a[0]), "r"(a[1]), "r"(a[2]), "r"(a[3]), "r"(b[0]), "r"(b[1]));
}

// ======================= scratch globals =======================
__device__ float g_om[2*216*HW];                    // conv_om out (fp32 planar)
__device__ float g_t2[2*128*HW];                    // conv2 out (fp32 planar)
__device__ float g_fea[2*128*HW];                   // dcn out (fp32 planar)
// padded px-major bf16 tensors (float-backed: PXB98 floats = 2 batches of PXB98 bf16)
__device__ __align__(128) float g_din98[PXB98];
__device__ __align__(128) float g_t1b98[PXB98];
// packed conv weights: per (chunk,tap) block 20480 B: [hi 128co x 80B][lo same]
__device__ __align__(128) float g_wp1[36*5120];
__device__ __align__(128) float g_wp2[36*5120];
__device__ __align__(128) float g_wpom[72*5120];
__device__ __align__(128) float g_wprq[72*5120];
// packed DCN weights: per (g,k) block 12288 B: [hi 128co x 48B][lo at +6144]
__device__ __align__(128) float g_wtp[72*3072];

// ============================================================================
// Merged prep (488 blocks):
// 0-35 wp1 | 36-71 wp2 | 72-143 wpom | 144-215 wprq | 216-287 dcn wt |
// 288-479 din98 transpose (b,y) | 480-487 border zero (tensor,b,plane)
// ============================================================================
__device__ __forceinline__ void pack_block(const float* __restrict__ w,
                                           float* __restrict__ dst,
                                           int CIN, int COUT, int co0,
                                           int cb, int tap)
{
    char* d = (char*)dst;
    for (int e = threadIdx.x; e < 128*40; e += 256) {
        int co = e / 40;
        int cl = e - co * 40;
        float v = 0.f;
        if (cl < 32 && (co0 + co) < COUT)
            v = w[((size_t)(co0 + co) * CIN + cb * 32 + cl) * 9 + tap];
        __nv_bfloat16 hi = __float2bfloat16(v);
        __nv_bfloat16 lo = __float2bfloat16(v - __bfloat162float(hi));
        *(__nv_bfloat16*)(d +         co * 80 + cl * 2) = hi;
        *(__nv_bfloat16*)(d + 10240 + co * 80 + cl * 2) = lo;
    }
}

__global__ void prepack_all_k(const float* __restrict__ R1,
                              const float* __restrict__ Q0,
                              const float* __restrict__ w1,
                              const float* __restrict__ w2,
                              const float* __restrict__ w_om,
                              const float* __restrict__ w_rq,
                              const float* __restrict__ w_dcn,
                              float* __restrict__ wp1, float* __restrict__ wp2,
                              float* __restrict__ wpom, float* __restrict__ wprq,
                              float* __restrict__ wtp,
                              __nv_bfloat16* __restrict__ din,
                              __nv_bfloat16* __restrict__ t1b)
{
    const int blk = blockIdx.x;
    if (blk < 36) {
        pack_block(w1, wp1 + (size_t)blk*5120, 128, 128, 0, blk/9, blk%9);
    } else if (blk < 72) {
        int b2 = blk - 36;
        pack_block(w2, wp2 + (size_t)b2*5120, 128, 128, 0, b2/9, b2%9);
    } else if (blk < 108) {
        int b2 = blk - 72;
        pack_block(w_om, wpom + (size_t)b2*5120, 128, 216, 0, b2/9, b2%9);
    } else if (blk < 144) {
        int b2 = blk - 108;
        pack_block(w_om, wpom + (size_t)(36 + b2)*5120, 128, 216, 128, b2/9, b2%9);
    } else if (blk < 216) {
        int b2 = blk - 144;
        pack_block(w_rq, wprq + (size_t)b2*5120, 256, 128, 0, b2/9, b2%9);
    } else if (blk < 288) {
        int b2 = blk - 216;
        int g = b2 / 9, k = b2 % 9;
        char* d = (char*)wtp + (size_t)b2 * 12288;
        for (int e = threadIdx.x; e < 2048; e += 256) {
            int co = e >> 4;
            int c  = e & 15;
            float v = w_dcn[(co*128 + g*16 + c)*9 + k];
            __nv_bfloat16 hi = __float2bfloat16(v);
            __nv_bfloat16 lo = __float2bfloat16(v - __bfloat162float(hi));
            *(__nv_bfloat16*)(d +        co * 48 + c * 2) = hi;
            *(__nv_bfloat16*)(d + 6144 + co * 48 + c * 2) = lo;
        }
    } else if (blk < 480) {
        // din98 transpose: one (b, y) row -> padded pixel-major hi/lo of R1-Q0
        __shared__ float ts[64][97];
        int tb = blk - 288;
        int b  = tb / 96;
        int y  = tb % 96;
        for (int half = 0; half < 2; half++) {
            for (int e = threadIdx.x; e < 64*96; e += 256) {
                int ci = e / 96;
                int x  = e - ci * 96;
                size_t idx = ((size_t)(b*128 + half*64 + ci)*96 + y)*96 + x;
                ts[ci][x] = R1[idx] - Q0[idx];
            }
            __syncthreads();
            for (int e = threadIdx.x; e < 96*64; e += 256) {
                int x  = e / 64;
                int ci = e - x * 64;
                float v = ts[ci][x];
                __nv_bfloat16 hi = __float2bfloat16(v);
                __nv_bfloat16 lo = __float2bfloat16(v - __bfloat162float(hi));
                size_t o = (size_t)b*PXB98 + (size_t)((y+1)*98 + (x+1))*128 + half*64 + ci;
                din[o]           = hi;
                din[o + PLANE98] = lo;
            }
            __syncthreads();
        }
    } else {
        // border zeroing: 388 border px x 128 ch, as u32 writes
        int idx = blk - 480;
        int tensor = idx >> 2;
        int b      = (idx >> 1) & 1;
        int plane  = idx & 1;
        uint32_t* dst = (uint32_t*)(tensor ? t1b : din);
        size_t base32 = ((size_t)b*PXB98 + (size_t)plane*PLANE98) >> 1;
        for (int e = threadIdx.x; e < 388*64; e += 256) {
            int pxi = e >> 6;
            int w   = e & 63;
            int y, x;
            if      (pxi < 98)  { y = 0;        x = pxi; }
            else if (pxi < 196) { y = 97;       x = pxi - 98; }
            else if (pxi < 292) { y = pxi-196+1; x = 0; }
            else                { y = pxi-292+1; x = 97; }
            dst[base32 + (size_t)(y*98 + x)*64 + w] = 0u;
        }
    }
}

// ============================================================================
// convPX_k: padded px-major bf16 input conv (conv1 / conv2). CIN=128, COUT=128.
// A double-buffered via branchless cp.async (always in-bounds). B 3-stage ring.
// Two barriers per iter (WAR + post-wait visibility).
// OUTFMT: 0 = fp32 planar, 1 = padded bf16 pixel-major hi/lo.
// ============================================================================
#define SMA_BUF 16000
#define SMBX_OFF 32000
#define SMBX_ST  20480
#define CONVPX_SMEM (32000 + 3*20480)   // 93440

__device__ __forceinline__ void loadA98(uint32_t sbase, int buf,
                                        const __nv_bfloat16* __restrict__ t,
                                        int cbn, int b, int x0, int y0, int tid)
{
    const uint32_t abase = sbase + (uint32_t)buf * SMA_BUF;
#pragma unroll
    for (int i = 0; i < 4; i++) {
        int e = tid + i*256;
        if (e < 800) {
            int plane = e >= 400;
            int rr  = e - plane*400;
            int px  = rr >> 2;
            int seg = rr & 3;
            int gy  = y0 + px / 10;     // padded row, always in [0,97]
            int gx  = x0 + px % 10;     // padded col, always in [0,97]
            const __nv_bfloat16* src = t + (size_t)b*PXB98 + (size_t)plane*PLANE98
                                     + (size_t)(gy*98 + gx)*128 + cbn*32 + seg*8;
            cp_async16(abase + (uint32_t)(plane*8000 + px*80 + seg*16), src);
        }
    }
}

template<int OUTFMT>
__global__ __launch_bounds__(256, 2)
void convPX_k(const __nv_bfloat16* __restrict__ inA,
              const float* __restrict__ wpack, const float* __restrict__ bias,
              float* __restrict__ out_f, __nv_bfloat16* __restrict__ out_b)
{
    extern __shared__ char sm[];
    const int tid    = threadIdx.x;
    const int lane   = tid & 31;
    const int wid    = tid >> 5;
    const int warp_m = wid & 1;
    const int warp_n = wid >> 1;
    const int x0     = blockIdx.x * 8;
    const int y0     = blockIdx.y * 8;
    const int b      = blockIdx.z;

    const uint32_t sbase = smem_u32(sm);
    const uint32_t smB   = sbase + SMBX_OFF;

    const int dyL  = (lane >> 3) & 1;
    const int xL   = lane & 7;
    const int kAL  = (lane & 16) ? 16 : 0;
    const uint32_t aoffL = (uint32_t)((dyL*10 + xL)*80 + kAL) + (uint32_t)warp_m*3200u;
    const int colL = (lane & 7) + ((lane & 16) ? 8 : 0);
    const int kBL  = (lane & 8) ? 16 : 0;
    const uint32_t boffL = (uint32_t)((warp_n*32 + colL)*80 + kBL);

    float acc[2][4][4];
#pragma unroll
    for (int i = 0; i < 2; i++)
#pragma unroll
        for (int j = 0; j < 4; j++)
#pragma unroll
            for (int k = 0; k < 4; k++) acc[i][j][k] = 0.f;

    // prologue: A(chunk0)+B0 group; B1 group
    loadA98(sbase, 0, inA, 0, b, x0, y0, tid);
    {
        const char* src = (const char*)wpack;
#pragma unroll
        for (int i = 0; i < 5; i++)
            cp_async16(smB + (uint32_t)(tid + i*256)*16u, src + (tid + i*256)*16);
        asm volatile("cp.async.commit_group;");
        src += 20480;
#pragma unroll
        for (int i = 0; i < 5; i++)
            cp_async16(smB + SMBX_ST + (uint32_t)(tid + i*256)*16u, src + (tid + i*256)*16);
        asm volatile("cp.async.commit_group;");
    }

    for (int iter = 0; iter < 36; iter++) {
        const int cb  = iter / 9;
        const int tap = iter - cb * 9;
        const int ky  = tap / 3, kx = tap % 3;

        __syncthreads();   // WAR: everyone done reading stage being overwritten

        if (tap == 0 && cb + 1 < 4)
            loadA98(sbase, (cb + 1) & 1, inA, cb + 1, b, x0, y0, tid);
        if (iter + 2 < 36) {
            const char* src = (const char*)wpack + (size_t)(iter + 2) * 20480;
            uint32_t dstb = smB + (uint32_t)((iter + 2) % 3) * SMBX_ST;
#pragma unroll
            for (int i = 0; i < 5; i++)
                cp_async16(dstb + (uint32_t)(tid + i*256)*16u, src + (tid + i*256)*16);
        }
        asm volatile("cp.async.commit_group;");
        asm volatile("cp.async.wait_group 2;");
        __syncthreads();   // visibility: all threads' copies for this iter landed

        const uint32_t abase  = sbase + (uint32_t)(cb & 1) * SMA_BUF;
        const uint32_t bstage = smB + (uint32_t)(iter % 3) * SMBX_ST;
        const uint32_t atap   = abase + aoffL + (uint32_t)((ky*10 + kx)*80);

#pragma unroll
        for (int ks = 0; ks < 2; ks++) {
            uint32_t bh[2][4], bl[2][4];
#pragma unroll
            for (int nfp = 0; nfp < 2; nfp++) {
                uint32_t ba = bstage + boffL + (uint32_t)(nfp*16*80 + ks*32);
                ldsm_x4(bh[nfp], ba);
                ldsm_x4(bl[nfp], ba + 10240u);
            }
#pragma unroll
            for (int mf = 0; mf < 2; mf++) {
                uint32_t ar = atap + (uint32_t)(mf*1600 + ks*32);
                uint32_t ah[4], al[4];
                ldsm_x4(ah, ar);
                ldsm_x4(al, ar + 8000u);
#pragma unroll
                for (int nf = 0; nf < 4; nf++) {
                    const uint32_t* bhp = &bh[nf >> 1][(nf & 1) * 2];
                    const uint32_t* blp = &bl[nf >> 1][(nf & 1) * 2];
                    mma_bf16(acc[mf][nf], ah, bhp);
                    mma_bf16(acc[mf][nf], ah, blp);
                    mma_bf16(acc[mf][nf], al, bhp);
                }
            }
        }
    }

    // ---- epilogue (relu always) ----
    const int xr = lane >> 2;
#pragma unroll
    for (int nf = 0; nf < 4; nf++) {
        const int co_a = warp_n*32 + nf*8 + (lane & 3)*2;
        const int co_b = co_a + 1;
        const float ba_ = bias[co_a];
        const float bb_ = bias[co_b];
#pragma unroll
        for (int mf = 0; mf < 2; mf++) {
            const int ya = y0 + warp_m*4 + mf*2;
            float v0 = fmaxf(acc[mf][nf][0] + ba_, 0.f);
            float v1 = fmaxf(acc[mf][nf][1] + bb_, 0.f);
            float v2 = fmaxf(acc[mf][nf][2] + ba_, 0.f);
            float v3 = fmaxf(acc[mf][nf][3] + bb_, 0.f);
            if (OUTFMT == 0) {
                out_f[((size_t)(b*128 + co_a)*HH + ya    )*WW + x0 + xr] = v0;
                out_f[((size_t)(b*128 + co_a)*HH + ya + 1)*WW + x0 + xr] = v2;
                out_f[((size_t)(b*128 + co_b)*HH + ya    )*WW + x0 + xr] = v1;
                out_f[((size_t)(b*128 + co_b)*HH + ya + 1)*WW + x0 + xr] = v3;
            } else {
                size_t o1 = (size_t)b*PXB98
                          + (size_t)((ya+1)*98 + x0 + xr + 1)*128 + co_a;
                size_t o2 = o1 + 98*128;
                __nv_bfloat16 h0 = __float2bfloat16(v0);
                __nv_bfloat16 h1 = __float2bfloat16(v1);
                __nv_bfloat16 h2 = __float2bfloat16(v2);
                __nv_bfloat16 h3 = __float2bfloat16(v3);
                *(uint32_t*)&out_b[o1] = (uint32_t)*(uint16_t*)&h0 | ((uint32_t)*(uint16_t*)&h1 << 16);
                *(uint32_t*)&out_b[o2] = (uint32_t)*(uint16_t*)&h2 | ((uint32_t)*(uint16_t*)&h3 << 16);
                __nv_bfloat16 l0 = __float2bfloat16(v0 - __bfloat162float(h0));
                __nv_bfloat16 l1 = __float2bfloat16(v1 - __bfloat162float(h1));
                __nv_bfloat16 l2 = __float2bfloat16(v2 - __bfloat162float(h2));
                __nv_bfloat16 l3 = __float2bfloat16(v3 - __bfloat162float(h3));
                *(uint32_t*)&out_b[o1 + PLANE98] = (uint32_t)*(uint16_t*)&l0 | ((uint32_t)*(uint16_t*)&l1 << 16);
                *(uint32_t*)&out_b[o2 + PLANE98] = (uint32_t)*(uint16_t*)&l2 | ((uint32_t)*(uint16_t*)&l3 << 16);
            }
        }
    }
}

// ============================================================================
// convR6_k: R6-proven fp32-planar conv (MODE 0 = A, MODE 2 = concat(A,B)).
// Used for conv_om and conv_rq.
// ============================================================================
#define SMA_LO   8000
#define SMB      16000
#define SMB_ST   20480
#define CONVF_SMEM (16000 + 3*20480)   // 77440

template<int MODE, bool RELU>
__global__ __launch_bounds__(256, 2)
void convR6_k(const float* __restrict__ A, const float* __restrict__ Bp,
              const float* __restrict__ wpack0, const float* __restrict__ bias,
              float* __restrict__ out, int CIN, int COUT, int ncot, int nchunk)
{
    extern __shared__ char sm[];
    const int tid    = threadIdx.x;
    const int lane   = tid & 31;
    const int wid    = tid >> 5;
    const int warp_m = wid & 1;
    const int warp_n = wid >> 1;
    const int x0     = blockIdx.x * 8;
    const int y0     = blockIdx.y * 8;
    const int b      = blockIdx.z / ncot;
    const int cot    = blockIdx.z % ncot;
    const int co0    = cot * 128;
    const float* wpack = wpack0 + (size_t)cot * nchunk * 9 * 5120;

    const uint32_t sbase = smem_u32(sm);
    const uint32_t smA   = sbase;
    const uint32_t smAlo = sbase + SMA_LO;
    const uint32_t smB   = sbase + SMB;

    const int dyL  = (lane >> 3) & 1;
    const int xL   = lane & 7;
    const int kAL  = (lane & 16) ? 16 : 0;
    const uint32_t aoffL = (uint32_t)((dyL*10 + xL)*80 + kAL) + (uint32_t)warp_m*3200u;
    const int colL = (lane & 7) + ((lane & 16) ? 8 : 0);
    const int kBL  = (lane & 8) ? 16 : 0;
    const uint32_t boffL = (uint32_t)((warp_n*32 + colL)*80 + kBL);

    float acc[2][4][4];
#pragma unroll
    for (int i = 0; i < 2; i++)
#pragma unroll
        for (int j = 0; j < 4; j++)
#pragma unroll
            for (int k = 0; k < 4; k++) acc[i][j][k] = 0.f;

    const int niter = nchunk * 9;

#pragma unroll
    for (int it = 0; it < 2; it++) {
        const char* src = (const char*)wpack + (size_t)it * 20480;
        uint32_t dstb = smB + (uint32_t)it * SMB_ST;
#pragma unroll
        for (int i = 0; i < 5; i++)
            cp_async16(dstb + (uint32_t)(tid + i*256)*16u, src + (tid + i*256)*16);
        asm volatile("cp.async.commit_group;");
    }

    for (int iter = 0; iter < niter; iter++) {
        const int cb  = iter / 9;
        const int tap = iter - cb * 9;
        const int ky  = tap / 3, kx = tap % 3;

        __syncthreads();

        if (tap == 0) {
            for (int idx = tid; idx < 3200; idx += 256) {
                int ci  = idx / 100;
                int rem = idx - ci * 100;
                int yy  = rem / 10;
                int xx  = rem - yy * 10;
                int gy  = y0 - 1 + yy;
                int gx  = x0 - 1 + xx;
                float v = 0.f;
                if ((unsigned)gy < (unsigned)HH && (unsigned)gx < (unsigned)WW) {
                    if (MODE == 2) {
                        int cg = cb*32 + ci;
                        if (cg < 128) v = A[((size_t)(b*128 + cg))*HW + gy*WW + gx];
                        else          v = Bp[((size_t)(b*128 + cg - 128))*HW + gy*WW + gx];
                    } else {
                        v = A[((size_t)(b*CIN + cb*32 + ci))*HW + gy*WW + gx];
                    }
                }
                __nv_bfloat16 hi = __float2bfloat16(v);
                __nv_bfloat16 lo = __float2bfloat16(v - __bfloat162float(hi));
                int off = (yy*10 + xx)*80 + ci*2;
                *(__nv_bfloat16*)(sm + off)          = hi;
                *(__nv_bfloat16*)(sm + SMA_LO + off) = lo;
            }
            __syncthreads();
        }

        if (iter + 2 < niter) {
            const char* src = (const char*)wpack + (size_t)(iter + 2) * 20480;
            uint32_t dstb = smB + (uint32_t)((iter + 2) % 3) * SMB_ST;
#pragma unroll
            for (int i = 0; i < 5; i++)
                cp_async16(dstb + (uint32_t)(tid + i*256)*16u, src + (tid + i*256)*16);
        }
        asm volatile("cp.async.commit_group;");
        asm volatile("cp.async.wait_group 2;");

        const uint32_t bstage = smB + (uint32_t)(iter % 3) * SMB_ST;
        const uint32_t atap   = aoffL + (uint32_t)((ky*10 + kx)*80);

#pragma unroll
        for (int ks = 0; ks < 2; ks++) {
            uint32_t bh[2][4], bl[2][4];
#pragma unroll
            for (int nfp = 0; nfp < 2; nfp++) {
                uint32_t ba = bstage + boffL + (uint32_t)(nfp*16*80 + ks*32);
                ldsm_x4(bh[nfp], ba);
                ldsm_x4(bl[nfp], ba + 10240u);
            }
#pragma unroll
            for (int mf = 0; mf < 2; mf++) {
                uint32_t ar = atap + (uint32_t)(mf*1600 + ks*32);
                uint32_t ah[4], al[4];
                ldsm_x4(ah, smA   + ar);
                ldsm_x4(al, smAlo + ar);
#pragma unroll
                for (int nf = 0; nf < 4; nf++) {
                    const uint32_t* bhp = &bh[nf >> 1][(nf & 1) * 2];
                    const uint32_t* blp = &bl[nf >> 1][(nf & 1) * 2];
                    mma_bf16(acc[mf][nf], ah, bhp);
                    mma_bf16(acc[mf][nf], ah, blp);
                    mma_bf16(acc[mf][nf], al, bhp);
                }
            }
        }
    }

    const int xr = lane >> 2;
#pragma unroll
    for (int nf = 0; nf < 4; nf++) {
        const int co_a = co0 + warp_n*32 + nf*8 + (lane & 3)*2;
        const int co_b = co_a + 1;
        float ba_ = (co_a < COUT) ? bias[co_a] : 0.f;
        float bb_ = (co_b < COUT) ? bias[co_b] : 0.f;
#pragma unroll
        for (int mf = 0; mf < 2; mf++) {
            const int ya = y0 + warp_m*4 + mf*2;
            float v0 = acc[mf][nf][0] + ba_;
            float v1 = acc[mf][nf][1] + bb_;
            float v2 = acc[mf][nf][2] + ba_;
            float v3 = acc[mf][nf][3] + bb_;
            if (RELU) {
                v0 = fmaxf(v0, 0.f); v1 = fmaxf(v1, 0.f);
                v2 = fmaxf(v2, 0.f); v3 = fmaxf(v3, 0.f);
            }
            if (co_a < COUT) {
                out[((size_t)(b*COUT + co_a)*HH + ya    )*WW + x0 + xr] = v0;
                out[((size_t)(b*COUT + co_a)*HH + ya + 1)*WW + x0 + xr] = v2;
            }
            if (co_b < COUT) {
                out[((size_t)(b*COUT + co_b)*HH + ya    )*WW + x0 + xr] = v1;
                out[((size_t)(b*COUT + co_b)*HH + ya + 1)*WW + x0 + xr] = v3;
            }
        }
    }
}

// ============================================================================
// DCNv2 via mma.sync (R6-proven, verbatim).
// ============================================================================
#define DCN_A_ST  6144
#define DCN_WT    12288
#define DCN_WT_ST 12288
#define DCN_SMEM  (12288 + 3*12288)   // 49152

__global__ __launch_bounds__(256, 2)
void dcnMMA_k(const float* __restrict__ R1, const float* __restrict__ om,
              const float* __restrict__ wtp, const float* __restrict__ bias,
              float* __restrict__ out)
{
    extern __shared__ char sm[];
    const int tid    = threadIdx.x;
    const int lane   = tid & 31;
    const int wid    = tid >> 5;
    const int warp_m = wid & 1;
    const int warp_n = wid >> 1;
    const int x0     = blockIdx.x * 8;
    const int y0     = blockIdx.y * 8;
    const int b      = blockIdx.z;

    const uint32_t sbase = smem_u32(sm);
    const uint32_t smWT  = sbase + DCN_WT;

    const int px_s = tid >> 2;
    const int cq   = tid & 3;
    const int hs   = y0 + (px_s >> 3);
    const int gxs  = x0 + (px_s & 7);

    const uint32_t aoffL = (uint32_t)((lane & 15) * 48 + ((lane & 16) ? 16 : 0))
                         + (uint32_t)warp_m * (32*48);
    const int colL = (lane & 7) + ((lane & 16) ? 8 : 0);
    const int kBL  = (lane & 8) ? 16 : 0;
    const uint32_t boffL = (uint32_t)((warp_n*32 + colL)*48 + kBL);

    float acc[2][4][4];
#pragma unroll
    for (int i = 0; i < 2; i++)
#pragma unroll
        for (int j = 0; j < 4; j++)
#pragma unroll
            for (int k = 0; k < 4; k++) acc[i][j][k] = 0.f;

#pragma unroll
    for (int it = 0; it < 2; it++) {
        const char* src = (const char*)wtp + (size_t)it * 12288;
        uint32_t dstb = smWT + (uint32_t)it * DCN_WT_ST;
#pragma unroll
        for (int i = 0; i < 3; i++)
            cp_async16(dstb + (uint32_t)(tid + i*256)*16u, src + (tid + i*256)*16);
        asm volatile("cp.async.commit_group;");
    }

    for (int iter = 0; iter < 72; iter++) {
        const int g = iter / 9;
        const int k = iter - g * 9;
        const int ky = k / 3, kx = k % 3;

        {
            const int obase = (b*216)*HW + hs*WW + gxs;
            float dy = om[obase + (18*g + 2*k    ) * HW];
            float dx = om[obase + (18*g + 2*k + 1) * HW];
            float mr = om[obase + (144 + 9*g + k ) * HW];
            float m  = 1.f / (1.f + __expf(-mr));
            float py  = dy + (float)(ky + hs - 1);
            float pxx = dx + (float)(kx + gxs - 1);
            float fy = floorf(py), fx = floorf(pxx);
            float ly = py - fy,  lx = pxx - fx;
            int   yi = (int)fy,  xi = (int)fx;
            float w00 = (1.f-ly)*(1.f-lx)*m;
            float w01 = (1.f-ly)*lx*m;
            float w10 = ly*(1.f-lx)*m;
            float w11 = ly*lx*m;
            bool iy0 = (unsigned)yi     < (unsigned)HH;
            bool iy1 = (unsigned)(yi+1) < (unsigned)HH;
            bool ix0 = (unsigned)xi     < (unsigned)WW;
            bool ix1 = (unsigned)(xi+1) < (unsigned)WW;
            uint32_t hp[2], lp[2];
#pragma unroll
            for (int jp = 0; jp < 2; jp++) {
                float vv[2];
#pragma unroll
                for (int jj = 0; jj < 2; jj++) {
                    int c = cq*4 + jp*2 + jj;
                    const float* base = &R1[((size_t)(b*128 + g*16 + c)) * HW];
                    float v = 0.f;
                    if (iy0 && ix0) v = fmaf(w00, base[yi*WW + xi],         v);
                    if (iy0 && ix1) v = fmaf(w01, base[yi*WW + xi + 1],     v);
                    if (iy1 && ix0) v = fmaf(w10, base[(yi+1)*WW + xi],     v);
                    if (iy1 && ix1) v = fmaf(w11, base[(yi+1)*WW + xi + 1], v);
                    vv[jj] = v;
                }
                __nv_bfloat16 h0 = __float2bfloat16(vv[0]);
                __nv_bfloat16 h1 = __float2bfloat16(vv[1]);
                hp[jp] = (uint32_t)*(uint16_t*)&h0 | ((uint32_t)*(uint16_t*)&h1 << 16);
                __nv_bfloat16 l0 = __float2bfloat16(vv[0] - __bfloat162float(h0));
                __nv_bfloat16 l1 = __float2bfloat16(vv[1] - __bfloat162float(h1));
                lp[jp] = (uint32_t)*(uint16_t*)&l0 | ((uint32_t)*(uint16_t*)&l1 << 16);
            }
            char* asb = sm + (iter & 1) * DCN_A_ST;
            *(uint2*)(asb +        px_s*48 + cq*8) = make_uint2(hp[0], hp[1]);
            *(uint2*)(asb + 3072 + px_s*48 + cq*8) = make_uint2(lp[0], lp[1]);
        }

        __syncthreads();

        if (iter + 2 < 72) {
            const char* src = (const char*)wtp + (size_t)(iter + 2) * 12288;
            uint32_t dstb = smWT + (uint32_t)((iter + 2) % 3) * DCN_WT_ST;
#pragma unroll
            for (int i = 0; i < 3; i++)
                cp_async16(dstb + (uint32_t)(tid + i*256)*16u, src + (tid + i*256)*16);
        }
        asm volatile("cp.async.commit_group;");
        asm volatile("cp.async.wait_group 2;");

        const uint32_t astage = sbase + (uint32_t)(iter & 1) * DCN_A_ST;
        const uint32_t wstage = smWT + (uint32_t)(iter % 3) * DCN_WT_ST;

        uint32_t bh[2][4], bl[2][4];
#pragma unroll
        for (int nfp = 0; nfp < 2; nfp++) {
            uint32_t ba = wstage + boffL + (uint32_t)(nfp*16*48);
            ldsm_x4(bh[nfp], ba);
            ldsm_x4(bl[nfp], ba + 6144u);
        }
#pragma unroll
        for (int mf = 0; mf < 2; mf++) {
            uint32_t ar = aoffL + astage + (uint32_t)(mf*16*48);
            uint32_t ah[4], al[4];
            ldsm_x4(ah, ar);
            ldsm_x4(al, ar + 3072u);
#pragma unroll
            for (int nf = 0; nf < 4; nf++) {
                const uint32_t* bhp = &bh[nf >> 1][(nf & 1) * 2];
                const uint32_t* blp = &bl[nf >> 1][(nf & 1) * 2];
                mma_bf16(acc[mf][nf], ah, bhp);
                mma_bf16(acc[mf][nf], ah, blp);
                mma_bf16(acc[mf][nf], al, bhp);
            }
        }
    }

    const int r0 = warp_m*32 + (lane >> 2);
#pragma unroll
    for (int nf = 0; nf < 4; nf++) {
        const int co_a = warp_n*32 + nf*8 + (lane & 3)*2;
        const int co_b = co_a + 1;
        const float ba_ = bias[co_a];
        const float bb_ = bias[co_b];
#pragma unroll
        for (int mf = 0; mf < 2; mf++) {
            const int p1 = r0 + mf*16;
            const int p2 = p1 + 8;
            const int o1 = (y0 + (p1 >> 3))*WW + x0 + (p1 & 7);
            const int o2 = (y0 + (p2 >> 3))*WW + x0 + (p2 & 7);
            out[((size_t)(b*128 + co_a))*HW + o1] = fmaxf(acc[mf][nf][0] + ba_, 0.f);
            out[((size_t)(b*128 + co_b))*HW + o1] = fmaxf(acc[mf][nf][1] + bb_, 0.f);
            out[((size_t)(b*128 + co_a))*HW + o2] = fmaxf(acc[mf][nf][2] + ba_, 0.f);
            out[((size_t)(b*128 + co_b))*HW + o2] = fmaxf(acc[mf][nf][3] + bb_, 0.f);
        }
    }
}

// ============================================================================
extern "C" void kernel_launch(void* const* d_in, const int* in_sizes, int n_in,
                              void* d_out, int out_size)
{
    (void)in_sizes; (void)n_in; (void)out_size;
    const float* R1    = (const float*)d_in[0];
    const float* Q0    = (const float*)d_in[1];
    const float* w1    = (const float*)d_in[2];
    const float* b1    = (const float*)d_in[3];
    const float* w2    = (const float*)d_in[4];
    const float* b2    = (const float*)d_in[5];
    const float* w_om  = (const float*)d_in[6];
    const float* b_om  = (const float*)d_in[7];
    const float* w_dcn = (const float*)d_in[8];
    const float* b_dcn = (const float*)d_in[9];
    const float* w_rq  = (const float*)d_in[10];
    const float* b_rq  = (const float*)d_in[11];
    float* out = (float*)d_out;

    float *om, *t2, *fea, *wp1, *wp2, *wpom, *wprq, *wtp, *dinf, *t1f;
    cudaGetSymbolAddress((void**)&om,   g_om);
    cudaGetSymbolAddress((void**)&t2,   g_t2);
    cudaGetSymbolAddress((void**)&fea,  g_fea);
    cudaGetSymbolAddress((void**)&wp1,  g_wp1);
    cudaGetSymbolAddress((void**)&wp2,  g_wp2);
    cudaGetSymbolAddress((void**)&wpom, g_wpom);
    cudaGetSymbolAddress((void**)&wprq, g_wprq);
    cudaGetSymbolAddress((void**)&wtp,  g_wtp);
    cudaGetSymbolAddress((void**)&dinf, g_din98);
    cudaGetSymbolAddress((void**)&t1f,  g_t1b98);
    __nv_bfloat16* din = (__nv_bfloat16*)dinf;
    __nv_bfloat16* t1b = (__nv_bfloat16*)t1f;

    cudaFuncSetAttribute(convPX_k<1>,       cudaFuncAttributeMaxDynamicSharedMemorySize, CONVPX_SMEM);
    cudaFuncSetAttribute(convPX_k<0>,       cudaFuncAttributeMaxDynamicSharedMemorySize, CONVPX_SMEM);
    cudaFuncSetAttribute(convR6_k<0,false>, cudaFuncAttributeMaxDynamicSharedMemorySize, CONVF_SMEM);
    cudaFuncSetAttribute(convR6_k<2,true >, cudaFuncAttributeMaxDynamicSharedMemorySize, CONVF_SMEM);
    cudaFuncSetAttribute(dcnMMA_k,          cudaFuncAttributeMaxDynamicSharedMemorySize, DCN_SMEM);

    // all prep in one launch (weights + din transpose + border zeroing)
    prepack_all_k<<<488, 256>>>(R1, Q0, w1, w2, w_om, w_rq, w_dcn,
                                wp1, wp2, wpom, wprq, wtp, din, t1b);

    // conv1: relu(conv(R1-Q0)) -> t1 (padded px-major bf16)
    convPX_k<1><<<dim3(12,12,2), 256, CONVPX_SMEM>>>(din, wp1, b1, nullptr, t1b);
    // conv2: relu(conv(t1)) -> t2 (fp32 planar)
    convPX_k<0><<<dim3(12,12,2), 256, CONVPX_SMEM>>>(t1b, wp2, b2, t2, nullptr);
    // conv_om: conv(t2) -> om (fp32 planar, 216 ch)  [R6-proven]
    convR6_k<0,false><<<dim3(12,12,4), 256, CONVF_SMEM>>>(t2, nullptr, wpom, b_om, om, 128, 216, 2, 4);
    // deformable conv v2 + relu -> fea (fp32 planar)  [R6-proven]
    dcnMMA_k<<<dim3(12,12,2), 256, DCN_SMEM>>>(R1, om, wtp, b_dcn, fea);
    // conv_rq: relu(conv(concat(fea, Q0))) -> out  [R6-proven]
    convR6_k<2,true ><<<dim3(12,12,2), 256, CONVF_SMEM>>>(fea, Q0, wprq, b_rq, out, 256, 128, 1, 8);
}

// round 11
// speedup vs baseline: 2.8553x; 1.1875x over previous
#include <cuda_runtime.h>
#include <cuda_bf16.h>
#include <math.h>
#include <cstdint>

#define HH 96
#define WW 96
#define HW (HH*WW)

// padded pixel-major bf16 tensor: [b][plane(hi/lo)][98*98 px][128 ch]
#define PLANE98 (9604*128)
#define PXB98   (2*PLANE98)

// ======================= helpers =======================
__device__ __forceinline__ uint32_t smem_u32(const void* p) {
    uint32_t a;
    asm("{ .reg .u64 t; cvta.to.shared.u64 t, %1; cvt.u32.u64 %0, t; }" : "=r"(a) : "l"(p));
    return a;
}
__device__ __forceinline__ void cp_async16(uint32_t saddr, const void* g) {
    asm volatile("cp.async.cg.shared.global [%0], [%1], 16;" :: "r"(saddr), "l"(g));
}
__device__ __forceinline__ void ldsm_x4(uint32_t* r, uint32_t a) {
    asm volatile("ldmatrix.sync.aligned.m8n8.x4.shared.b16 {%0,%1,%2,%3}, [%4];"
        : "=r"(r[0]), "=r"(r[1]), "=r"(r[2]), "=r"(r[3]) : "r"(a));
}
__device__ __forceinline__ void mma_bf16(float* c, const uint32_t* a, const uint32_t* b) {
    asm volatile("mma.sync.aligned.m16n8k16.row.col.f32.bf16.bf16.f32 "
        "{%0,%1,%2,%3}, {%4,%5,%6,%7}, {%8,%9}, {%0,%1,%2,%3};"
        : "+f"(c[0]), "+f"(c[1]), "+f"(c[2]), "+f"(c[3])
        : "r"(a[0]), "r"(a[1]), "r"(a[2]), "r"(a[3]), "r"(b[0]), "r"(b[1]));
}

// ======================= scratch globals =======================
__device__ float g_om[2*216*HW];                    // conv_om out (fp32 planar)
__device__ float g_fea[2*128*HW];                   // dcn out (fp32 planar)
__device__ __align__(128) float g_R1px[2*HW*128];   // R1 pixel-major fp32 [b][px][128]
// padded px-major bf16 tensors
__device__ __align__(128) float g_din98[PXB98];
__device__ __align__(128) float g_t1b98[PXB98];
__device__ __align__(128) float g_t2b98[PXB98];
// packed conv weights: per (chunk,tap) block 20480 B: [hi 128co x 80B][lo same]
__device__ __align__(128) float g_wp1[36*5120];
__device__ __align__(128) float g_wp2[36*5120];
__device__ __align__(128) float g_wpom[72*5120];
__device__ __align__(128) float g_wprq[72*5120];
// packed DCN weights: per (g,k) block 12288 B: [hi 128co x 48B][lo at +6144]
__device__ __align__(128) float g_wtp[72*3072];

// ============================================================================
// Merged prep (684 blocks):
// 0-35 wp1 | 36-71 wp2 | 72-143 wpom | 144-215 wprq | 216-287 dcn wt |
// 288-479 din98 transpose | 480-671 R1px transpose | 672-683 border zero
// ============================================================================
__device__ __forceinline__ void pack_block(const float* __restrict__ w,
                                           float* __restrict__ dst,
                                           int CIN, int COUT, int co0,
                                           int cb, int tap)
{
    char* d = (char*)dst;
    for (int e = threadIdx.x; e < 128*40; e += 256) {
        int co = e / 40;
        int cl = e - co * 40;
        float v = 0.f;
        if (cl < 32 && (co0 + co) < COUT)
            v = w[((size_t)(co0 + co) * CIN + cb * 32 + cl) * 9 + tap];
        __nv_bfloat16 hi = __float2bfloat16(v);
        __nv_bfloat16 lo = __float2bfloat16(v - __bfloat162float(hi));
        *(__nv_bfloat16*)(d +         co * 80 + cl * 2) = hi;
        *(__nv_bfloat16*)(d + 10240 + co * 80 + cl * 2) = lo;
    }
}

__global__ void prepack_all_k(const float* __restrict__ R1,
                              const float* __restrict__ Q0,
                              const float* __restrict__ w1,
                              const float* __restrict__ w2,
                              const float* __restrict__ w_om,
                              const float* __restrict__ w_rq,
                              const float* __restrict__ w_dcn,
                              float* __restrict__ wp1, float* __restrict__ wp2,
                              float* __restrict__ wpom, float* __restrict__ wprq,
                              float* __restrict__ wtp,
                              __nv_bfloat16* __restrict__ din,
                              __nv_bfloat16* __restrict__ t1b,
                              __nv_bfloat16* __restrict__ t2b,
                              float* __restrict__ r1px)
{
    __shared__ float ts[64][97];   // single shared buffer reused by both transposes
    const int blk = blockIdx.x;
    if (blk < 36) {
        pack_block(w1, wp1 + (size_t)blk*5120, 128, 128, 0, blk/9, blk%9);
    } else if (blk < 72) {
        int b2 = blk - 36;
        pack_block(w2, wp2 + (size_t)b2*5120, 128, 128, 0, b2/9, b2%9);
    } else if (blk < 108) {
        int b2 = blk - 72;
        pack_block(w_om, wpom + (size_t)b2*5120, 128, 216, 0, b2/9, b2%9);
    } else if (blk < 144) {
        int b2 = blk - 108;
        pack_block(w_om, wpom + (size_t)(36 + b2)*5120, 128, 216, 128, b2/9, b2%9);
    } else if (blk < 216) {
        int b2 = blk - 144;
        pack_block(w_rq, wprq + (size_t)b2*5120, 256, 128, 0, b2/9, b2%9);
    } else if (blk < 288) {
        int b2 = blk - 216;
        int g = b2 / 9, k = b2 % 9;
        char* d = (char*)wtp + (size_t)b2 * 12288;
        for (int e = threadIdx.x; e < 2048; e += 256) {
            int co = e >> 4;
            int c  = e & 15;
            float v = w_dcn[(co*128 + g*16 + c)*9 + k];
            __nv_bfloat16 hi = __float2bfloat16(v);
            __nv_bfloat16 lo = __float2bfloat16(v - __bfloat162float(hi));
            *(__nv_bfloat16*)(d +        co * 48 + c * 2) = hi;
            *(__nv_bfloat16*)(d + 6144 + co * 48 + c * 2) = lo;
        }
    } else if (blk < 480) {
        // din98 transpose: one (b, y) row -> padded pixel-major hi/lo of R1-Q0
        int tb = blk - 288;
        int b  = tb / 96;
        int y  = tb % 96;
        for (int half = 0; half < 2; half++) {
            for (int e = threadIdx.x; e < 64*96; e += 256) {
                int ci = e / 96;
                int x  = e - ci * 96;
                size_t idx = ((size_t)(b*128 + half*64 + ci)*96 + y)*96 + x;
                ts[ci][x] = R1[idx] - Q0[idx];
            }
            __syncthreads();
            for (int e = threadIdx.x; e < 96*64; e += 256) {
                int x  = e / 64;
                int ci = e - x * 64;
                float v = ts[ci][x];
                __nv_bfloat16 hi = __float2bfloat16(v);
                __nv_bfloat16 lo = __float2bfloat16(v - __bfloat162float(hi));
                size_t o = (size_t)b*PXB98 + (size_t)((y+1)*98 + (x+1))*128 + half*64 + ci;
                din[o]           = hi;
                din[o + PLANE98] = lo;
            }
            __syncthreads();
        }
    } else if (blk < 672) {
        // R1px transpose (fp32, unpadded 96x96): one (b, y) row
        int tb = blk - 480;
        int b  = tb / 96;
        int y  = tb % 96;
        for (int half = 0; half < 2; half++) {
            for (int e = threadIdx.x; e < 64*96; e += 256) {
                int ci = e / 96;
                int x  = e - ci * 96;
                ts[ci][x] = R1[((size_t)(b*128 + half*64 + ci)*96 + y)*96 + x];
            }
            __syncthreads();
            for (int e = threadIdx.x; e < 96*64; e += 256) {
                int x  = e / 64;
                int ci = e - x * 64;
                r1px[((size_t)b*HW + y*96 + x)*128 + half*64 + ci] = ts[ci][x];
            }
            __syncthreads();
        }
    } else {
        // border zeroing: 388 border px x 128 ch per (tensor,b,plane)
        int idx = blk - 672;
        int tensor = idx >> 2;          // 0 din, 1 t1b, 2 t2b
        int b      = (idx >> 1) & 1;
        int plane  = idx & 1;
        uint32_t* dst = (uint32_t*)(tensor == 0 ? (void*)din :
                                    tensor == 1 ? (void*)t1b : (void*)t2b);
        size_t base32 = ((size_t)b*PXB98 + (size_t)plane*PLANE98) >> 1;
        for (int e = threadIdx.x; e < 388*64; e += 256) {
            int pxi = e >> 6;
            int w   = e & 63;
            int y, x;
            if      (pxi < 98)  { y = 0;         x = pxi; }
            else if (pxi < 196) { y = 97;        x = pxi - 98; }
            else if (pxi < 292) { y = pxi-196+1; x = 0; }
            else                { y = pxi-292+1; x = 97; }
            dst[base32 + (size_t)(y*98 + x)*64 + w] = 0u;
        }
    }
}

// ============================================================================
// convPX_k: padded px-major bf16 input conv. CIN=128 (4 chunks).
// OUTFMT: 0 = fp32 planar (COUT-guarded), 1 = padded bf16 px-major (COUT=128).
// ============================================================================
#define SMA_BUF 16000
#define SMBX_OFF 32000
#define SMBX_ST  20480
#define CONVPX_SMEM (32000 + 3*20480)   // 93440

__device__ __forceinline__ void loadA98(uint32_t sbase, int buf,
                                        const __nv_bfloat16* __restrict__ t,
                                        int cbn, int b, int x0, int y0, int tid)
{
    const uint32_t abase = sbase + (uint32_t)buf * SMA_BUF;
#pragma unroll
    for (int i = 0; i < 4; i++) {
        int e = tid + i*256;
        if (e < 800) {
            int plane = e >= 400;
            int rr  = e - plane*400;
            int px  = rr >> 2;
            int seg = rr & 3;
            int gy  = y0 + px / 10;
            int gx  = x0 + px % 10;
            const __nv_bfloat16* src = t + (size_t)b*PXB98 + (size_t)plane*PLANE98
                                     + (size_t)(gy*98 + gx)*128 + cbn*32 + seg*8;
            cp_async16(abase + (uint32_t)(plane*8000 + px*80 + seg*16), src);
        }
    }
}

template<int OUTFMT>
__global__ __launch_bounds__(256, 2)
void convPX_k(const __nv_bfloat16* __restrict__ inA,
              const float* __restrict__ wpack0, const float* __restrict__ bias,
              float* __restrict__ out_f, __nv_bfloat16* __restrict__ out_b,
              int COUT, int ncot)
{
    extern __shared__ char sm[];
    const int tid    = threadIdx.x;
    const int lane   = tid & 31;
    const int wid    = tid >> 5;
    const int warp_m = wid & 1;
    const int warp_n = wid >> 1;
    const int x0     = blockIdx.x * 8;
    const int y0     = blockIdx.y * 8;
    const int b      = blockIdx.z / ncot;
    const int cot    = blockIdx.z % ncot;
    const int co0    = cot * 128;
    const float* wpack = wpack0 + (size_t)cot * 36 * 5120;

    const uint32_t sbase = smem_u32(sm);
    const uint32_t smB   = sbase + SMBX_OFF;

    const int dyL  = (lane >> 3) & 1;
    const int xL   = lane & 7;
    const int kAL  = (lane & 16) ? 16 : 0;
    const uint32_t aoffL = (uint32_t)((dyL*10 + xL)*80 + kAL) + (uint32_t)warp_m*3200u;
    const int colL = (lane & 7) + ((lane & 16) ? 8 : 0);
    const int kBL  = (lane & 8) ? 16 : 0;
    const uint32_t boffL = (uint32_t)((warp_n*32 + colL)*80 + kBL);

    float acc[2][4][4];
#pragma unroll
    for (int i = 0; i < 2; i++)
#pragma unroll
        for (int j = 0; j < 4; j++)
#pragma unroll
            for (int k = 0; k < 4; k++) acc[i][j][k] = 0.f;

    loadA98(sbase, 0, inA, 0, b, x0, y0, tid);
    {
        const char* src = (const char*)wpack;
#pragma unroll
        for (int i = 0; i < 5; i++)
            cp_async16(smB + (uint32_t)(tid + i*256)*16u, src + (tid + i*256)*16);
        asm volatile("cp.async.commit_group;");
        src += 20480;
#pragma unroll
        for (int i = 0; i < 5; i++)
            cp_async16(smB + SMBX_ST + (uint32_t)(tid + i*256)*16u, src + (tid + i*256)*16);
        asm volatile("cp.async.commit_group;");
    }

    for (int iter = 0; iter < 36; iter++) {
        const int cb  = iter / 9;
        const int tap = iter - cb * 9;
        const int ky  = tap / 3, kx = tap % 3;

        __syncthreads();

        if (tap == 0 && cb + 1 < 4)
            loadA98(sbase, (cb + 1) & 1, inA, cb + 1, b, x0, y0, tid);
        if (iter + 2 < 36) {
            const char* src = (const char*)wpack + (size_t)(iter + 2) * 20480;
            uint32_t dstb = smB + (uint32_t)((iter + 2) % 3) * SMBX_ST;
#pragma unroll
            for (int i = 0; i < 5; i++)
                cp_async16(dstb + (uint32_t)(tid + i*256)*16u, src + (tid + i*256)*16);
        }
        asm volatile("cp.async.commit_group;");
        asm volatile("cp.async.wait_group 2;");
        __syncthreads();

        const uint32_t abase  = sbase + (uint32_t)(cb & 1) * SMA_BUF;
        const uint32_t bstage = smB + (uint32_t)(iter % 3) * SMBX_ST;
        const uint32_t atap   = abase + aoffL + (uint32_t)((ky*10 + kx)*80);

#pragma unroll
        for (int ks = 0; ks < 2; ks++) {
            uint32_t bh[2][4], bl[2][4];
#pragma unroll
            for (int nfp = 0; nfp < 2; nfp++) {
                uint32_t ba = bstage + boffL + (uint32_t)(nfp*16*80 + ks*32);
                ldsm_x4(bh[nfp], ba);
                ldsm_x4(bl[nfp], ba + 10240u);
            }
#pragma unroll
            for (int mf = 0; mf < 2; mf++) {
                uint32_t ar = atap + (uint32_t)(mf*1600 + ks*32);
                uint32_t ah[4], al[4];
                ldsm_x4(ah, ar);
                ldsm_x4(al, ar + 8000u);
#pragma unroll
                for (int nf = 0; nf < 4; nf++) {
                    const uint32_t* bhp = &bh[nf >> 1][(nf & 1) * 2];
                    const uint32_t* blp = &bl[nf >> 1][(nf & 1) * 2];
                    mma_bf16(acc[mf][nf], ah, bhp);
                    mma_bf16(acc[mf][nf], ah, blp);
                    mma_bf16(acc[mf][nf], al, bhp);
                }
            }
        }
    }

    // ---- epilogue ----
    const int xr = lane >> 2;
#pragma unroll
    for (int nf = 0; nf < 4; nf++) {
        const int co_a = co0 + warp_n*32 + nf*8 + (lane & 3)*2;
        const int co_b = co_a + 1;
        const float ba_ = (co_a < COUT) ? bias[co_a] : 0.f;
        const float bb_ = (co_b < COUT) ? bias[co_b] : 0.f;
#pragma unroll
        for (int mf = 0; mf < 2; mf++) {
            const int ya = y0 + warp_m*4 + mf*2;
            float v0 = acc[mf][nf][0] + ba_;
            float v1 = acc[mf][nf][1] + bb_;
            float v2 = acc[mf][nf][2] + ba_;
            float v3 = acc[mf][nf][3] + bb_;
            if (OUTFMT == 1) {   // conv1/conv2: relu + bf16 px-major (COUT=128)
                v0 = fmaxf(v0, 0.f); v1 = fmaxf(v1, 0.f);
                v2 = fmaxf(v2, 0.f); v3 = fmaxf(v3, 0.f);
                size_t o1 = (size_t)b*PXB98
                          + (size_t)((ya+1)*98 + x0 + xr + 1)*128 + (co_a - co0);
                size_t o2 = o1 + 98*128;
                __nv_bfloat16 h0 = __float2bfloat16(v0);
                __nv_bfloat16 h1 = __float2bfloat16(v1);
                __nv_bfloat16 h2 = __float2bfloat16(v2);
                __nv_bfloat16 h3 = __float2bfloat16(v3);
                *(uint32_t*)&out_b[o1] = (uint32_t)*(uint16_t*)&h0 | ((uint32_t)*(uint16_t*)&h1 << 16);
                *(uint32_t*)&out_b[o2] = (uint32_t)*(uint16_t*)&h2 | ((uint32_t)*(uint16_t*)&h3 << 16);
                __nv_bfloat16 l0 = __float2bfloat16(v0 - __bfloat162float(h0));
                __nv_bfloat16 l1 = __float2bfloat16(v1 - __bfloat162float(h1));
                __nv_bfloat16 l2 = __float2bfloat16(v2 - __bfloat162float(h2));
                __nv_bfloat16 l3 = __float2bfloat16(v3 - __bfloat162float(h3));
                *(uint32_t*)&out_b[o1 + PLANE98] = (uint32_t)*(uint16_t*)&l0 | ((uint32_t)*(uint16_t*)&l1 << 16);
                *(uint32_t*)&out_b[o2 + PLANE98] = (uint32_t)*(uint16_t*)&l2 | ((uint32_t)*(uint16_t*)&l3 << 16);
            } else {             // conv_om: fp32 planar, no relu, COUT guards
                if (co_a < COUT) {
                    out_f[((size_t)(b*COUT + co_a)*HH + ya    )*WW + x0 + xr] = v0;
                    out_f[((size_t)(b*COUT + co_a)*HH + ya + 1)*WW + x0 + xr] = v2;
                }
                if (co_b < COUT) {
                    out_f[((size_t)(b*COUT + co_b)*HH + ya    )*WW + x0 + xr] = v1;
                    out_f[((size_t)(b*COUT + co_b)*HH + ya + 1)*WW + x0 + xr] = v3;
                }
            }
        }
    }
}

// ============================================================================
// convR6_k: fp32-planar concat conv (conv_rq), R6-proven.
// ============================================================================
#define SMA_LO   8000
#define SMB      16000
#define SMB_ST   20480
#define CONVF_SMEM (16000 + 3*20480)   // 77440

__global__ __launch_bounds__(256, 2)
void convR6_k(const float* __restrict__ A, const float* __restrict__ Bp,
              const float* __restrict__ wpack, const float* __restrict__ bias,
              float* __restrict__ out, int nchunk)
{
    extern __shared__ char sm[];
    const int tid    = threadIdx.x;
    const int lane   = tid & 31;
    const int wid    = tid >> 5;
    const int warp_m = wid & 1;
    const int warp_n = wid >> 1;
    const int x0     = blockIdx.x * 8;
    const int y0     = blockIdx.y * 8;
    const int b      = blockIdx.z;

    const uint32_t sbase = smem_u32(sm);
    const uint32_t smA   = sbase;
    const uint32_t smAlo = sbase + SMA_LO;
    const uint32_t smB   = sbase + SMB;

    const int dyL  = (lane >> 3) & 1;
    const int xL   = lane & 7;
    const int kAL  = (lane & 16) ? 16 : 0;
    const uint32_t aoffL = (uint32_t)((dyL*10 + xL)*80 + kAL) + (uint32_t)warp_m*3200u;
    const int colL = (lane & 7) + ((lane & 16) ? 8 : 0);
    const int kBL  = (lane & 8) ? 16 : 0;
    const uint32_t boffL = (uint32_t)((warp_n*32 + colL)*80 + kBL);

    float acc[2][4][4];
#pragma unroll
    for (int i = 0; i < 2; i++)
#pragma unroll
        for (int j = 0; j < 4; j++)
#pragma unroll
            for (int k = 0; k < 4; k++) acc[i][j][k] = 0.f;

    const int niter = nchunk * 9;

#pragma unroll
    for (int it = 0; it < 2; it++) {
        const char* src = (const char*)wpack + (size_t)it * 20480;
        uint32_t dstb = smB + (uint32_t)it * SMB_ST;
#pragma unroll
        for (int i = 0; i < 5; i++)
            cp_async16(dstb + (uint32_t)(tid + i*256)*16u, src + (tid + i*256)*16);
        asm volatile("cp.async.commit_group;");
    }

    for (int iter = 0; iter < niter; iter++) {
        const int cb  = iter / 9;
        const int tap = iter - cb * 9;
        const int ky  = tap / 3, kx = tap % 3;

        __syncthreads();

        if (tap == 0) {
            for (int idx = tid; idx < 3200; idx += 256) {
                int ci  = idx / 100;
                int rem = idx - ci * 100;
                int yy  = rem / 10;
                int xx  = rem - yy * 10;
                int gy  = y0 - 1 + yy;
                int gx  = x0 - 1 + xx;
                float v = 0.f;
                if ((unsigned)gy < (unsigned)HH && (unsigned)gx < (unsigned)WW) {
                    int cg = cb*32 + ci;
                    if (cg < 128) v = A[((size_t)(b*128 + cg))*HW + gy*WW + gx];
                    else          v = Bp[((size_t)(b*128 + cg - 128))*HW + gy*WW + gx];
                }
                __nv_bfloat16 hi = __float2bfloat16(v);
                __nv_bfloat16 lo = __float2bfloat16(v - __bfloat162float(hi));
                int off = (yy*10 + xx)*80 + ci*2;
                *(__nv_bfloat16*)(sm + off)          = hi;
                *(__nv_bfloat16*)(sm + SMA_LO + off) = lo;
            }
            __syncthreads();
        }

        if (iter + 2 < niter) {
            const char* src = (const char*)wpack + (size_t)(iter + 2) * 20480;
            uint32_t dstb = smB + (uint32_t)((iter + 2) % 3) * SMB_ST;
#pragma unroll
            for (int i = 0; i < 5; i++)
                cp_async16(dstb + (uint32_t)(tid + i*256)*16u, src + (tid + i*256)*16);
        }
        asm volatile("cp.async.commit_group;");
        asm volatile("cp.async.wait_group 2;");

        const uint32_t bstage = smB + (uint32_t)(iter % 3) * SMB_ST;
        const uint32_t atap   = aoffL + (uint32_t)((ky*10 + kx)*80);

#pragma unroll
        for (int ks = 0; ks < 2; ks++) {
            uint32_t bh[2][4], bl[2][4];
#pragma unroll
            for (int nfp = 0; nfp < 2; nfp++) {
                uint32_t ba = bstage + boffL + (uint32_t)(nfp*16*80 + ks*32);
                ldsm_x4(bh[nfp], ba);
                ldsm_x4(bl[nfp], ba + 10240u);
            }
#pragma unroll
            for (int mf = 0; mf < 2; mf++) {
                uint32_t ar = atap + (uint32_t)(mf*1600 + ks*32);
                uint32_t ah[4], al[4];
                ldsm_x4(ah, smA   + ar);
                ldsm_x4(al, smAlo + ar);
#pragma unroll
                for (int nf = 0; nf < 4; nf++) {
                    const uint32_t* bhp = &bh[nf >> 1][(nf & 1) * 2];
                    const uint32_t* blp = &bl[nf >> 1][(nf & 1) * 2];
                    mma_bf16(acc[mf][nf], ah, bhp);
                    mma_bf16(acc[mf][nf], ah, blp);
                    mma_bf16(acc[mf][nf], al, bhp);
                }
            }
        }
    }

    const int xr = lane >> 2;
#pragma unroll
    for (int nf = 0; nf < 4; nf++) {
        const int co_a = warp_n*32 + nf*8 + (lane & 3)*2;
        const int co_b = co_a + 1;
        float ba_ = bias[co_a];
        float bb_ = bias[co_b];
#pragma unroll
        for (int mf = 0; mf < 2; mf++) {
            const int ya = y0 + warp_m*4 + mf*2;
            float v0 = fmaxf(acc[mf][nf][0] + ba_, 0.f);
            float v1 = fmaxf(acc[mf][nf][1] + bb_, 0.f);
            float v2 = fmaxf(acc[mf][nf][2] + ba_, 0.f);
            float v3 = fmaxf(acc[mf][nf][3] + bb_, 0.f);
            out[((size_t)(b*128 + co_a)*HH + ya    )*WW + x0 + xr] = v0;
            out[((size_t)(b*128 + co_a)*HH + ya + 1)*WW + x0 + xr] = v2;
            out[((size_t)(b*128 + co_b)*HH + ya    )*WW + x0 + xr] = v1;
            out[((size_t)(b*128 + co_b)*HH + ya + 1)*WW + x0 + xr] = v3;
        }
    }
}

// ============================================================================
// DCNv2 via mma.sync; sampling reads px-major fp32 R1 (float4 per corner).
// ============================================================================
#define DCN_A_ST  6144
#define DCN_WT    12288
#define DCN_WT_ST 12288
#define DCN_SMEM  (12288 + 3*12288)   // 49152

__global__ __launch_bounds__(256, 2)
void dcnMMA_k(const float* __restrict__ R1px, const float* __restrict__ om,
              const float* __restrict__ wtp, const float* __restrict__ bias,
              float* __restrict__ out)
{
    extern __shared__ char sm[];
    const int tid    = threadIdx.x;
    const int lane   = tid & 31;
    const int wid    = tid >> 5;
    const int warp_m = wid & 1;
    const int warp_n = wid >> 1;
    const int x0     = blockIdx.x * 8;
    const int y0     = blockIdx.y * 8;
    const int b      = blockIdx.z;

    const uint32_t sbase = smem_u32(sm);
    const uint32_t smWT  = sbase + DCN_WT;

    const int px_s = tid >> 2;
    const int cq   = tid & 3;
    const int hs   = y0 + (px_s >> 3);
    const int gxs  = x0 + (px_s & 7);

    const uint32_t aoffL = (uint32_t)((lane & 15) * 48 + ((lane & 16) ? 16 : 0))
                         + (uint32_t)warp_m * (32*48);
    const int colL = (lane & 7) + ((lane & 16) ? 8 : 0);
    const int kBL  = (lane & 8) ? 16 : 0;
    const uint32_t boffL = (uint32_t)((warp_n*32 + colL)*48 + kBL);

    float acc[2][4][4];
#pragma unroll
    for (int i = 0; i < 2; i++)
#pragma unroll
        for (int j = 0; j < 4; j++)
#pragma unroll
            for (int k = 0; k < 4; k++) acc[i][j][k] = 0.f;

#pragma unroll
    for (int it = 0; it < 2; it++) {
        const char* src = (const char*)wtp + (size_t)it * 12288;
        uint32_t dstb = smWT + (uint32_t)it * DCN_WT_ST;
#pragma unroll
        for (int i = 0; i < 3; i++)
            cp_async16(dstb + (uint32_t)(tid + i*256)*16u, src + (tid + i*256)*16);
        asm volatile("cp.async.commit_group;");
    }

    for (int iter = 0; iter < 72; iter++) {
        const int g = iter / 9;
        const int k = iter - g * 9;
        const int ky = k / 3, kx = k % 3;

        {
            const int obase = (b*216)*HW + hs*WW + gxs;
            float dy = om[obase + (18*g + 2*k    ) * HW];
            float dx = om[obase + (18*g + 2*k + 1) * HW];
            float mr = om[obase + (144 + 9*g + k ) * HW];
            float m  = 1.f / (1.f + __expf(-mr));
            float py  = dy + (float)(ky + hs - 1);
            float pxx = dx + (float)(kx + gxs - 1);
            float fy = floorf(py), fx = floorf(pxx);
            float ly = py - fy,  lx = pxx - fx;
            int   yi = (int)fy,  xi = (int)fx;
            float w00 = (1.f-ly)*(1.f-lx)*m;
            float w01 = (1.f-ly)*lx*m;
            float w10 = ly*(1.f-lx)*m;
            float w11 = ly*lx*m;
            bool iy0 = (unsigned)yi     < (unsigned)HH;
            bool iy1 = (unsigned)(yi+1) < (unsigned)HH;
            bool ix0 = (unsigned)xi     < (unsigned)WW;
            bool ix1 = (unsigned)(xi+1) < (unsigned)WW;

            // px-major sampling: one float4 (4 channels) per corner
            const float* pb = R1px + (size_t)b*HW*128 + g*16 + cq*4;
            float4 z = make_float4(0.f, 0.f, 0.f, 0.f);
            float4 a00 = (iy0 && ix0) ? *(const float4*)(pb + (size_t)(yi*WW + xi)*128)       : z;
            float4 a01 = (iy0 && ix1) ? *(const float4*)(pb + (size_t)(yi*WW + xi + 1)*128)   : z;
            float4 a10 = (iy1 && ix0) ? *(const float4*)(pb + (size_t)((yi+1)*WW + xi)*128)   : z;
            float4 a11 = (iy1 && ix1) ? *(const float4*)(pb + (size_t)((yi+1)*WW + xi + 1)*128) : z;
            float vv0 = w00*a00.x + w01*a01.x + w10*a10.x + w11*a11.x;
            float vv1 = w00*a00.y + w01*a01.y + w10*a10.y + w11*a11.y;
            float vv2 = w00*a00.z + w01*a01.z + w10*a10.z + w11*a11.z;
            float vv3 = w00*a00.w + w01*a01.w + w10*a10.w + w11*a11.w;

            __nv_bfloat16 h0 = __float2bfloat16(vv0);
            __nv_bfloat16 h1 = __float2bfloat16(vv1);
            __nv_bfloat16 h2 = __float2bfloat16(vv2);
            __nv_bfloat16 h3 = __float2bfloat16(vv3);
            uint32_t hp0 = (uint32_t)*(uint16_t*)&h0 | ((uint32_t)*(uint16_t*)&h1 << 16);
            uint32_t hp1 = (uint32_t)*(uint16_t*)&h2 | ((uint32_t)*(uint16_t*)&h3 << 16);
            __nv_bfloat16 l0 = __float2bfloat16(vv0 - __bfloat162float(h0));
            __nv_bfloat16 l1 = __float2bfloat16(vv1 - __bfloat162float(h1));
            __nv_bfloat16 l2 = __float2bfloat16(vv2 - __bfloat162float(h2));
            __nv_bfloat16 l3 = __float2bfloat16(vv3 - __bfloat162float(h3));
            uint32_t lp0 = (uint32_t)*(uint16_t*)&l0 | ((uint32_t)*(uint16_t*)&l1 << 16);
            uint32_t lp1 = (uint32_t)*(uint16_t*)&l2 | ((uint32_t)*(uint16_t*)&l3 << 16);

            char* asb = sm + (iter & 1) * DCN_A_ST;
            *(uint2*)(asb +        px_s*48 + cq*8) = make_uint2(hp0, hp1);
            *(uint2*)(asb + 3072 + px_s*48 + cq*8) = make_uint2(lp0, lp1);
        }

        __syncthreads();

        if (iter + 2 < 72) {
            const char* src = (const char*)wtp + (size_t)(iter + 2) * 12288;
            uint32_t dstb = smWT + (uint32_t)((iter + 2) % 3) * DCN_WT_ST;
#pragma unroll
            for (int i = 0; i < 3; i++)
                cp_async16(dstb + (uint32_t)(tid + i*256)*16u, src + (tid + i*256)*16);
        }
        asm volatile("cp.async.commit_group;");
        asm volatile("cp.async.wait_group 2;");

        const uint32_t astage = sbase + (uint32_t)(iter & 1) * DCN_A_ST;
        const uint32_t wstage = smWT + (uint32_t)(iter % 3) * DCN_WT_ST;

        uint32_t bh[2][4], bl[2][4];
#pragma unroll
        for (int nfp = 0; nfp < 2; nfp++) {
            uint32_t ba = wstage + boffL + (uint32_t)(nfp*16*48);
            ldsm_x4(bh[nfp], ba);
            ldsm_x4(bl[nfp], ba + 6144u);
        }
#pragma unroll
        for (int mf = 0; mf < 2; mf++) {
            uint32_t ar = aoffL + astage + (uint32_t)(mf*16*48);
            uint32_t ah[4], al[4];
            ldsm_x4(ah, ar);
            ldsm_x4(al, ar + 3072u);
#pragma unroll
            for (int nf = 0; nf < 4; nf++) {
                const uint32_t* bhp = &bh[nf >> 1][(nf & 1) * 2];
                const uint32_t* blp = &bl[nf >> 1][(nf & 1) * 2];
                mma_bf16(acc[mf][nf], ah, bhp);
                mma_bf16(acc[mf][nf], ah, blp);
                mma_bf16(acc[mf][nf], al, bhp);
            }
        }
    }

    const int r0 = warp_m*32 + (lane >> 2);
#pragma unroll
    for (int nf = 0; nf < 4; nf++) {
        const int co_a = warp_n*32 + nf*8 + (lane & 3)*2;
        const int co_b = co_a + 1;
        const float ba_ = bias[co_a];
        const float bb_ = bias[co_b];
#pragma unroll
        for (int mf = 0; mf < 2; mf++) {
            const int p1 = r0 + mf*16;
            const int p2 = p1 + 8;
            const int o1 = (y0 + (p1 >> 3))*WW + x0 + (p1 & 7);
            const int o2 = (y0 + (p2 >> 3))*WW + x0 + (p2 & 7);
            out[((size_t)(b*128 + co_a))*HW + o1] = fmaxf(acc[mf][nf][0] + ba_, 0.f);
            out[((size_t)(b*128 + co_b))*HW + o1] = fmaxf(acc[mf][nf][1] + bb_, 0.f);
            out[((size_t)(b*128 + co_a))*HW + o2] = fmaxf(acc[mf][nf][2] + ba_, 0.f);
            out[((size_t)(b*128 + co_b))*HW + o2] = fmaxf(acc[mf][nf][3] + bb_, 0.f);
        }
    }
}

// ============================================================================
extern "C" void kernel_launch(void* const* d_in, const int* in_sizes, int n_in,
                              void* d_out, int out_size)
{
    (void)in_sizes; (void)n_in; (void)out_size;
    const float* R1    = (const float*)d_in[0];
    const float* Q0    = (const float*)d_in[1];
    const float* w1    = (const float*)d_in[2];
    const float* b1    = (const float*)d_in[3];
    const float* w2    = (const float*)d_in[4];
    const float* b2    = (const float*)d_in[5];
    const float* w_om  = (const float*)d_in[6];
    const float* b_om  = (const float*)d_in[7];
    const float* w_dcn = (const float*)d_in[8];
    const float* b_dcn = (const float*)d_in[9];
    const float* w_rq  = (const float*)d_in[10];
    const float* b_rq  = (const float*)d_in[11];
    float* out = (float*)d_out;

    float *om, *fea, *wp1, *wp2, *wpom, *wprq, *wtp, *dinf, *t1f, *t2f, *r1px;
    cudaGetSymbolAddress((void**)&om,   g_om);
    cudaGetSymbolAddress((void**)&fea,  g_fea);
    cudaGetSymbolAddress((void**)&wp1,  g_wp1);
    cudaGetSymbolAddress((void**)&wp2,  g_wp2);
    cudaGetSymbolAddress((void**)&wpom, g_wpom);
    cudaGetSymbolAddress((void**)&wprq, g_wprq);
    cudaGetSymbolAddress((void**)&wtp,  g_wtp);
    cudaGetSymbolAddress((void**)&dinf, g_din98);
    cudaGetSymbolAddress((void**)&t1f,  g_t1b98);
    cudaGetSymbolAddress((void**)&t2f,  g_t2b98);
    cudaGetSymbolAddress((void**)&r1px, g_R1px);
    __nv_bfloat16* din = (__nv_bfloat16*)dinf;
    __nv_bfloat16* t1b = (__nv_bfloat16*)t1f;
    __nv_bfloat16* t2b = (__nv_bfloat16*)t2f;

    cudaFuncSetAttribute(convPX_k<1>, cudaFuncAttributeMaxDynamicSharedMemorySize, CONVPX_SMEM);
    cudaFuncSetAttribute(convPX_k<0>, cudaFuncAttributeMaxDynamicSharedMemorySize, CONVPX_SMEM);
    cudaFuncSetAttribute(convR6_k,    cudaFuncAttributeMaxDynamicSharedMemorySize, CONVF_SMEM);
    cudaFuncSetAttribute(dcnMMA_k,    cudaFuncAttributeMaxDynamicSharedMemorySize, DCN_SMEM);

    // all prep in one launch (weights + transposes + border zeroing)
    prepack_all_k<<<684, 256>>>(R1, Q0, w1, w2, w_om, w_rq, w_dcn,
                                wp1, wp2, wpom, wprq, wtp, din, t1b, t2b, r1px);

    // conv1: relu(conv(R1-Q0)) -> t1 (padded px-major bf16)
    convPX_k<1><<<dim3(12,12,2), 256, CONVPX_SMEM>>>(din, wp1, b1, nullptr, t1b, 128, 1);
    // conv2: relu(conv(t1)) -> t2 (padded px-major bf16)
    convPX_k<1><<<dim3(12,12,2), 256, CONVPX_SMEM>>>(t1b, wp2, b2, nullptr, t2b, 128, 1);
    // conv_om: conv(t2) -> om (fp32 planar, 216 ch, 2 co-tiles)
    convPX_k<0><<<dim3(12,12,4), 256, CONVPX_SMEM>>>(t2b, wpom, b_om, om, nullptr, 216, 2);
    // deformable conv v2 + relu -> fea (fp32 planar); sampling from px-major R1
    dcnMMA_k<<<dim3(12,12,2), 256, DCN_SMEM>>>(r1px, om, wtp, b_dcn, fea);
    // conv_rq: relu(conv(concat(fea, Q0))) -> out
    convR6_k<<<dim3(12,12,2), 256, CONVF_SMEM>>>(fea, Q0, wprq, b_rq, out, 8);
}

// round 12
// speedup vs baseline: 3.0872x; 1.0812x over previous
#include <cuda_runtime.h>
#include <cuda_bf16.h>
#include <math.h>
#include <cstdint>

#define HH 96
#define WW 96
#define HW (HH*WW)

// padded pixel-major bf16 tensor: [b][plane(hi/lo)][98*98 px][128 ch]
#define PLANE98 (9604*128)
#define PXB98   (2*PLANE98)

// ======================= helpers =======================
__device__ __forceinline__ uint32_t smem_u32(const void* p) {
    uint32_t a;
    asm("{ .reg .u64 t; cvta.to.shared.u64 t, %1; cvt.u32.u64 %0, t; }" : "=r"(a) : "l"(p));
    return a;
}
__device__ __forceinline__ void cp_async16(uint32_t saddr, const void* g) {
    asm volatile("cp.async.cg.shared.global [%0], [%1], 16;" :: "r"(saddr), "l"(g));
}
__device__ __forceinline__ void ldsm_x4(uint32_t* r, uint32_t a) {
    asm volatile("ldmatrix.sync.aligned.m8n8.x4.shared.b16 {%0,%1,%2,%3}, [%4];"
        : "=r"(r[0]), "=r"(r[1]), "=r"(r[2]), "=r"(r[3]) : "r"(a));
}
__device__ __forceinline__ void mma_bf16(float* c, const uint32_t* a, const uint32_t* b) {
    asm volatile("mma.sync.aligned.m16n8k16.row.col.f32.bf16.bf16.f32 "
        "{%0,%1,%2,%3}, {%4,%5,%6,%7}, {%8,%9}, {%0,%1,%2,%3};"
        : "+f"(c[0]), "+f"(c[1]), "+f"(c[2]), "+f"(c[3])
        : "r"(a[0]), "r"(a[1]), "r"(a[2]), "r"(a[3]), "r"(b[0]), "r"(b[1]));
}

// ======================= scratch globals =======================
__device__ float g_om[2*216*HW];                    // conv_om out (fp32 planar)
__device__ __align__(128) float g_R1px[2*HW*128];   // R1 pixel-major fp32
// padded px-major bf16 tensors (float-backed)
__device__ __align__(128) float g_din98[PXB98];
__device__ __align__(128) float g_t1b98[PXB98];
__device__ __align__(128) float g_t2b98[PXB98];
__device__ __align__(128) float g_q098 [PXB98];
__device__ __align__(128) float g_fea98[PXB98];
// packed conv weights: per (chunk,tap) block 20480 B: [hi 128co x 80B][lo same]
__device__ __align__(128) float g_wp1[36*5120];
__device__ __align__(128) float g_wp2[36*5120];
__device__ __align__(128) float g_wpom[72*5120];
__device__ __align__(128) float g_wprq[72*5120];
// packed DCN weights: per (g,k) block 12288 B: [hi 128co x 48B][lo at +6144]
__device__ __align__(128) float g_wtp[72*3072];

// ============================================================================
// Merged prep (884 blocks):
// 0-215 conv weight packs | 216-287 dcn wt | 288-479 din98 | 480-671 R1px |
// 672-863 q098 | 864-883 border zero (5 tensors x b x plane)
// ============================================================================
__device__ __forceinline__ void pack_block(const float* __restrict__ w,
                                           float* __restrict__ dst,
                                           int CIN, int COUT, int co0,
                                           int cb, int tap)
{
    char* d = (char*)dst;
    for (int e = threadIdx.x; e < 128*40; e += 256) {
        int co = e / 40;
        int cl = e - co * 40;
        float v = 0.f;
        if (cl < 32 && (co0 + co) < COUT)
            v = w[((size_t)(co0 + co) * CIN + cb * 32 + cl) * 9 + tap];
        __nv_bfloat16 hi = __float2bfloat16(v);
        __nv_bfloat16 lo = __float2bfloat16(v - __bfloat162float(hi));
        *(__nv_bfloat16*)(d +         co * 80 + cl * 2) = hi;
        *(__nv_bfloat16*)(d + 10240 + co * 80 + cl * 2) = lo;
    }
}

__device__ __forceinline__ void transpose_px98(float ts[64][97],
                                               const float* __restrict__ srcA,
                                               const float* __restrict__ srcB,
                                               __nv_bfloat16* __restrict__ dst,
                                               int b, int y, bool diff)
{
    for (int half = 0; half < 2; half++) {
        for (int e = threadIdx.x; e < 64*96; e += 256) {
            int ci = e / 96;
            int x  = e - ci * 96;
            size_t idx = ((size_t)(b*128 + half*64 + ci)*96 + y)*96 + x;
            ts[ci][x] = diff ? (srcA[idx] - srcB[idx]) : srcA[idx];
        }
        __syncthreads();
        for (int e = threadIdx.x; e < 96*64; e += 256) {
            int x  = e / 64;
            int ci = e - x * 64;
            float v = ts[ci][x];
            __nv_bfloat16 hi = __float2bfloat16(v);
            __nv_bfloat16 lo = __float2bfloat16(v - __bfloat162float(hi));
            size_t o = (size_t)b*PXB98 + (size_t)((y+1)*98 + (x+1))*128 + half*64 + ci;
            dst[o]           = hi;
            dst[o + PLANE98] = lo;
        }
        __syncthreads();
    }
}

__global__ void prepack_all_k(const float* __restrict__ R1,
                              const float* __restrict__ Q0,
                              const float* __restrict__ w1,
                              const float* __restrict__ w2,
                              const float* __restrict__ w_om,
                              const float* __restrict__ w_rq,
                              const float* __restrict__ w_dcn,
                              float* __restrict__ wp1, float* __restrict__ wp2,
                              float* __restrict__ wpom, float* __restrict__ wprq,
                              float* __restrict__ wtp,
                              __nv_bfloat16* __restrict__ din,
                              __nv_bfloat16* __restrict__ t1b,
                              __nv_bfloat16* __restrict__ t2b,
                              __nv_bfloat16* __restrict__ q0p,
                              __nv_bfloat16* __restrict__ feap,
                              float* __restrict__ r1px)
{
    __shared__ float ts[64][97];
    const int blk = blockIdx.x;
    if (blk < 36) {
        pack_block(w1, wp1 + (size_t)blk*5120, 128, 128, 0, blk/9, blk%9);
    } else if (blk < 72) {
        int b2 = blk - 36;
        pack_block(w2, wp2 + (size_t)b2*5120, 128, 128, 0, b2/9, b2%9);
    } else if (blk < 108) {
        int b2 = blk - 72;
        pack_block(w_om, wpom + (size_t)b2*5120, 128, 216, 0, b2/9, b2%9);
    } else if (blk < 144) {
        int b2 = blk - 108;
        pack_block(w_om, wpom + (size_t)(36 + b2)*5120, 128, 216, 128, b2/9, b2%9);
    } else if (blk < 216) {
        int b2 = blk - 144;
        pack_block(w_rq, wprq + (size_t)b2*5120, 256, 128, 0, b2/9, b2%9);
    } else if (blk < 288) {
        int b2 = blk - 216;
        int g = b2 / 9, k = b2 % 9;
        char* d = (char*)wtp + (size_t)b2 * 12288;
        for (int e = threadIdx.x; e < 2048; e += 256) {
            int co = e >> 4;
            int c  = e & 15;
            float v = w_dcn[(co*128 + g*16 + c)*9 + k];
            __nv_bfloat16 hi = __float2bfloat16(v);
            __nv_bfloat16 lo = __float2bfloat16(v - __bfloat162float(hi));
            *(__nv_bfloat16*)(d +        co * 48 + c * 2) = hi;
            *(__nv_bfloat16*)(d + 6144 + co * 48 + c * 2) = lo;
        }
    } else if (blk < 480) {
        int tb = blk - 288;
        transpose_px98(ts, R1, Q0, din, tb / 96, tb % 96, true);
    } else if (blk < 672) {
        // R1px transpose (fp32, unpadded)
        int tb = blk - 480;
        int b  = tb / 96;
        int y  = tb % 96;
        for (int half = 0; half < 2; half++) {
            for (int e = threadIdx.x; e < 64*96; e += 256) {
                int ci = e / 96;
                int x  = e - ci * 96;
                ts[ci][x] = R1[((size_t)(b*128 + half*64 + ci)*96 + y)*96 + x];
            }
            __syncthreads();
            for (int e = threadIdx.x; e < 96*64; e += 256) {
                int x  = e / 64;
                int ci = e - x * 64;
                r1px[((size_t)b*HW + y*96 + x)*128 + half*64 + ci] = ts[ci][x];
            }
            __syncthreads();
        }
    } else if (blk < 864) {
        int tb = blk - 672;
        transpose_px98(ts, Q0, nullptr, q0p, tb / 96, tb % 96, false);
    } else {
        // border zeroing: 388 border px x 128 ch per (tensor,b,plane)
        int idx = blk - 864;
        int tensor = idx >> 2;          // 0 din, 1 t1b, 2 t2b, 3 q0p, 4 feap
        int b      = (idx >> 1) & 1;
        int plane  = idx & 1;
        uint32_t* dst = (uint32_t*)(tensor == 0 ? (void*)din :
                                    tensor == 1 ? (void*)t1b :
                                    tensor == 2 ? (void*)t2b :
                                    tensor == 3 ? (void*)q0p : (void*)feap);
        size_t base32 = ((size_t)b*PXB98 + (size_t)plane*PLANE98) >> 1;
        for (int e = threadIdx.x; e < 388*64; e += 256) {
            int pxi = e >> 6;
            int w   = e & 63;
            int y, x;
            if      (pxi < 98)  { y = 0;         x = pxi; }
            else if (pxi < 196) { y = 97;        x = pxi - 98; }
            else if (pxi < 292) { y = pxi-196+1; x = 0; }
            else                { y = pxi-292+1; x = 97; }
            dst[base32 + (size_t)(y*98 + x)*64 + w] = 0u;
        }
    }
}

// ============================================================================
// convPX_k: padded px-major bf16 input conv. CIN = nchunk*32.
// Chunks 0-3 from inA, 4-7 from inB (concat).
// OUTFMT: 0 = fp32 planar (COUT-guarded), 1 = padded bf16 px-major (COUT=128).
// ============================================================================
#define SMA_BUF 16000
#define SMBX_OFF 32000
#define SMBX_ST  20480
#define CONVPX_SMEM (32000 + 3*20480)   // 93440

__device__ __forceinline__ void loadA98(uint32_t sbase, int buf,
                                        const __nv_bfloat16* __restrict__ tA,
                                        const __nv_bfloat16* __restrict__ tB,
                                        int cbn, int b, int x0, int y0, int tid)
{
    const __nv_bfloat16* t = (cbn < 4) ? tA : tB;
    const int cbc = (cbn < 4) ? cbn : cbn - 4;
    const uint32_t abase = sbase + (uint32_t)buf * SMA_BUF;
#pragma unroll
    for (int i = 0; i < 4; i++) {
        int e = tid + i*256;
        if (e < 800) {
            int plane = e >= 400;
            int rr  = e - plane*400;
            int px  = rr >> 2;
            int seg = rr & 3;
            int gy  = y0 + px / 10;
            int gx  = x0 + px % 10;
            const __nv_bfloat16* src = t + (size_t)b*PXB98 + (size_t)plane*PLANE98
                                     + (size_t)(gy*98 + gx)*128 + cbc*32 + seg*8;
            cp_async16(abase + (uint32_t)(plane*8000 + px*80 + seg*16), src);
        }
    }
}

template<bool RELU, int OUTFMT>
__global__ __launch_bounds__(256, 2)
void convPX_k(const __nv_bfloat16* __restrict__ inA,
              const __nv_bfloat16* __restrict__ inB,
              const float* __restrict__ wpack0, const float* __restrict__ bias,
              float* __restrict__ out_f, __nv_bfloat16* __restrict__ out_b,
              int COUT, int ncot, int nchunk)
{
    extern __shared__ char sm[];
    const int tid    = threadIdx.x;
    const int lane   = tid & 31;
    const int wid    = tid >> 5;
    const int warp_m = wid & 1;
    const int warp_n = wid >> 1;
    const int x0     = blockIdx.x * 8;
    const int y0     = blockIdx.y * 8;
    const int b      = blockIdx.z / ncot;
    const int cot    = blockIdx.z % ncot;
    const int co0    = cot * 128;
    const float* wpack = wpack0 + (size_t)cot * nchunk * 9 * 5120;

    const uint32_t sbase = smem_u32(sm);
    const uint32_t smB   = sbase + SMBX_OFF;

    const int dyL  = (lane >> 3) & 1;
    const int xL   = lane & 7;
    const int kAL  = (lane & 16) ? 16 : 0;
    const uint32_t aoffL = (uint32_t)((dyL*10 + xL)*80 + kAL) + (uint32_t)warp_m*3200u;
    const int colL = (lane & 7) + ((lane & 16) ? 8 : 0);
    const int kBL  = (lane & 8) ? 16 : 0;
    const uint32_t boffL = (uint32_t)((warp_n*32 + colL)*80 + kBL);

    float acc[2][4][4];
#pragma unroll
    for (int i = 0; i < 2; i++)
#pragma unroll
        for (int j = 0; j < 4; j++)
#pragma unroll
            for (int k = 0; k < 4; k++) acc[i][j][k] = 0.f;

    const int niter = nchunk * 9;

    loadA98(sbase, 0, inA, inB, 0, b, x0, y0, tid);
    {
        const char* src = (const char*)wpack;
#pragma unroll
        for (int i = 0; i < 5; i++)
            cp_async16(smB + (uint32_t)(tid + i*256)*16u, src + (tid + i*256)*16);
        asm volatile("cp.async.commit_group;");
        src += 20480;
#pragma unroll
        for (int i = 0; i < 5; i++)
            cp_async16(smB + SMBX_ST + (uint32_t)(tid + i*256)*16u, src + (tid + i*256)*16);
        asm volatile("cp.async.commit_group;");
    }

    for (int iter = 0; iter < niter; iter++) {
        const int cb  = iter / 9;
        const int tap = iter - cb * 9;
        const int ky  = tap / 3, kx = tap % 3;

        __syncthreads();

        if (tap == 0 && cb + 1 < nchunk)
            loadA98(sbase, (cb + 1) & 1, inA, inB, cb + 1, b, x0, y0, tid);
        if (iter + 2 < niter) {
            const char* src = (const char*)wpack + (size_t)(iter + 2) * 20480;
            uint32_t dstb = smB + (uint32_t)((iter + 2) % 3) * SMBX_ST;
#pragma unroll
            for (int i = 0; i < 5; i++)
                cp_async16(dstb + (uint32_t)(tid + i*256)*16u, src + (tid + i*256)*16);
        }
        asm volatile("cp.async.commit_group;");
        asm volatile("cp.async.wait_group 2;");
        __syncthreads();

        const uint32_t abase  = sbase + (uint32_t)(cb & 1) * SMA_BUF;
        const uint32_t bstage = smB + (uint32_t)(iter % 3) * SMBX_ST;
        const uint32_t atap   = abase + aoffL + (uint32_t)((ky*10 + kx)*80);

#pragma unroll
        for (int ks = 0; ks < 2; ks++) {
            uint32_t bh[2][4], bl[2][4];
#pragma unroll
            for (int nfp = 0; nfp < 2; nfp++) {
                uint32_t ba = bstage + boffL + (uint32_t)(nfp*16*80 + ks*32);
                ldsm_x4(bh[nfp], ba);
                ldsm_x4(bl[nfp], ba + 10240u);
            }
#pragma unroll
            for (int mf = 0; mf < 2; mf++) {
                uint32_t ar = atap + (uint32_t)(mf*1600 + ks*32);
                uint32_t ah[4], al[4];
                ldsm_x4(ah, ar);
                ldsm_x4(al, ar + 8000u);
#pragma unroll
                for (int nf = 0; nf < 4; nf++) {
                    const uint32_t* bhp = &bh[nf >> 1][(nf & 1) * 2];
                    const uint32_t* blp = &bl[nf >> 1][(nf & 1) * 2];
                    mma_bf16(acc[mf][nf], ah, bhp);
                    mma_bf16(acc[mf][nf], ah, blp);
                    mma_bf16(acc[mf][nf], al, bhp);
                }
            }
        }
    }

    // ---- epilogue ----
    const int xr = lane >> 2;
#pragma unroll
    for (int nf = 0; nf < 4; nf++) {
        const int co_a = co0 + warp_n*32 + nf*8 + (lane & 3)*2;
        const int co_b = co_a + 1;
        const float ba_ = (co_a < COUT) ? bias[co_a] : 0.f;
        const float bb_ = (co_b < COUT) ? bias[co_b] : 0.f;
#pragma unroll
        for (int mf = 0; mf < 2; mf++) {
            const int ya = y0 + warp_m*4 + mf*2;
            float v0 = acc[mf][nf][0] + ba_;
            float v1 = acc[mf][nf][1] + bb_;
            float v2 = acc[mf][nf][2] + ba_;
            float v3 = acc[mf][nf][3] + bb_;
            if (RELU) {
                v0 = fmaxf(v0, 0.f); v1 = fmaxf(v1, 0.f);
                v2 = fmaxf(v2, 0.f); v3 = fmaxf(v3, 0.f);
            }
            if (OUTFMT == 1) {
                size_t o1 = (size_t)b*PXB98
                          + (size_t)((ya+1)*98 + x0 + xr + 1)*128 + (co_a - co0);
                size_t o2 = o1 + 98*128;
                __nv_bfloat16 h0 = __float2bfloat16(v0);
                __nv_bfloat16 h1 = __float2bfloat16(v1);
                __nv_bfloat16 h2 = __float2bfloat16(v2);
                __nv_bfloat16 h3 = __float2bfloat16(v3);
                *(uint32_t*)&out_b[o1] = (uint32_t)*(uint16_t*)&h0 | ((uint32_t)*(uint16_t*)&h1 << 16);
                *(uint32_t*)&out_b[o2] = (uint32_t)*(uint16_t*)&h2 | ((uint32_t)*(uint16_t*)&h3 << 16);
                __nv_bfloat16 l0 = __float2bfloat16(v0 - __bfloat162float(h0));
                __nv_bfloat16 l1 = __float2bfloat16(v1 - __bfloat162float(h1));
                __nv_bfloat16 l2 = __float2bfloat16(v2 - __bfloat162float(h2));
                __nv_bfloat16 l3 = __float2bfloat16(v3 - __bfloat162float(h3));
                *(uint32_t*)&out_b[o1 + PLANE98] = (uint32_t)*(uint16_t*)&l0 | ((uint32_t)*(uint16_t*)&l1 << 16);
                *(uint32_t*)&out_b[o2 + PLANE98] = (uint32_t)*(uint16_t*)&l2 | ((uint32_t)*(uint16_t*)&l3 << 16);
            } else {
                if (co_a < COUT) {
                    out_f[((size_t)(b*COUT + co_a)*HH + ya    )*WW + x0 + xr] = v0;
                    out_f[((size_t)(b*COUT + co_a)*HH + ya + 1)*WW + x0 + xr] = v2;
                }
                if (co_b < COUT) {
                    out_f[((size_t)(b*COUT + co_b)*HH + ya    )*WW + x0 + xr] = v1;
                    out_f[((size_t)(b*COUT + co_b)*HH + ya + 1)*WW + x0 + xr] = v3;
                }
            }
        }
    }
}

// ============================================================================
// DCNv2 via mma.sync; px-major fp32 R1 sampling; px-major bf16 hi/lo output.
// ============================================================================
#define DCN_A_ST  6144
#define DCN_WT    12288
#define DCN_WT_ST 12288
#define DCN_SMEM  (12288 + 3*12288)   // 49152

__global__ __launch_bounds__(256, 2)
void dcnMMA_k(const float* __restrict__ R1px, const float* __restrict__ om,
              const float* __restrict__ wtp, const float* __restrict__ bias,
              __nv_bfloat16* __restrict__ feap)
{
    extern __shared__ char sm[];
    const int tid    = threadIdx.x;
    const int lane   = tid & 31;
    const int wid    = tid >> 5;
    const int warp_m = wid & 1;
    const int warp_n = wid >> 1;
    const int x0     = blockIdx.x * 8;
    const int y0     = blockIdx.y * 8;
    const int b      = blockIdx.z;

    const uint32_t sbase = smem_u32(sm);
    const uint32_t smWT  = sbase + DCN_WT;

    const int px_s = tid >> 2;
    const int cq   = tid & 3;
    const int hs   = y0 + (px_s >> 3);
    const int gxs  = x0 + (px_s & 7);

    const uint32_t aoffL = (uint32_t)((lane & 15) * 48 + ((lane & 16) ? 16 : 0))
                         + (uint32_t)warp_m * (32*48);
    const int colL = (lane & 7) + ((lane & 16) ? 8 : 0);
    const int kBL  = (lane & 8) ? 16 : 0;
    const uint32_t boffL = (uint32_t)((warp_n*32 + colL)*48 + kBL);

    float acc[2][4][4];
#pragma unroll
    for (int i = 0; i < 2; i++)
#pragma unroll
        for (int j = 0; j < 4; j++)
#pragma unroll
            for (int k = 0; k < 4; k++) acc[i][j][k] = 0.f;

#pragma unroll
    for (int it = 0; it < 2; it++) {
        const char* src = (const char*)wtp + (size_t)it * 12288;
        uint32_t dstb = smWT + (uint32_t)it * DCN_WT_ST;
#pragma unroll
        for (int i = 0; i < 3; i++)
            cp_async16(dstb + (uint32_t)(tid + i*256)*16u, src + (tid + i*256)*16);
        asm volatile("cp.async.commit_group;");
    }

    for (int iter = 0; iter < 72; iter++) {
        const int g = iter / 9;
        const int k = iter - g * 9;
        const int ky = k / 3, kx = k % 3;

        {
            const int obase = (b*216)*HW + hs*WW + gxs;
            float dy = om[obase + (18*g + 2*k    ) * HW];
            float dx = om[obase + (18*g + 2*k + 1) * HW];
            float mr = om[obase + (144 + 9*g + k ) * HW];
            float m  = 1.f / (1.f + __expf(-mr));
            float py  = dy + (float)(ky + hs - 1);
            float pxx = dx + (float)(kx + gxs - 1);
            float fy = floorf(py), fx = floorf(pxx);
            float ly = py - fy,  lx = pxx - fx;
            int   yi = (int)fy,  xi = (int)fx;
            float w00 = (1.f-ly)*(1.f-lx)*m;
            float w01 = (1.f-ly)*lx*m;
            float w10 = ly*(1.f-lx)*m;
            float w11 = ly*lx*m;
            bool iy0 = (unsigned)yi     < (unsigned)HH;
            bool iy1 = (unsigned)(yi+1) < (unsigned)HH;
            bool ix0 = (unsigned)xi     < (unsigned)WW;
            bool ix1 = (unsigned)(xi+1) < (unsigned)WW;

            const float* pb = R1px + (size_t)b*HW*128 + g*16 + cq*4;
            float4 z = make_float4(0.f, 0.f, 0.f, 0.f);
            float4 a00 = (iy0 && ix0) ? *(const float4*)(pb + (size_t)(yi*WW + xi)*128)         : z;
            float4 a01 = (iy0 && ix1) ? *(const float4*)(pb + (size_t)(yi*WW + xi + 1)*128)     : z;
            float4 a10 = (iy1 && ix0) ? *(const float4*)(pb + (size_t)((yi+1)*WW + xi)*128)     : z;
            float4 a11 = (iy1 && ix1) ? *(const float4*)(pb + (size_t)((yi+1)*WW + xi + 1)*128) : z;
            float vv0 = w00*a00.x + w01*a01.x + w10*a10.x + w11*a11.x;
            float vv1 = w00*a00.y + w01*a01.y + w10*a10.y + w11*a11.y;
            float vv2 = w00*a00.z + w01*a01.z + w10*a10.z + w11*a11.z;
            float vv3 = w00*a00.w + w01*a01.w + w10*a10.w + w11*a11.w;

            __nv_bfloat16 h0 = __float2bfloat16(vv0);
            __nv_bfloat16 h1 = __float2bfloat16(vv1);
            __nv_bfloat16 h2 = __float2bfloat16(vv2);
            __nv_bfloat16 h3 = __float2bfloat16(vv3);
            uint32_t hp0 = (uint32_t)*(uint16_t*)&h0 | ((uint32_t)*(uint16_t*)&h1 << 16);
            uint32_t hp1 = (uint32_t)*(uint16_t*)&h2 | ((uint32_t)*(uint16_t*)&h3 << 16);
            __nv_bfloat16 l0 = __float2bfloat16(vv0 - __bfloat162float(h0));
            __nv_bfloat16 l1 = __float2bfloat16(vv1 - __bfloat162float(h1));
            __nv_bfloat16 l2 = __float2bfloat16(vv2 - __bfloat162float(h2));
            __nv_bfloat16 l3 = __float2bfloat16(vv3 - __bfloat162float(h3));
            uint32_t lp0 = (uint32_t)*(uint16_t*)&l0 | ((uint32_t)*(uint16_t*)&l1 << 16);
            uint32_t lp1 = (uint32_t)*(uint16_t*)&l2 | ((uint32_t)*(uint16_t*)&l3 << 16);

            char* asb = sm + (iter & 1) * DCN_A_ST;
            *(uint2*)(asb +        px_s*48 + cq*8) = make_uint2(hp0, hp1);
            *(uint2*)(asb + 3072 + px_s*48 + cq*8) = make_uint2(lp0, lp1);
        }

        __syncthreads();

        if (iter + 2 < 72) {
            const char* src = (const char*)wtp + (size_t)(iter + 2) * 12288;
            uint32_t dstb = smWT + (uint32_t)((iter + 2) % 3) * DCN_WT_ST;
#pragma unroll
            for (int i = 0; i < 3; i++)
                cp_async16(dstb + (uint32_t)(tid + i*256)*16u, src + (tid + i*256)*16);
        }
        asm volatile("cp.async.commit_group;");
        asm volatile("cp.async.wait_group 2;");

        const uint32_t astage = sbase + (uint32_t)(iter & 1) * DCN_A_ST;
        const uint32_t wstage = smWT + (uint32_t)(iter % 3) * DCN_WT_ST;

        uint32_t bh[2][4], bl[2][4];
#pragma unroll
        for (int nfp = 0; nfp < 2; nfp++) {
            uint32_t ba = wstage + boffL + (uint32_t)(nfp*16*48);
            ldsm_x4(bh[nfp], ba);
            ldsm_x4(bl[nfp], ba + 6144u);
        }
#pragma unroll
        for (int mf = 0; mf < 2; mf++) {
            uint32_t ar = aoffL + astage + (uint32_t)(mf*16*48);
            uint32_t ah[4], al[4];
            ldsm_x4(ah, ar);
            ldsm_x4(al, ar + 3072u);
#pragma unroll
            for (int nf = 0; nf < 4; nf++) {
                const uint32_t* bhp = &bh[nf >> 1][(nf & 1) * 2];
                const uint32_t* blp = &bl[nf >> 1][(nf & 1) * 2];
                mma_bf16(acc[mf][nf], ah, bhp);
                mma_bf16(acc[mf][nf], ah, blp);
                mma_bf16(acc[mf][nf], al, bhp);
            }
        }
    }

    // ---- epilogue: bias + relu -> padded px-major bf16 hi/lo ----
    const int r0 = warp_m*32 + (lane >> 2);
#pragma unroll
    for (int nf = 0; nf < 4; nf++) {
        const int co_a = warp_n*32 + nf*8 + (lane & 3)*2;
        const float ba_ = bias[co_a];
        const float bb_ = bias[co_a + 1];
#pragma unroll
        for (int mf = 0; mf < 2; mf++) {
            const int p1 = r0 + mf*16;
            const int p2 = p1 + 8;
            const int y1 = y0 + (p1 >> 3), x1 = x0 + (p1 & 7);
            const int y2 = y0 + (p2 >> 3), x2 = x0 + (p2 & 7);
            float v0 = fmaxf(acc[mf][nf][0] + ba_, 0.f);
            float v1 = fmaxf(acc[mf][nf][1] + bb_, 0.f);
            float v2 = fmaxf(acc[mf][nf][2] + ba_, 0.f);
            float v3 = fmaxf(acc[mf][nf][3] + bb_, 0.f);
            size_t o1 = (size_t)b*PXB98 + (size_t)((y1+1)*98 + x1 + 1)*128 + co_a;
            size_t o2 = (size_t)b*PXB98 + (size_t)((y2+1)*98 + x2 + 1)*128 + co_a;
            __nv_bfloat16 h0 = __float2bfloat16(v0);
            __nv_bfloat16 h1 = __float2bfloat16(v1);
            __nv_bfloat16 h2 = __float2bfloat16(v2);
            __nv_bfloat16 h3 = __float2bfloat16(v3);
            *(uint32_t*)&feap[o1] = (uint32_t)*(uint16_t*)&h0 | ((uint32_t)*(uint16_t*)&h1 << 16);
            *(uint32_t*)&feap[o2] = (uint32_t)*(uint16_t*)&h2 | ((uint32_t)*(uint16_t*)&h3 << 16);
            __nv_bfloat16 l0 = __float2bfloat16(v0 - __bfloat162float(h0));
            __nv_bfloat16 l1 = __float2bfloat16(v1 - __bfloat162float(h1));
            __nv_bfloat16 l2 = __float2bfloat16(v2 - __bfloat162float(h2));
            __nv_bfloat16 l3 = __float2bfloat16(v3 - __bfloat162float(h3));
            *(uint32_t*)&feap[o1 + PLANE98] = (uint32_t)*(uint16_t*)&l0 | ((uint32_t)*(uint16_t*)&l1 << 16);
            *(uint32_t*)&feap[o2 + PLANE98] = (uint32_t)*(uint16_t*)&l2 | ((uint32_t)*(uint16_t*)&l3 << 16);
        }
    }
}

// ============================================================================
extern "C" void kernel_launch(void* const* d_in, const int* in_sizes, int n_in,
                              void* d_out, int out_size)
{
    (void)in_sizes; (void)n_in; (void)out_size;
    const float* R1    = (const float*)d_in[0];
    const float* Q0    = (const float*)d_in[1];
    const float* w1    = (const float*)d_in[2];
    const float* b1    = (const float*)d_in[3];
    const float* w2    = (const float*)d_in[4];
    const float* b2    = (const float*)d_in[5];
    const float* w_om  = (const float*)d_in[6];
    const float* b_om  = (const float*)d_in[7];
    const float* w_dcn = (const float*)d_in[8];
    const float* b_dcn = (const float*)d_in[9];
    const float* w_rq  = (const float*)d_in[10];
    const float* b_rq  = (const float*)d_in[11];
    float* out = (float*)d_out;

    float *om, *wp1, *wp2, *wpom, *wprq, *wtp, *dinf, *t1f, *t2f, *q0f, *feaf, *r1px;
    cudaGetSymbolAddress((void**)&om,   g_om);
    cudaGetSymbolAddress((void**)&wp1,  g_wp1);
    cudaGetSymbolAddress((void**)&wp2,  g_wp2);
    cudaGetSymbolAddress((void**)&wpom, g_wpom);
    cudaGetSymbolAddress((void**)&wprq, g_wprq);
    cudaGetSymbolAddress((void**)&wtp,  g_wtp);
    cudaGetSymbolAddress((void**)&dinf, g_din98);
    cudaGetSymbolAddress((void**)&t1f,  g_t1b98);
    cudaGetSymbolAddress((void**)&t2f,  g_t2b98);
    cudaGetSymbolAddress((void**)&q0f,  g_q098);
    cudaGetSymbolAddress((void**)&feaf, g_fea98);
    cudaGetSymbolAddress((void**)&r1px, g_R1px);
    __nv_bfloat16* din  = (__nv_bfloat16*)dinf;
    __nv_bfloat16* t1b  = (__nv_bfloat16*)t1f;
    __nv_bfloat16* t2b  = (__nv_bfloat16*)t2f;
    __nv_bfloat16* q0p  = (__nv_bfloat16*)q0f;
    __nv_bfloat16* feap = (__nv_bfloat16*)feaf;

    cudaFuncSetAttribute(convPX_k<true ,1>, cudaFuncAttributeMaxDynamicSharedMemorySize, CONVPX_SMEM);
    cudaFuncSetAttribute(convPX_k<false,0>, cudaFuncAttributeMaxDynamicSharedMemorySize, CONVPX_SMEM);
    cudaFuncSetAttribute(convPX_k<true ,0>, cudaFuncAttributeMaxDynamicSharedMemorySize, CONVPX_SMEM);
    cudaFuncSetAttribute(dcnMMA_k, cudaFuncAttributeMaxDynamicSharedMemorySize, DCN_SMEM);

    // all prep in one launch
    prepack_all_k<<<884, 256>>>(R1, Q0, w1, w2, w_om, w_rq, w_dcn,
                                wp1, wp2, wpom, wprq, wtp,
                                din, t1b, t2b, q0p, feap, r1px);

    // conv1: relu(conv(R1-Q0)) -> t1 (px-major bf16)
    convPX_k<true ,1><<<dim3(12,12,2), 256, CONVPX_SMEM>>>(din, din, wp1, b1, nullptr, t1b, 128, 1, 4);
    // conv2: relu(conv(t1)) -> t2 (px-major bf16)
    convPX_k<true ,1><<<dim3(12,12,2), 256, CONVPX_SMEM>>>(t1b, t1b, wp2, b2, nullptr, t2b, 128, 1, 4);
    // conv_om: conv(t2) -> om (fp32 planar, 216 ch)
    convPX_k<false,0><<<dim3(12,12,4), 256, CONVPX_SMEM>>>(t2b, t2b, wpom, b_om, om, nullptr, 216, 2, 4);
    // deformable conv v2 + relu -> fea (px-major bf16)
    dcnMMA_k<<<dim3(12,12,2), 256, DCN_SMEM>>>(r1px, om, wtp, b_dcn, feap);
    // conv_rq: relu(conv(concat(fea, Q0))) -> out (fp32 planar)
    convPX_k<true ,0><<<dim3(12,12,2), 256, CONVPX_SMEM>>>(feap, q0p, wprq, b_rq, out, nullptr, 128, 1, 8);
}

// round 13
// speedup vs baseline: 3.1512x; 1.0207x over previous
#include <cuda_runtime.h>
#include <cuda_bf16.h>
#include <math.h>
#include <cstdint>

#define HH 96
#define WW 96
#define HW (HH*WW)

// padded pixel-major bf16 tensor: [b][plane(hi/lo)][98*98 px][128 ch]
#define PLANE98 (9604*128)
#define PXB98   (2*PLANE98)

// ======================= helpers =======================
__device__ __forceinline__ uint32_t smem_u32(const void* p) {
    uint32_t a;
    asm("{ .reg .u64 t; cvta.to.shared.u64 t, %1; cvt.u32.u64 %0, t; }" : "=r"(a) : "l"(p));
    return a;
}
__device__ __forceinline__ void cp_async16(uint32_t saddr, const void* g) {
    asm volatile("cp.async.cg.shared.global [%0], [%1], 16;" :: "r"(saddr), "l"(g));
}
__device__ __forceinline__ void ldsm_x4(uint32_t* r, uint32_t a) {
    asm volatile("ldmatrix.sync.aligned.m8n8.x4.shared.b16 {%0,%1,%2,%3}, [%4];"
        : "=r"(r[0]), "=r"(r[1]), "=r"(r[2]), "=r"(r[3]) : "r"(a));
}
__device__ __forceinline__ void mma_bf16(float* c, const uint32_t* a, const uint32_t* b) {
    asm volatile("mma.sync.aligned.m16n8k16.row.col.f32.bf16.bf16.f32 "
        "{%0,%1,%2,%3}, {%4,%5,%6,%7}, {%8,%9}, {%0,%1,%2,%3};"
        : "+f"(c[0]), "+f"(c[1]), "+f"(c[2]), "+f"(c[3])
        : "r"(a[0]), "r"(a[1]), "r"(a[2]), "r"(a[3]), "r"(b[0]), "r"(b[1]));
}

// ======================= scratch globals =======================
__device__ float g_om[2*216*HW];                    // conv_om out (fp32 planar)
__device__ __align__(128) float g_R1px[2*HW*128];   // R1 pixel-major fp32
// padded px-major bf16 tensors (float-backed)
__device__ __align__(128) float g_din98[PXB98];
__device__ __align__(128) float g_t1b98[PXB98];
__device__ __align__(128) float g_t2b98[PXB98];
__device__ __align__(128) float g_q098 [PXB98];
__device__ __align__(128) float g_fea98[PXB98];
// packed conv weights: per (chunk,tap) block 20480 B: [hi 128co x 80B][lo same]
__device__ __align__(128) float g_wp1[36*5120];
__device__ __align__(128) float g_wp2[36*5120];
__device__ __align__(128) float g_wpom[72*5120];
__device__ __align__(128) float g_wprq[72*5120];
// packed DCN weights: per (g,k) block 12288 B: [hi 128co x 48B][lo at +6144]
__device__ __align__(128) float g_wtp[72*3072];

// ============================================================================
// Merged prep (884 blocks) — unchanged from R12.
// ============================================================================
__device__ __forceinline__ void pack_block(const float* __restrict__ w,
                                           float* __restrict__ dst,
                                           int CIN, int COUT, int co0,
                                           int cb, int tap)
{
    char* d = (char*)dst;
    for (int e = threadIdx.x; e < 128*40; e += 256) {
        int co = e / 40;
        int cl = e - co * 40;
        float v = 0.f;
        if (cl < 32 && (co0 + co) < COUT)
            v = w[((size_t)(co0 + co) * CIN + cb * 32 + cl) * 9 + tap];
        __nv_bfloat16 hi = __float2bfloat16(v);
        __nv_bfloat16 lo = __float2bfloat16(v - __bfloat162float(hi));
        *(__nv_bfloat16*)(d +         co * 80 + cl * 2) = hi;
        *(__nv_bfloat16*)(d + 10240 + co * 80 + cl * 2) = lo;
    }
}

__device__ __forceinline__ void transpose_px98(float ts[64][97],
                                               const float* __restrict__ srcA,
                                               const float* __restrict__ srcB,
                                               __nv_bfloat16* __restrict__ dst,
                                               int b, int y, bool diff)
{
    for (int half = 0; half < 2; half++) {
        for (int e = threadIdx.x; e < 64*96; e += 256) {
            int ci = e / 96;
            int x  = e - ci * 96;
            size_t idx = ((size_t)(b*128 + half*64 + ci)*96 + y)*96 + x;
            ts[ci][x] = diff ? (srcA[idx] - srcB[idx]) : srcA[idx];
        }
        __syncthreads();
        for (int e = threadIdx.x; e < 96*64; e += 256) {
            int x  = e / 64;
            int ci = e - x * 64;
            float v = ts[ci][x];
            __nv_bfloat16 hi = __float2bfloat16(v);
            __nv_bfloat16 lo = __float2bfloat16(v - __bfloat162float(hi));
            size_t o = (size_t)b*PXB98 + (size_t)((y+1)*98 + (x+1))*128 + half*64 + ci;
            dst[o]           = hi;
            dst[o + PLANE98] = lo;
        }
        __syncthreads();
    }
}

__global__ void prepack_all_k(const float* __restrict__ R1,
                              const float* __restrict__ Q0,
                              const float* __restrict__ w1,
                              const float* __restrict__ w2,
                              const float* __restrict__ w_om,
                              const float* __restrict__ w_rq,
                              const float* __restrict__ w_dcn,
                              float* __restrict__ wp1, float* __restrict__ wp2,
                              float* __restrict__ wpom, float* __restrict__ wprq,
                              float* __restrict__ wtp,
                              __nv_bfloat16* __restrict__ din,
                              __nv_bfloat16* __restrict__ t1b,
                              __nv_bfloat16* __restrict__ t2b,
                              __nv_bfloat16* __restrict__ q0p,
                              __nv_bfloat16* __restrict__ feap,
                              float* __restrict__ r1px)
{
    __shared__ float ts[64][97];
    const int blk = blockIdx.x;
    if (blk < 36) {
        pack_block(w1, wp1 + (size_t)blk*5120, 128, 128, 0, blk/9, blk%9);
    } else if (blk < 72) {
        int b2 = blk - 36;
        pack_block(w2, wp2 + (size_t)b2*5120, 128, 128, 0, b2/9, b2%9);
    } else if (blk < 108) {
        int b2 = blk - 72;
        pack_block(w_om, wpom + (size_t)b2*5120, 128, 216, 0, b2/9, b2%9);
    } else if (blk < 144) {
        int b2 = blk - 108;
        pack_block(w_om, wpom + (size_t)(36 + b2)*5120, 128, 216, 128, b2/9, b2%9);
    } else if (blk < 216) {
        int b2 = blk - 144;
        pack_block(w_rq, wprq + (size_t)b2*5120, 256, 128, 0, b2/9, b2%9);
    } else if (blk < 288) {
        int b2 = blk - 216;
        int g = b2 / 9, k = b2 % 9;
        char* d = (char*)wtp + (size_t)b2 * 12288;
        for (int e = threadIdx.x; e < 2048; e += 256) {
            int co = e >> 4;
            int c  = e & 15;
            float v = w_dcn[(co*128 + g*16 + c)*9 + k];
            __nv_bfloat16 hi = __float2bfloat16(v);
            __nv_bfloat16 lo = __float2bfloat16(v - __bfloat162float(hi));
            *(__nv_bfloat16*)(d +        co * 48 + c * 2) = hi;
            *(__nv_bfloat16*)(d + 6144 + co * 48 + c * 2) = lo;
        }
    } else if (blk < 480) {
        int tb = blk - 288;
        transpose_px98(ts, R1, Q0, din, tb / 96, tb % 96, true);
    } else if (blk < 672) {
        int tb = blk - 480;
        int b  = tb / 96;
        int y  = tb % 96;
        for (int half = 0; half < 2; half++) {
            for (int e = threadIdx.x; e < 64*96; e += 256) {
                int ci = e / 96;
                int x  = e - ci * 96;
                ts[ci][x] = R1[((size_t)(b*128 + half*64 + ci)*96 + y)*96 + x];
            }
            __syncthreads();
            for (int e = threadIdx.x; e < 96*64; e += 256) {
                int x  = e / 64;
                int ci = e - x * 64;
                r1px[((size_t)b*HW + y*96 + x)*128 + half*64 + ci] = ts[ci][x];
            }
            __syncthreads();
        }
    } else if (blk < 864) {
        int tb = blk - 672;
        transpose_px98(ts, Q0, nullptr, q0p, tb / 96, tb % 96, false);
    } else {
        int idx = blk - 864;
        int tensor = idx >> 2;
        int b      = (idx >> 1) & 1;
        int plane  = idx & 1;
        uint32_t* dst = (uint32_t*)(tensor == 0 ? (void*)din :
                                    tensor == 1 ? (void*)t1b :
                                    tensor == 2 ? (void*)t2b :
                                    tensor == 3 ? (void*)q0p : (void*)feap);
        size_t base32 = ((size_t)b*PXB98 + (size_t)plane*PLANE98) >> 1;
        for (int e = threadIdx.x; e < 388*64; e += 256) {
            int pxi = e >> 6;
            int w   = e & 63;
            int y, x;
            if      (pxi < 98)  { y = 0;         x = pxi; }
            else if (pxi < 196) { y = 97;        x = pxi - 98; }
            else if (pxi < 292) { y = pxi-196+1; x = 0; }
            else                { y = pxi-292+1; x = 97; }
            dst[base32 + (size_t)(y*98 + x)*64 + w] = 0u;
        }
    }
}

// ============================================================================
// convPX_k: single barrier per tap (wait_group -> barrier -> prefetch -> MMA).
// ============================================================================
#define SMA_BUF 16000
#define SMBX_OFF 32000
#define SMBX_ST  20480
#define CONVPX_SMEM (32000 + 3*20480)   // 93440

__device__ __forceinline__ void loadA98(uint32_t sbase, int buf,
                                        const __nv_bfloat16* __restrict__ tA,
                                        const __nv_bfloat16* __restrict__ tB,
                                        int cbn, int b, int x0, int y0, int tid)
{
    const __nv_bfloat16* t = (cbn < 4) ? tA : tB;
    const int cbc = (cbn < 4) ? cbn : cbn - 4;
    const uint32_t abase = sbase + (uint32_t)buf * SMA_BUF;
#pragma unroll
    for (int i = 0; i < 4; i++) {
        int e = tid + i*256;
        if (e < 800) {
            int plane = e >= 400;
            int rr  = e - plane*400;
            int px  = rr >> 2;
            int seg = rr & 3;
            int gy  = y0 + px / 10;
            int gx  = x0 + px % 10;
            const __nv_bfloat16* src = t + (size_t)b*PXB98 + (size_t)plane*PLANE98
                                     + (size_t)(gy*98 + gx)*128 + cbc*32 + seg*8;
            cp_async16(abase + (uint32_t)(plane*8000 + px*80 + seg*16), src);
        }
    }
}

template<bool RELU, int OUTFMT>
__global__ __launch_bounds__(256, 2)
void convPX_k(const __nv_bfloat16* __restrict__ inA,
              const __nv_bfloat16* __restrict__ inB,
              const float* __restrict__ wpack0, const float* __restrict__ bias,
              float* __restrict__ out_f, __nv_bfloat16* __restrict__ out_b,
              int COUT, int ncot, int nchunk)
{
    extern __shared__ char sm[];
    const int tid    = threadIdx.x;
    const int lane   = tid & 31;
    const int wid    = tid >> 5;
    const int warp_m = wid & 1;
    const int warp_n = wid >> 1;
    const int x0     = blockIdx.x * 8;
    const int y0     = blockIdx.y * 8;
    const int b      = blockIdx.z / ncot;
    const int cot    = blockIdx.z % ncot;
    const int co0    = cot * 128;
    const float* wpack = wpack0 + (size_t)cot * nchunk * 9 * 5120;

    const uint32_t sbase = smem_u32(sm);
    const uint32_t smB   = sbase + SMBX_OFF;

    const int dyL  = (lane >> 3) & 1;
    const int xL   = lane & 7;
    const int kAL  = (lane & 16) ? 16 : 0;
    const uint32_t aoffL = (uint32_t)((dyL*10 + xL)*80 + kAL) + (uint32_t)warp_m*3200u;
    const int colL = (lane & 7) + ((lane & 16) ? 8 : 0);
    const int kBL  = (lane & 8) ? 16 : 0;
    const uint32_t boffL = (uint32_t)((warp_n*32 + colL)*80 + kBL);

    float acc[2][4][4];
#pragma unroll
    for (int i = 0; i < 2; i++)
#pragma unroll
        for (int j = 0; j < 4; j++)
#pragma unroll
            for (int k = 0; k < 4; k++) acc[i][j][k] = 0.f;

    const int niter = nchunk * 9;

    // prologue: G0 = A(chunk0) + B0 ; G1 = B1
    loadA98(sbase, 0, inA, inB, 0, b, x0, y0, tid);
    {
        const char* src = (const char*)wpack;
#pragma unroll
        for (int i = 0; i < 5; i++)
            cp_async16(smB + (uint32_t)(tid + i*256)*16u, src + (tid + i*256)*16);
        asm volatile("cp.async.commit_group;");
        src += 20480;
#pragma unroll
        for (int i = 0; i < 5; i++)
            cp_async16(smB + SMBX_ST + (uint32_t)(tid + i*256)*16u, src + (tid + i*256)*16);
        asm volatile("cp.async.commit_group;");
    }

    for (int iter = 0; iter < niter; iter++) {
        const int cb  = iter / 9;
        const int tap = iter - cb * 9;
        const int ky  = tap / 3, kx = tap % 3;

        // iter's group (committed at iter-2 / prologue) drained for this thread
        asm volatile("cp.async.wait_group 1;");
        // single barrier: visibility of all threads' copies + WAR on stage/(A buf)
        __syncthreads();

        if (tap == 0 && cb + 1 < nchunk)
            loadA98(sbase, (cb + 1) & 1, inA, inB, cb + 1, b, x0, y0, tid);
        if (iter + 2 < niter) {
            const char* src = (const char*)wpack + (size_t)(iter + 2) * 20480;
            uint32_t dstb = smB + (uint32_t)((iter + 2) % 3) * SMBX_ST;
#pragma unroll
            for (int i = 0; i < 5; i++)
                cp_async16(dstb + (uint32_t)(tid + i*256)*16u, src + (tid + i*256)*16);
        }
        asm volatile("cp.async.commit_group;");

        const uint32_t abase  = sbase + (uint32_t)(cb & 1) * SMA_BUF;
        const uint32_t bstage = smB + (uint32_t)(iter % 3) * SMBX_ST;
        const uint32_t atap   = abase + aoffL + (uint32_t)((ky*10 + kx)*80);

#pragma unroll
        for (int ks = 0; ks < 2; ks++) {
            uint32_t bh[2][4], bl[2][4];
#pragma unroll
            for (int nfp = 0; nfp < 2; nfp++) {
                uint32_t ba = bstage + boffL + (uint32_t)(nfp*16*80 + ks*32);
                ldsm_x4(bh[nfp], ba);
                ldsm_x4(bl[nfp], ba + 10240u);
            }
#pragma unroll
            for (int mf = 0; mf < 2; mf++) {
                uint32_t ar = atap + (uint32_t)(mf*1600 + ks*32);
                uint32_t ah[4], al[4];
                ldsm_x4(ah, ar);
                ldsm_x4(al, ar + 8000u);
#pragma unroll
                for (int nf = 0; nf < 4; nf++) {
                    const uint32_t* bhp = &bh[nf >> 1][(nf & 1) * 2];
                    const uint32_t* blp = &bl[nf >> 1][(nf & 1) * 2];
                    mma_bf16(acc[mf][nf], ah, bhp);
                    mma_bf16(acc[mf][nf], ah, blp);
                    mma_bf16(acc[mf][nf], al, bhp);
                }
            }
        }
    }

    // ---- epilogue ----
    const int xr = lane >> 2;
#pragma unroll
    for (int nf = 0; nf < 4; nf++) {
        const int co_a = co0 + warp_n*32 + nf*8 + (lane & 3)*2;
        const int co_b = co_a + 1;
        const float ba_ = (co_a < COUT) ? bias[co_a] : 0.f;
        const float bb_ = (co_b < COUT) ? bias[co_b] : 0.f;
#pragma unroll
        for (int mf = 0; mf < 2; mf++) {
            const int ya = y0 + warp_m*4 + mf*2;
            float v0 = acc[mf][nf][0] + ba_;
            float v1 = acc[mf][nf][1] + bb_;
            float v2 = acc[mf][nf][2] + ba_;
            float v3 = acc[mf][nf][3] + bb_;
            if (RELU) {
                v0 = fmaxf(v0, 0.f); v1 = fmaxf(v1, 0.f);
                v2 = fmaxf(v2, 0.f); v3 = fmaxf(v3, 0.f);
            }
            if (OUTFMT == 1) {
                size_t o1 = (size_t)b*PXB98
                          + (size_t)((ya+1)*98 + x0 + xr + 1)*128 + (co_a - co0);
                size_t o2 = o1 + 98*128;
                __nv_bfloat16 h0 = __float2bfloat16(v0);
                __nv_bfloat16 h1 = __float2bfloat16(v1);
                __nv_bfloat16 h2 = __float2bfloat16(v2);
                __nv_bfloat16 h3 = __float2bfloat16(v3);
                *(uint32_t*)&out_b[o1] = (uint32_t)*(uint16_t*)&h0 | ((uint32_t)*(uint16_t*)&h1 << 16);
                *(uint32_t*)&out_b[o2] = (uint32_t)*(uint16_t*)&h2 | ((uint32_t)*(uint16_t*)&h3 << 16);
                __nv_bfloat16 l0 = __float2bfloat16(v0 - __bfloat162float(h0));
                __nv_bfloat16 l1 = __float2bfloat16(v1 - __bfloat162float(h1));
                __nv_bfloat16 l2 = __float2bfloat16(v2 - __bfloat162float(h2));
                __nv_bfloat16 l3 = __float2bfloat16(v3 - __bfloat162float(h3));
                *(uint32_t*)&out_b[o1 + PLANE98] = (uint32_t)*(uint16_t*)&l0 | ((uint32_t)*(uint16_t*)&l1 << 16);
                *(uint32_t*)&out_b[o2 + PLANE98] = (uint32_t)*(uint16_t*)&l2 | ((uint32_t)*(uint16_t*)&l3 << 16);
            } else {
                if (co_a < COUT) {
                    out_f[((size_t)(b*COUT + co_a)*HH + ya    )*WW + x0 + xr] = v0;
                    out_f[((size_t)(b*COUT + co_a)*HH + ya + 1)*WW + x0 + xr] = v2;
                }
                if (co_b < COUT) {
                    out_f[((size_t)(b*COUT + co_b)*HH + ya    )*WW + x0 + xr] = v1;
                    out_f[((size_t)(b*COUT + co_b)*HH + ya + 1)*WW + x0 + xr] = v3;
                }
            }
        }
    }
}

// ============================================================================
// DCNv2: quad-shfl param dedup + single wait-before-barrier ordering.
// ============================================================================
#define DCN_A_ST  6144
#define DCN_WT    12288
#define DCN_WT_ST 12288
#define DCN_SMEM  (12288 + 3*12288)   // 49152

__global__ __launch_bounds__(256, 2)
void dcnMMA_k(const float* __restrict__ R1px, const float* __restrict__ om,
              const float* __restrict__ wtp, const float* __restrict__ bias,
              __nv_bfloat16* __restrict__ feap)
{
    extern __shared__ char sm[];
    const int tid    = threadIdx.x;
    const int lane   = tid & 31;
    const int wid    = tid >> 5;
    const int warp_m = wid & 1;
    const int warp_n = wid >> 1;
    const int x0     = blockIdx.x * 8;
    const int y0     = blockIdx.y * 8;
    const int b      = blockIdx.z;

    const uint32_t sbase = smem_u32(sm);
    const uint32_t smWT  = sbase + DCN_WT;

    const int px_s = tid >> 2;
    const int cq   = tid & 3;
    const int hs   = y0 + (px_s >> 3);
    const int gxs  = x0 + (px_s & 7);
    const unsigned srcl = (unsigned)(lane & ~3);

    const uint32_t aoffL = (uint32_t)((lane & 15) * 48 + ((lane & 16) ? 16 : 0))
                         + (uint32_t)warp_m * (32*48);
    const int colL = (lane & 7) + ((lane & 16) ? 8 : 0);
    const int kBL  = (lane & 8) ? 16 : 0;
    const uint32_t boffL = (uint32_t)((warp_n*32 + colL)*48 + kBL);

    float acc[2][4][4];
#pragma unroll
    for (int i = 0; i < 2; i++)
#pragma unroll
        for (int j = 0; j < 4; j++)
#pragma unroll
            for (int k = 0; k < 4; k++) acc[i][j][k] = 0.f;

#pragma unroll
    for (int it = 0; it < 2; it++) {
        const char* src = (const char*)wtp + (size_t)it * 12288;
        uint32_t dstb = smWT + (uint32_t)it * DCN_WT_ST;
#pragma unroll
        for (int i = 0; i < 3; i++)
            cp_async16(dstb + (uint32_t)(tid + i*256)*16u, src + (tid + i*256)*16);
        asm volatile("cp.async.commit_group;");
    }

    for (int iter = 0; iter < 72; iter++) {
        const int g = iter / 9;
        const int k = iter - g * 9;

        // ---- params once per quad (cq==0), broadcast via shfl ----
        float w00, w01, w10, w11;
        int yi, xi;
        if (cq == 0) {
            const int ky = k / 3, kx = k % 3;
            const int obase = (b*216)*HW + hs*WW + gxs;
            float dy = om[obase + (18*g + 2*k    ) * HW];
            float dx = om[obase + (18*g + 2*k + 1) * HW];
            float mr = om[obase + (144 + 9*g + k ) * HW];
            float m  = 1.f / (1.f + __expf(-mr));
            float py  = dy + (float)(ky + hs - 1);
            float pxx = dx + (float)(kx + gxs - 1);
            float fy = floorf(py), fx = floorf(pxx);
            float ly = py - fy,  lx = pxx - fx;
            yi = (int)fy;  xi = (int)fx;
            w00 = (1.f-ly)*(1.f-lx)*m;
            w01 = (1.f-ly)*lx*m;
            w10 = ly*(1.f-lx)*m;
            w11 = ly*lx*m;
        }
        w00 = __shfl_sync(0xffffffffu, w00, srcl);
        w01 = __shfl_sync(0xffffffffu, w01, srcl);
        w10 = __shfl_sync(0xffffffffu, w10, srcl);
        w11 = __shfl_sync(0xffffffffu, w11, srcl);
        yi  = __shfl_sync(0xffffffffu, yi,  srcl);
        xi  = __shfl_sync(0xffffffffu, xi,  srcl);

        {
            bool iy0 = (unsigned)yi     < (unsigned)HH;
            bool iy1 = (unsigned)(yi+1) < (unsigned)HH;
            bool ix0 = (unsigned)xi     < (unsigned)WW;
            bool ix1 = (unsigned)(xi+1) < (unsigned)WW;

            const float* pb = R1px + (size_t)b*HW*128 + g*16 + cq*4;
            float4 z = make_float4(0.f, 0.f, 0.f, 0.f);
            float4 a00 = (iy0 && ix0) ? *(const float4*)(pb + (size_t)(yi*WW + xi)*128)         : z;
            float4 a01 = (iy0 && ix1) ? *(const float4*)(pb + (size_t)(yi*WW + xi + 1)*128)     : z;
            float4 a10 = (iy1 && ix0) ? *(const float4*)(pb + (size_t)((yi+1)*WW + xi)*128)     : z;
            float4 a11 = (iy1 && ix1) ? *(const float4*)(pb + (size_t)((yi+1)*WW + xi + 1)*128) : z;
            float vv0 = w00*a00.x + w01*a01.x + w10*a10.x + w11*a11.x;
            float vv1 = w00*a00.y + w01*a01.y + w10*a10.y + w11*a11.y;
            float vv2 = w00*a00.z + w01*a01.z + w10*a10.z + w11*a11.z;
            float vv3 = w00*a00.w + w01*a01.w + w10*a10.w + w11*a11.w;

            __nv_bfloat16 h0 = __float2bfloat16(vv0);
            __nv_bfloat16 h1 = __float2bfloat16(vv1);
            __nv_bfloat16 h2 = __float2bfloat16(vv2);
            __nv_bfloat16 h3 = __float2bfloat16(vv3);
            uint32_t hp0 = (uint32_t)*(uint16_t*)&h0 | ((uint32_t)*(uint16_t*)&h1 << 16);
            uint32_t hp1 = (uint32_t)*(uint16_t*)&h2 | ((uint32_t)*(uint16_t*)&h3 << 16);
            __nv_bfloat16 l0 = __float2bfloat16(vv0 - __bfloat162float(h0));
            __nv_bfloat16 l1 = __float2bfloat16(vv1 - __bfloat162float(h1));
            __nv_bfloat16 l2 = __float2bfloat16(vv2 - __bfloat162float(h2));
            __nv_bfloat16 l3 = __float2bfloat16(vv3 - __bfloat162float(h3));
            uint32_t lp0 = (uint32_t)*(uint16_t*)&l0 | ((uint32_t)*(uint16_t*)&l1 << 16);
            uint32_t lp1 = (uint32_t)*(uint16_t*)&l2 | ((uint32_t)*(uint16_t*)&l3 << 16);

            char* asb = sm + (iter & 1) * DCN_A_ST;
            *(uint2*)(asb +        px_s*48 + cq*8) = make_uint2(hp0, hp1);
            *(uint2*)(asb + 3072 + px_s*48 + cq*8) = make_uint2(lp0, lp1);
        }

        // wt(iter) drained for this thread, then single barrier
        asm volatile("cp.async.wait_group 1;");
        __syncthreads();

        if (iter + 2 < 72) {
            const char* src = (const char*)wtp + (size_t)(iter + 2) * 12288;
            uint32_t dstb = smWT + (uint32_t)((iter + 2) % 3) * DCN_WT_ST;
#pragma unroll
            for (int i = 0; i < 3; i++)
                cp_async16(dstb + (uint32_t)(tid + i*256)*16u, src + (tid + i*256)*16);
        }
        asm volatile("cp.async.commit_group;");

        const uint32_t astage = sbase + (uint32_t)(iter & 1) * DCN_A_ST;
        const uint32_t wstage = smWT + (uint32_t)(iter % 3) * DCN_WT_ST;

        uint32_t bh[2][4], bl[2][4];
#pragma unroll
        for (int nfp = 0; nfp < 2; nfp++) {
            uint32_t ba = wstage + boffL + (uint32_t)(nfp*16*48);
            ldsm_x4(bh[nfp], ba);
            ldsm_x4(bl[nfp], ba + 6144u);
        }
#pragma unroll
        for (int mf = 0; mf < 2; mf++) {
            uint32_t ar = aoffL + astage + (uint32_t)(mf*16*48);
            uint32_t ah[4], al[4];
            ldsm_x4(ah, ar);
            ldsm_x4(al, ar + 3072u);
#pragma unroll
            for (int nf = 0; nf < 4; nf++) {
                const uint32_t* bhp = &bh[nf >> 1][(nf & 1) * 2];
                const uint32_t* blp = &bl[nf >> 1][(nf & 1) * 2];
                mma_bf16(acc[mf][nf], ah, bhp);
                mma_bf16(acc[mf][nf], ah, blp);
                mma_bf16(acc[mf][nf], al, bhp);
            }
        }
    }

    // ---- epilogue: bias + relu -> padded px-major bf16 hi/lo ----
    const int r0 = warp_m*32 + (lane >> 2);
#pragma unroll
    for (int nf = 0; nf < 4; nf++) {
        const int co_a = warp_n*32 + nf*8 + (lane & 3)*2;
        const float ba_ = bias[co_a];
        const float bb_ = bias[co_a + 1];
#pragma unroll
        for (int mf = 0; mf < 2; mf++) {
            const int p1 = r0 + mf*16;
            const int p2 = p1 + 8;
            const int y1 = y0 + (p1 >> 3), x1 = x0 + (p1 & 7);
            const int y2 = y0 + (p2 >> 3), x2 = x0 + (p2 & 7);
            float v0 = fmaxf(acc[mf][nf][0] + ba_, 0.f);
            float v1 = fmaxf(acc[mf][nf][1] + bb_, 0.f);
            float v2 = fmaxf(acc[mf][nf][2] + ba_, 0.f);
            float v3 = fmaxf(acc[mf][nf][3] + bb_, 0.f);
            size_t o1 = (size_t)b*PXB98 + (size_t)((y1+1)*98 + x1 + 1)*128 + co_a;
            size_t o2 = (size_t)b*PXB98 + (size_t)((y2+1)*98 + x2 + 1)*128 + co_a;
            __nv_bfloat16 h0 = __float2bfloat16(v0);
            __nv_bfloat16 h1 = __float2bfloat16(v1);
            __nv_bfloat16 h2 = __float2bfloat16(v2);
            __nv_bfloat16 h3 = __float2bfloat16(v3);
            *(uint32_t*)&feap[o1] = (uint32_t)*(uint16_t*)&h0 | ((uint32_t)*(uint16_t*)&h1 << 16);
            *(uint32_t*)&feap[o2] = (uint32_t)*(uint16_t*)&h2 | ((uint32_t)*(uint16_t*)&h3 << 16);
            __nv_bfloat16 l0 = __float2bfloat16(v0 - __bfloat162float(h0));
            __nv_bfloat16 l1 = __float2bfloat16(v1 - __bfloat162float(h1));
            __nv_bfloat16 l2 = __float2bfloat16(v2 - __bfloat162float(h2));
            __nv_bfloat16 l3 = __float2bfloat16(v3 - __bfloat162float(h3));
            *(uint32_t*)&feap[o1 + PLANE98] = (uint32_t)*(uint16_t*)&l0 | ((uint32_t)*(uint16_t*)&l1 << 16);
            *(uint32_t*)&feap[o2 + PLANE98] = (uint32_t)*(uint16_t*)&l2 | ((uint32_t)*(uint16_t*)&l3 << 16);
        }
    }
}

// ============================================================================
extern "C" void kernel_launch(void* const* d_in, const int* in_sizes, int n_in,
                              void* d_out, int out_size)
{
    (void)in_sizes; (void)n_in; (void)out_size;
    const float* R1    = (const float*)d_in[0];
    const float* Q0    = (const float*)d_in[1];
    const float* w1    = (const float*)d_in[2];
    const float* b1    = (const float*)d_in[3];
    const float* w2    = (const float*)d_in[4];
    const float* b2    = (const float*)d_in[5];
    const float* w_om  = (const float*)d_in[6];
    const float* b_om  = (const float*)d_in[7];
    const float* w_dcn = (const float*)d_in[8];
    const float* b_dcn = (const float*)d_in[9];
    const float* w_rq  = (const float*)d_in[10];
    const float* b_rq  = (const float*)d_in[11];
    float* out = (float*)d_out;

    float *om, *wp1, *wp2, *wpom, *wprq, *wtp, *dinf, *t1f, *t2f, *q0f, *feaf, *r1px;
    cudaGetSymbolAddress((void**)&om,   g_om);
    cudaGetSymbolAddress((void**)&wp1,  g_wp1);
    cudaGetSymbolAddress((void**)&wp2,  g_wp2);
    cudaGetSymbolAddress((void**)&wpom, g_wpom);
    cudaGetSymbolAddress((void**)&wprq, g_wprq);
    cudaGetSymbolAddress((void**)&wtp,  g_wtp);
    cudaGetSymbolAddress((void**)&dinf, g_din98);
    cudaGetSymbolAddress((void**)&t1f,  g_t1b98);
    cudaGetSymbolAddress((void**)&t2f,  g_t2b98);
    cudaGetSymbolAddress((void**)&q0f,  g_q098);
    cudaGetSymbolAddress((void**)&feaf, g_fea98);
    cudaGetSymbolAddress((void**)&r1px, g_R1px);
    __nv_bfloat16* din  = (__nv_bfloat16*)dinf;
    __nv_bfloat16* t1b  = (__nv_bfloat16*)t1f;
    __nv_bfloat16* t2b  = (__nv_bfloat16*)t2f;
    __nv_bfloat16* q0p  = (__nv_bfloat16*)q0f;
    __nv_bfloat16* feap = (__nv_bfloat16*)feaf;

    cudaFuncSetAttribute(convPX_k<true ,1>, cudaFuncAttributeMaxDynamicSharedMemorySize, CONVPX_SMEM);
    cudaFuncSetAttribute(convPX_k<false,0>, cudaFuncAttributeMaxDynamicSharedMemorySize, CONVPX_SMEM);
    cudaFuncSetAttribute(convPX_k<true ,0>, cudaFuncAttributeMaxDynamicSharedMemorySize, CONVPX_SMEM);
    cudaFuncSetAttribute(dcnMMA_k, cudaFuncAttributeMaxDynamicSharedMemorySize, DCN_SMEM);

    // all prep in one launch
    prepack_all_k<<<884, 256>>>(R1, Q0, w1, w2, w_om, w_rq, w_dcn,
                                wp1, wp2, wpom, wprq, wtp,
                                din, t1b, t2b, q0p, feap, r1px);

    // conv1: relu(conv(R1-Q0)) -> t1 (px-major bf16)
    convPX_k<true ,1><<<dim3(12,12,2), 256, CONVPX_SMEM>>>(din, din, wp1, b1, nullptr, t1b, 128, 1, 4);
    // conv2: relu(conv(t1)) -> t2 (px-major bf16)
    convPX_k<true ,1><<<dim3(12,12,2), 256, CONVPX_SMEM>>>(t1b, t1b, wp2, b2, nullptr, t2b, 128, 1, 4);
    // conv_om: conv(t2) -> om (fp32 planar, 216 ch)
    convPX_k<false,0><<<dim3(12,12,4), 256, CONVPX_SMEM>>>(t2b, t2b, wpom, b_om, om, nullptr, 216, 2, 4);
    // deformable conv v2 + relu -> fea (px-major bf16)
    dcnMMA_k<<<dim3(12,12,2), 256, DCN_SMEM>>>(r1px, om, wtp, b_dcn, feap);
    // conv_rq: relu(conv(concat(fea, Q0))) -> out (fp32 planar)
    convPX_k<true ,0><<<dim3(12,12,2), 256, CONVPX_SMEM>>>(feap, q0p, wprq, b_rq, out, nullptr, 128, 1, 8);
}

// round 15
// speedup vs baseline: 3.3397x; 1.0598x over previous
#include <cuda_runtime.h>
#include <cuda_bf16.h>
#include <math.h>
#include <cstdint>

#define HH 96
#define WW 96
#define HW (HH*WW)

// padded pixel-major bf16 tensor: [b][plane(hi/lo)][98*98 px][128 ch]
#define PLANE98 (9604*128)
#define PXB98   (2*PLANE98)

// ======================= helpers =======================
__device__ __forceinline__ uint32_t smem_u32(const void* p) {
    uint32_t a;
    asm("{ .reg .u64 t; cvta.to.shared.u64 t, %1; cvt.u32.u64 %0, t; }" : "=r"(a) : "l"(p));
    return a;
}
__device__ __forceinline__ void cp_async16(uint32_t saddr, const void* g) {
    asm volatile("cp.async.cg.shared.global [%0], [%1], 16;" :: "r"(saddr), "l"(g));
}
__device__ __forceinline__ void ldsm_x4(uint32_t* r, uint32_t a) {
    asm volatile("ldmatrix.sync.aligned.m8n8.x4.shared.b16 {%0,%1,%2,%3}, [%4];"
        : "=r"(r[0]), "=r"(r[1]), "=r"(r[2]), "=r"(r[3]) : "r"(a));
}
__device__ __forceinline__ void mma_bf16(float* c, const uint32_t* a, const uint32_t* b) {
    asm volatile("mma.sync.aligned.m16n8k16.row.col.f32.bf16.bf16.f32 "
        "{%0,%1,%2,%3}, {%4,%5,%6,%7}, {%8,%9}, {%0,%1,%2,%3};"
        : "+f"(c[0]), "+f"(c[1]), "+f"(c[2]), "+f"(c[3])
        : "r"(a[0]), "r"(a[1]), "r"(a[2]), "r"(a[3]), "r"(b[0]), "r"(b[1]));
}

// ======================= scratch globals =======================
__device__ float g_om[2*216*HW];                    // conv_om out (fp32 planar)
__device__ __align__(128) float g_R1px[2*HW*128];   // R1 pixel-major fp32
// padded px-major bf16 tensors (float-backed)
__device__ __align__(128) float g_din98[PXB98];
__device__ __align__(128) float g_t1b98[PXB98];
__device__ __align__(128) float g_t2b98[PXB98];
__device__ __align__(128) float g_q098 [PXB98];
__device__ __align__(128) float g_fea98[PXB98];
// packed conv weights: per (chunk,tap) block 20480 B: [hi 128co x 80B][lo same]
__device__ __align__(128) float g_wp1[36*5120];
__device__ __align__(128) float g_wp2[36*5120];
__device__ __align__(128) float g_wpom[72*5120];
__device__ __align__(128) float g_wprq[72*5120];
// packed DCN weights: per (g,k) block 12288 B: [hi 128co x 48B][lo at +6144]
__device__ __align__(128) float g_wtp[72*3072];

// ============================================================================
// Merged prep (884 blocks) — unchanged.
// ============================================================================
__device__ __forceinline__ void pack_block(const float* __restrict__ w,
                                           float* __restrict__ dst,
                                           int CIN, int COUT, int co0,
                                           int cb, int tap)
{
    char* d = (char*)dst;
    for (int e = threadIdx.x; e < 128*40; e += 256) {
        int co = e / 40;
        int cl = e - co * 40;
        float v = 0.f;
        if (cl < 32 && (co0 + co) < COUT)
            v = w[((size_t)(co0 + co) * CIN + cb * 32 + cl) * 9 + tap];
        __nv_bfloat16 hi = __float2bfloat16(v);
        __nv_bfloat16 lo = __float2bfloat16(v - __bfloat162float(hi));
        *(__nv_bfloat16*)(d +         co * 80 + cl * 2) = hi;
        *(__nv_bfloat16*)(d + 10240 + co * 80 + cl * 2) = lo;
    }
}

__device__ __forceinline__ void transpose_px98(float ts[64][97],
                                               const float* __restrict__ srcA,
                                               const float* __restrict__ srcB,
                                               __nv_bfloat16* __restrict__ dst,
                                               int b, int y, bool diff)
{
    for (int half = 0; half < 2; half++) {
        for (int e = threadIdx.x; e < 64*96; e += 256) {
            int ci = e / 96;
            int x  = e - ci * 96;
            size_t idx = ((size_t)(b*128 + half*64 + ci)*96 + y)*96 + x;
            ts[ci][x] = diff ? (srcA[idx] - srcB[idx]) : srcA[idx];
        }
        __syncthreads();
        for (int e = threadIdx.x; e < 96*64; e += 256) {
            int x  = e / 64;
            int ci = e - x * 64;
            float v = ts[ci][x];
            __nv_bfloat16 hi = __float2bfloat16(v);
            __nv_bfloat16 lo = __float2bfloat16(v - __bfloat162float(hi));
            size_t o = (size_t)b*PXB98 + (size_t)((y+1)*98 + (x+1))*128 + half*64 + ci;
            dst[o]           = hi;
            dst[o + PLANE98] = lo;
        }
        __syncthreads();
    }
}

__global__ void prepack_all_k(const float* __restrict__ R1,
                              const float* __restrict__ Q0,
                              const float* __restrict__ w1,
                              const float* __restrict__ w2,
                              const float* __restrict__ w_om,
                              const float* __restrict__ w_rq,
                              const float* __restrict__ w_dcn,
                              float* __restrict__ wp1, float* __restrict__ wp2,
                              float* __restrict__ wpom, float* __restrict__ wprq,
                              float* __restrict__ wtp,
                              __nv_bfloat16* __restrict__ din,
                              __nv_bfloat16* __restrict__ t1b,
                              __nv_bfloat16* __restrict__ t2b,
                              __nv_bfloat16* __restrict__ q0p,
                              __nv_bfloat16* __restrict__ feap,
                              float* __restrict__ r1px)
{
    __shared__ float ts[64][97];
    const int blk = blockIdx.x;
    if (blk < 36) {
        pack_block(w1, wp1 + (size_t)blk*5120, 128, 128, 0, blk/9, blk%9);
    } else if (blk < 72) {
        int b2 = blk - 36;
        pack_block(w2, wp2 + (size_t)b2*5120, 128, 128, 0, b2/9, b2%9);
    } else if (blk < 108) {
        int b2 = blk - 72;
        pack_block(w_om, wpom + (size_t)b2*5120, 128, 216, 0, b2/9, b2%9);
    } else if (blk < 144) {
        int b2 = blk - 108;
        pack_block(w_om, wpom + (size_t)(36 + b2)*5120, 128, 216, 128, b2/9, b2%9);
    } else if (blk < 216) {
        int b2 = blk - 144;
        pack_block(w_rq, wprq + (size_t)b2*5120, 256, 128, 0, b2/9, b2%9);
    } else if (blk < 288) {
        int b2 = blk - 216;
        int g = b2 / 9, k = b2 % 9;
        char* d = (char*)wtp + (size_t)b2 * 12288;
        for (int e = threadIdx.x; e < 2048; e += 256) {
            int co = e >> 4;
            int c  = e & 15;
            float v = w_dcn[(co*128 + g*16 + c)*9 + k];
            __nv_bfloat16 hi = __float2bfloat16(v);
            __nv_bfloat16 lo = __float2bfloat16(v - __bfloat162float(hi));
            *(__nv_bfloat16*)(d +        co * 48 + c * 2) = hi;
            *(__nv_bfloat16*)(d + 6144 + co * 48 + c * 2) = lo;
        }
    } else if (blk < 480) {
        int tb = blk - 288;
        transpose_px98(ts, R1, Q0, din, tb / 96, tb % 96, true);
    } else if (blk < 672) {
        int tb = blk - 480;
        int b  = tb / 96;
        int y  = tb % 96;
        for (int half = 0; half < 2; half++) {
            for (int e = threadIdx.x; e < 64*96; e += 256) {
                int ci = e / 96;
                int x  = e - ci * 96;
                ts[ci][x] = R1[((size_t)(b*128 + half*64 + ci)*96 + y)*96 + x];
            }
            __syncthreads();
            for (int e = threadIdx.x; e < 96*64; e += 256) {
                int x  = e / 64;
                int ci = e - x * 64;
                r1px[((size_t)b*HW + y*96 + x)*128 + half*64 + ci] = ts[ci][x];
            }
            __syncthreads();
        }
    } else if (blk < 864) {
        int tb = blk - 672;
        transpose_px98(ts, Q0, nullptr, q0p, tb / 96, tb % 96, false);
    } else {
        int idx = blk - 864;
        int tensor = idx >> 2;
        int b      = (idx >> 1) & 1;
        int plane  = idx & 1;
        uint32_t* dst = (uint32_t*)(tensor == 0 ? (void*)din :
                                    tensor == 1 ? (void*)t1b :
                                    tensor == 2 ? (void*)t2b :
                                    tensor == 3 ? (void*)q0p : (void*)feap);
        size_t base32 = ((size_t)b*PXB98 + (size_t)plane*PLANE98) >> 1;
        for (int e = threadIdx.x; e < 388*64; e += 256) {
            int pxi = e >> 6;
            int w   = e & 63;
            int y, x;
            if      (pxi < 98)  { y = 0;         x = pxi; }
            else if (pxi < 196) { y = 97;        x = pxi - 98; }
            else if (pxi < 292) { y = pxi-196+1; x = 0; }
            else                { y = pxi-292+1; x = 97; }
            dst[base32 + (size_t)(y*98 + x)*64 + w] = 0u;
        }
    }
}

// ============================================================================
// convPX_k: 2-tap windows, 4-stage B ring, one barrier per window.
// ============================================================================
#define SMA_BUF 16000
#define SMBX_OFF 32000
#define SMBX_ST  20480
#define CONVPX_SMEM (32000 + 4*20480)   // 113920

__device__ __forceinline__ void loadA98(uint32_t sbase, int buf,
                                        const __nv_bfloat16* __restrict__ tA,
                                        const __nv_bfloat16* __restrict__ tB,
                                        int cbn, int b, int x0, int y0, int tid)
{
    const __nv_bfloat16* t = (cbn < 4) ? tA : tB;
    const int cbc = (cbn < 4) ? cbn : cbn - 4;
    const uint32_t abase = sbase + (uint32_t)buf * SMA_BUF;
#pragma unroll
    for (int i = 0; i < 4; i++) {
        int e = tid + i*256;
        if (e < 800) {
            int plane = e >= 400;
            int rr  = e - plane*400;
            int px  = rr >> 2;
            int seg = rr & 3;
            int gy  = y0 + px / 10;
            int gx  = x0 + px % 10;
            const __nv_bfloat16* src = t + (size_t)b*PXB98 + (size_t)plane*PLANE98
                                     + (size_t)(gy*98 + gx)*128 + cbc*32 + seg*8;
            cp_async16(abase + (uint32_t)(plane*8000 + px*80 + seg*16), src);
        }
    }
}

__device__ __forceinline__ void loadB(uint32_t smB, const float* wpack, int it, int tid)
{
    const char* src = (const char*)wpack + (size_t)it * 20480;
    uint32_t dstb = smB + (uint32_t)(it & 3) * SMBX_ST;
#pragma unroll
    for (int i = 0; i < 5; i++)
        cp_async16(dstb + (uint32_t)(tid + i*256)*16u, src + (tid + i*256)*16);
}

template<bool RELU, int OUTFMT>
__global__ __launch_bounds__(256, 2)
void convPX_k(const __nv_bfloat16* __restrict__ inA,
              const __nv_bfloat16* __restrict__ inB,
              const float* __restrict__ wpack0, const float* __restrict__ bias,
              float* __restrict__ out_f, __nv_bfloat16* __restrict__ out_b,
              int COUT, int ncot, int nchunk)
{
    extern __shared__ char sm[];
    const int tid    = threadIdx.x;
    const int lane   = tid & 31;
    const int wid    = tid >> 5;
    const int warp_m = wid & 1;
    const int warp_n = wid >> 1;
    const int x0     = blockIdx.x * 8;
    const int y0     = blockIdx.y * 8;
    const int b      = blockIdx.z / ncot;
    const int cot    = blockIdx.z % ncot;
    const int co0    = cot * 128;
    const float* wpack = wpack0 + (size_t)cot * nchunk * 9 * 5120;

    const uint32_t sbase = smem_u32(sm);
    const uint32_t smB   = sbase + SMBX_OFF;

    const int dyL  = (lane >> 3) & 1;
    const int xL   = lane & 7;
    const int kAL  = (lane & 16) ? 16 : 0;
    const uint32_t aoffL = (uint32_t)((dyL*10 + xL)*80 + kAL) + (uint32_t)warp_m*3200u;
    const int colL = (lane & 7) + ((lane & 16) ? 8 : 0);
    const int kBL  = (lane & 8) ? 16 : 0;
    const uint32_t boffL = (uint32_t)((warp_n*32 + colL)*80 + kBL);

    float acc[2][4][4];
#pragma unroll
    for (int i = 0; i < 2; i++)
#pragma unroll
        for (int j = 0; j < 4; j++)
#pragma unroll
            for (int k = 0; k < 4; k++) acc[i][j][k] = 0.f;

    const int niter = nchunk * 9;
    const int nwin  = niter >> 1;

    // prologue: A(chunk0) + B(0)->s0 + B(1)->s1, one group
    loadA98(sbase, 0, inA, inB, 0, b, x0, y0, tid);
    loadB(smB, wpack, 0, tid);
    loadB(smB, wpack, 1, tid);
    asm volatile("cp.async.commit_group;");

    for (int w = 0; w < nwin; w++) {
        const int i0 = w * 2;

        asm volatile("cp.async.wait_group 0;");   // group(w-1): data for i0, i0+1
        __syncthreads();                          // publish + WAR

        // prefetch B for next window (stages disjoint from current reads)
        if (i0 + 2 < niter) loadB(smB, wpack, i0 + 2, tid);
        if (i0 + 3 < niter) loadB(smB, wpack, i0 + 3, tid);
        // A chunk prefetch at tap==2 (once per chunk, 7 taps of lead)
#pragma unroll
        for (int j = 0; j < 2; j++) {
            const int i = i0 + j;
            if (i % 9 == 2 && i / 9 + 1 < nchunk)
                loadA98(sbase, (i/9 + 1) & 1, inA, inB, i/9 + 1, b, x0, y0, tid);
        }
        asm volatile("cp.async.commit_group;");

#pragma unroll
        for (int j = 0; j < 2; j++) {
            const int i  = i0 + j;
            const int cb = i / 9;
            const int tap = i - cb * 9;
            const int ky = tap / 3, kx = tap % 3;
            const uint32_t abase  = sbase + (uint32_t)(cb & 1) * SMA_BUF;
            const uint32_t bstage = smB + (uint32_t)(i & 3) * SMBX_ST;
            const uint32_t atap   = abase + aoffL + (uint32_t)((ky*10 + kx)*80);

#pragma unroll
            for (int ks = 0; ks < 2; ks++) {
                uint32_t bh[2][4], bl[2][4];
#pragma unroll
                for (int nfp = 0; nfp < 2; nfp++) {
                    uint32_t ba = bstage + boffL + (uint32_t)(nfp*16*80 + ks*32);
                    ldsm_x4(bh[nfp], ba);
                    ldsm_x4(bl[nfp], ba + 10240u);
                }
#pragma unroll
                for (int mf = 0; mf < 2; mf++) {
                    uint32_t ar = atap + (uint32_t)(mf*1600 + ks*32);
                    uint32_t ah[4], al[4];
                    ldsm_x4(ah, ar);
                    ldsm_x4(al, ar + 8000u);
#pragma unroll
                    for (int nf = 0; nf < 4; nf++) {
                        const uint32_t* bhp = &bh[nf >> 1][(nf & 1) * 2];
                        const uint32_t* blp = &bl[nf >> 1][(nf & 1) * 2];
                        mma_bf16(acc[mf][nf], ah, bhp);
                        mma_bf16(acc[mf][nf], ah, blp);
                        mma_bf16(acc[mf][nf], al, bhp);
                    }
                }
            }
        }
    }

    // ---- epilogue ----
    const int xr = lane >> 2;
#pragma unroll
    for (int nf = 0; nf < 4; nf++) {
        const int co_a = co0 + warp_n*32 + nf*8 + (lane & 3)*2;
        const int co_b = co_a + 1;
        const float ba_ = (co_a < COUT) ? bias[co_a] : 0.f;
        const float bb_ = (co_b < COUT) ? bias[co_b] : 0.f;
#pragma unroll
        for (int mf = 0; mf < 2; mf++) {
            const int ya = y0 + warp_m*4 + mf*2;
            float v0 = acc[mf][nf][0] + ba_;
            float v1 = acc[mf][nf][1] + bb_;
            float v2 = acc[mf][nf][2] + ba_;
            float v3 = acc[mf][nf][3] + bb_;
            if (RELU) {
                v0 = fmaxf(v0, 0.f); v1 = fmaxf(v1, 0.f);
                v2 = fmaxf(v2, 0.f); v3 = fmaxf(v3, 0.f);
            }
            if (OUTFMT == 1) {
                size_t o1 = (size_t)b*PXB98
                          + (size_t)((ya+1)*98 + x0 + xr + 1)*128 + (co_a - co0);
                size_t o2 = o1 + 98*128;
                __nv_bfloat16 h0 = __float2bfloat16(v0);
                __nv_bfloat16 h1 = __float2bfloat16(v1);
                __nv_bfloat16 h2 = __float2bfloat16(v2);
                __nv_bfloat16 h3 = __float2bfloat16(v3);
                *(uint32_t*)&out_b[o1] = (uint32_t)*(uint16_t*)&h0 | ((uint32_t)*(uint16_t*)&h1 << 16);
                *(uint32_t*)&out_b[o2] = (uint32_t)*(uint16_t*)&h2 | ((uint32_t)*(uint16_t*)&h3 << 16);
                __nv_bfloat16 l0 = __float2bfloat16(v0 - __bfloat162float(h0));
                __nv_bfloat16 l1 = __float2bfloat16(v1 - __bfloat162float(h1));
                __nv_bfloat16 l2 = __float2bfloat16(v2 - __bfloat162float(h2));
                __nv_bfloat16 l3 = __float2bfloat16(v3 - __bfloat162float(h3));
                *(uint32_t*)&out_b[o1 + PLANE98] = (uint32_t)*(uint16_t*)&l0 | ((uint32_t)*(uint16_t*)&l1 << 16);
                *(uint32_t*)&out_b[o2 + PLANE98] = (uint32_t)*(uint16_t*)&l2 | ((uint32_t)*(uint16_t*)&l3 << 16);
            } else {
                if (co_a < COUT) {
                    out_f[((size_t)(b*COUT + co_a)*HH + ya    )*WW + x0 + xr] = v0;
                    out_f[((size_t)(b*COUT + co_a)*HH + ya + 1)*WW + x0 + xr] = v2;
                }
                if (co_b < COUT) {
                    out_f[((size_t)(b*COUT + co_b)*HH + ya    )*WW + x0 + xr] = v1;
                    out_f[((size_t)(b*COUT + co_b)*HH + ya + 1)*WW + x0 + xr] = v3;
                }
            }
        }
    }
}

// ============================================================================
// DCNv2: software-pipelined sampling + quad-shfl param dedup.
// ============================================================================
#define DCN_A_ST  6144
#define DCN_WT    12288
#define DCN_WT_ST 12288
#define DCN_SMEM  (12288 + 3*12288)   // 49152

__global__ __launch_bounds__(256, 2)
void dcnMMA_k(const float* __restrict__ R1px, const float* __restrict__ om,
              const float* __restrict__ wtp, const float* __restrict__ bias,
              __nv_bfloat16* __restrict__ feap)
{
    extern __shared__ char sm[];
    const int tid    = threadIdx.x;
    const int lane   = tid & 31;
    const int wid    = tid >> 5;
    const int warp_m = wid & 1;
    const int warp_n = wid >> 1;
    const int x0     = blockIdx.x * 8;
    const int y0     = blockIdx.y * 8;
    const int b      = blockIdx.z;

    const uint32_t sbase = smem_u32(sm);
    const uint32_t smWT  = sbase + DCN_WT;

    const int px_s = tid >> 2;
    const int cq   = tid & 3;
    const int hs   = y0 + (px_s >> 3);
    const int gxs  = x0 + (px_s & 7);
    const unsigned srcl = (unsigned)(lane & ~3);
    const int obase = (b*216)*HW + hs*WW + gxs;

    const uint32_t aoffL = (uint32_t)((lane & 15) * 48 + ((lane & 16) ? 16 : 0))
                         + (uint32_t)warp_m * (32*48);
    const int colL = (lane & 7) + ((lane & 16) ? 8 : 0);
    const int kBL  = (lane & 8) ? 16 : 0;
    const uint32_t boffL = (uint32_t)((warp_n*32 + colL)*48 + kBL);

    float acc[2][4][4];
#pragma unroll
    for (int i = 0; i < 2; i++)
#pragma unroll
        for (int j = 0; j < 4; j++)
#pragma unroll
            for (int k = 0; k < 4; k++) acc[i][j][k] = 0.f;

    // wt prologue
#pragma unroll
    for (int it = 0; it < 2; it++) {
        const char* src = (const char*)wtp + (size_t)it * 12288;
        uint32_t dstb = smWT + (uint32_t)it * DCN_WT_ST;
#pragma unroll
        for (int i = 0; i < 3; i++)
            cp_async16(dstb + (uint32_t)(tid + i*256)*16u, src + (tid + i*256)*16);
        asm volatile("cp.async.commit_group;");
    }

    float om_dy = 0.f, om_dx = 0.f, om_mr = 0.f;   // om regs for iter 'i+1'
    // load om(0)
    if (cq == 0) {
        om_dy = om[obase + (18*0 + 2*0    ) * HW];
        om_dx = om[obase + (18*0 + 2*0 + 1) * HW];
        om_mr = om[obase + (144 + 9*0 + 0 ) * HW];
    }

    // full sample(0) + STS stage 0
    {
        float w00, w01, w10, w11; int yi, xi;
        if (cq == 0) {
            float m  = 1.f / (1.f + __expf(-om_mr));
            float py  = om_dy + (float)(0 + hs - 1);
            float pxx = om_dx + (float)(0 + gxs - 1);
            float fy = floorf(py), fx = floorf(pxx);
            float ly = py - fy,  lx = pxx - fx;
            yi = (int)fy; xi = (int)fx;
            w00 = (1.f-ly)*(1.f-lx)*m; w01 = (1.f-ly)*lx*m;
            w10 = ly*(1.f-lx)*m;       w11 = ly*lx*m;
        }
        w00 = __shfl_sync(0xffffffffu, w00, srcl);
        w01 = __shfl_sync(0xffffffffu, w01, srcl);
        w10 = __shfl_sync(0xffffffffu, w10, srcl);
        w11 = __shfl_sync(0xffffffffu, w11, srcl);
        yi  = __shfl_sync(0xffffffffu, yi,  srcl);
        xi  = __shfl_sync(0xffffffffu, xi,  srcl);
        bool iy0 = (unsigned)yi < HH, iy1 = (unsigned)(yi+1) < HH;
        bool ix0 = (unsigned)xi < WW, ix1 = (unsigned)(xi+1) < WW;
        const float* pg = R1px + (size_t)b*HW*128 + 0*16 + cq*4;
        float4 z = make_float4(0.f,0.f,0.f,0.f);
        float4 a00 = (iy0&&ix0) ? *(const float4*)(pg + (size_t)(yi*WW+xi)*128)       : z;
        float4 a01 = (iy0&&ix1) ? *(const float4*)(pg + (size_t)(yi*WW+xi+1)*128)     : z;
        float4 a10 = (iy1&&ix0) ? *(const float4*)(pg + (size_t)((yi+1)*WW+xi)*128)   : z;
        float4 a11 = (iy1&&ix1) ? *(const float4*)(pg + (size_t)((yi+1)*WW+xi+1)*128) : z;
        float vv0 = w00*a00.x + w01*a01.x + w10*a10.x + w11*a11.x;
        float vv1 = w00*a00.y + w01*a01.y + w10*a10.y + w11*a11.y;
        float vv2 = w00*a00.z + w01*a01.z + w10*a10.z + w11*a11.z;
        float vv3 = w00*a00.w + w01*a01.w + w10*a10.w + w11*a11.w;
        __nv_bfloat16 h0=__float2bfloat16(vv0), h1=__float2bfloat16(vv1);
        __nv_bfloat16 h2=__float2bfloat16(vv2), h3=__float2bfloat16(vv3);
        uint32_t hp0 = (uint32_t)*(uint16_t*)&h0 | ((uint32_t)*(uint16_t*)&h1 << 16);
        uint32_t hp1 = (uint32_t)*(uint16_t*)&h2 | ((uint32_t)*(uint16_t*)&h3 << 16);
        __nv_bfloat16 l0=__float2bfloat16(vv0-__bfloat162float(h0));
        __nv_bfloat16 l1=__float2bfloat16(vv1-__bfloat162float(h1));
        __nv_bfloat16 l2=__float2bfloat16(vv2-__bfloat162float(h2));
        __nv_bfloat16 l3=__float2bfloat16(vv3-__bfloat162float(h3));
        uint32_t lp0 = (uint32_t)*(uint16_t*)&l0 | ((uint32_t)*(uint16_t*)&l1 << 16);
        uint32_t lp1 = (uint32_t)*(uint16_t*)&l2 | ((uint32_t)*(uint16_t*)&l3 << 16);
        *(uint2*)(sm +        px_s*48 + cq*8) = make_uint2(hp0, hp1);
        *(uint2*)(sm + 3072 + px_s*48 + cq*8) = make_uint2(lp0, lp1);
    }
    // load om(1)
    if (cq == 0) {
        om_dy = om[obase + (18*0 + 2*1    ) * HW];
        om_dx = om[obase + (18*0 + 2*1 + 1) * HW];
        om_mr = om[obase + (144 + 9*0 + 1 ) * HW];
    }

    for (int iter = 0; iter < 72; iter++) {
        // ---- step1: params(i+1) from om regs; issue R1 loads; load om(i+2) ----
        float w00, w01, w10, w11;
        float4 a00, a01, a10, a11;
        const int in1 = iter + 1;
        if (in1 < 72) {
            const int g1 = in1 / 9;
            const int k1 = in1 - g1 * 9;
            int yi, xi;
            if (cq == 0) {
                float m  = 1.f / (1.f + __expf(-om_mr));
                float py  = om_dy + (float)(k1/3 + hs - 1);
                float pxx = om_dx + (float)(k1%3 + gxs - 1);
                float fy = floorf(py), fx = floorf(pxx);
                float ly = py - fy,  lx = pxx - fx;
                yi = (int)fy; xi = (int)fx;
                w00 = (1.f-ly)*(1.f-lx)*m; w01 = (1.f-ly)*lx*m;
                w10 = ly*(1.f-lx)*m;       w11 = ly*lx*m;
            }
            w00 = __shfl_sync(0xffffffffu, w00, srcl);
            w01 = __shfl_sync(0xffffffffu, w01, srcl);
            w10 = __shfl_sync(0xffffffffu, w10, srcl);
            w11 = __shfl_sync(0xffffffffu, w11, srcl);
            yi  = __shfl_sync(0xffffffffu, yi,  srcl);
            xi  = __shfl_sync(0xffffffffu, xi,  srcl);
            bool iy0 = (unsigned)yi < HH, iy1 = (unsigned)(yi+1) < HH;
            bool ix0 = (unsigned)xi < WW, ix1 = (unsigned)(xi+1) < WW;
            const float* pg = R1px + (size_t)b*HW*128 + g1*16 + cq*4;
            float4 z = make_float4(0.f,0.f,0.f,0.f);
            a00 = (iy0&&ix0) ? *(const float4*)(pg + (size_t)(yi*WW+xi)*128)       : z;
            a01 = (iy0&&ix1) ? *(const float4*)(pg + (size_t)(yi*WW+xi+1)*128)     : z;
            a10 = (iy1&&ix0) ? *(const float4*)(pg + (size_t)((yi+1)*WW+xi)*128)   : z;
            a11 = (iy1&&ix1) ? *(const float4*)(pg + (size_t)((yi+1)*WW+xi+1)*128) : z;
            // om(i+2)
            const int in2 = iter + 2;
            if (in2 < 72 && cq == 0) {
                const int g2 = in2 / 9;
                const int k2 = in2 - g2 * 9;
                om_dy = om[obase + (18*g2 + 2*k2    ) * HW];
                om_dx = om[obase + (18*g2 + 2*k2 + 1) * HW];
                om_mr = om[obase + (144 + 9*g2 + k2 ) * HW];
            }
        }

        // ---- step2/3: wt(iter) drained, publish stage(iter) ----
        asm volatile("cp.async.wait_group 1;");
        __syncthreads();

        // ---- step4: prefetch wt(iter+2) ----
        if (iter + 2 < 72) {
            const char* src = (const char*)wtp + (size_t)(iter + 2) * 12288;
            uint32_t dstb = smWT + (uint32_t)((iter + 2) % 3) * DCN_WT_ST;
#pragma unroll
            for (int i = 0; i < 3; i++)
                cp_async16(dstb + (uint32_t)(tid + i*256)*16u, src + (tid + i*256)*16);
        }
        asm volatile("cp.async.commit_group;");

        // ---- step5: MMA(iter) ----
        const uint32_t astage = sbase + (uint32_t)(iter & 1) * DCN_A_ST;
        const uint32_t wstage = smWT + (uint32_t)(iter % 3) * DCN_WT_ST;

        uint32_t bh[2][4], bl[2][4];
#pragma unroll
        for (int nfp = 0; nfp < 2; nfp++) {
            uint32_t ba = wstage + boffL + (uint32_t)(nfp*16*48);
            ldsm_x4(bh[nfp], ba);
            ldsm_x4(bl[nfp], ba + 6144u);
        }
#pragma unroll
        for (int mf = 0; mf < 2; mf++) {
            uint32_t ar = aoffL + astage + (uint32_t)(mf*16*48);
            uint32_t ah[4], al[4];
            ldsm_x4(ah, ar);
            ldsm_x4(al, ar + 3072u);
#pragma unroll
            for (int nf = 0; nf < 4; nf++) {
                const uint32_t* bhp = &bh[nf >> 1][(nf & 1) * 2];
                const uint32_t* blp = &bl[nf >> 1][(nf & 1) * 2];
                mma_bf16(acc[mf][nf], ah, bhp);
                mma_bf16(acc[mf][nf], ah, blp);
                mma_bf16(acc[mf][nf], al, bhp);
            }
        }

        // ---- step6: finish sample(i+1), STS stage (i+1)&1 ----
        if (in1 < 72) {
            float vv0 = w00*a00.x + w01*a01.x + w10*a10.x + w11*a11.x;
            float vv1 = w00*a00.y + w01*a01.y + w10*a10.y + w11*a11.y;
            float vv2 = w00*a00.z + w01*a01.z + w10*a10.z + w11*a11.z;
            float vv3 = w00*a00.w + w01*a01.w + w10*a10.w + w11*a11.w;
            __nv_bfloat16 h0=__float2bfloat16(vv0), h1=__float2bfloat16(vv1);
            __nv_bfloat16 h2=__float2bfloat16(vv2), h3=__float2bfloat16(vv3);
            uint32_t hp0 = (uint32_t)*(uint16_t*)&h0 | ((uint32_t)*(uint16_t*)&h1 << 16);
            uint32_t hp1 = (uint32_t)*(uint16_t*)&h2 | ((uint32_t)*(uint16_t*)&h3 << 16);
            __nv_bfloat16 l0=__float2bfloat16(vv0-__bfloat162float(h0));
            __nv_bfloat16 l1=__float2bfloat16(vv1-__bfloat162float(h1));
            __nv_bfloat16 l2=__float2bfloat16(vv2-__bfloat162float(h2));
            __nv_bfloat16 l3=__float2bfloat16(vv3-__bfloat162float(h3));
            uint32_t lp0 = (uint32_t)*(uint16_t*)&l0 | ((uint32_t)*(uint16_t*)&l1 << 16);
            uint32_t lp1 = (uint32_t)*(uint16_t*)&l2 | ((uint32_t)*(uint16_t*)&l3 << 16);
            char* asb = sm + (in1 & 1) * DCN_A_ST;
            *(uint2*)(asb +        px_s*48 + cq*8) = make_uint2(hp0, hp1);
            *(uint2*)(asb + 3072 + px_s*48 + cq*8) = make_uint2(lp0, lp1);
        }
    }

    // ---- epilogue: bias + relu -> padded px-major bf16 hi/lo ----
    const int r0 = warp_m*32 + (lane >> 2);
#pragma unroll
    for (int nf = 0; nf < 4; nf++) {
        const int co_a = warp_n*32 + nf*8 + (lane & 3)*2;
        const float ba_ = bias[co_a];
        const float bb_ = bias[co_a + 1];
#pragma unroll
        for (int mf = 0; mf < 2; mf++) {
            const int p1 = r0 + mf*16;
            const int p2 = p1 + 8;
            const int y1 = y0 + (p1 >> 3), x1 = x0 + (p1 & 7);
            const int y2 = y0 + (p2 >> 3), x2 = x0 + (p2 & 7);
            float v0 = fmaxf(acc[mf][nf][0] + ba_, 0.f);
            float v1 = fmaxf(acc[mf][nf][1] + bb_, 0.f);
            float v2 = fmaxf(acc[mf][nf][2] + ba_, 0.f);
            float v3 = fmaxf(acc[mf][nf][3] + bb_, 0.f);
            size_t o1 = (size_t)b*PXB98 + (size_t)((y1+1)*98 + x1 + 1)*128 + co_a;
            size_t o2 = (size_t)b*PXB98 + (size_t)((y2+1)*98 + x2 + 1)*128 + co_a;
            __nv_bfloat16 h0 = __float2bfloat16(v0);
            __nv_bfloat16 h1 = __float2bfloat16(v1);
            __nv_bfloat16 h2 = __float2bfloat16(v2);
            __nv_bfloat16 h3 = __float2bfloat16(v3);
            *(uint32_t*)&feap[o1] = (uint32_t)*(uint16_t*)&h0 | ((uint32_t)*(uint16_t*)&h1 << 16);
            *(uint32_t*)&feap[o2] = (uint32_t)*(uint16_t*)&h2 | ((uint32_t)*(uint16_t*)&h3 << 16);
            __nv_bfloat16 l0 = __float2bfloat16(v0 - __bfloat162float(h0));
            __nv_bfloat16 l1 = __float2bfloat16(v1 - __bfloat162float(h1));
            __nv_bfloat16 l2 = __float2bfloat16(v2 - __bfloat162float(h2));
            __nv_bfloat16 l3 = __float2bfloat16(v3 - __bfloat162float(h3));
            *(uint32_t*)&feap[o1 + PLANE98] = (uint32_t)*(uint16_t*)&l0 | ((uint32_t)*(uint16_t*)&l1 << 16);
            *(uint32_t*)&feap[o2 + PLANE98] = (uint32_t)*(uint16_t*)&l2 | ((uint32_t)*(uint16_t*)&l3 << 16);
        }
    }
}

// ============================================================================
extern "C" void kernel_launch(void* const* d_in, const int* in_sizes, int n_in,
                              void* d_out, int out_size)
{
    (void)in_sizes; (void)n_in; (void)out_size;
    const float* R1    = (const float*)d_in[0];
    const float* Q0    = (const float*)d_in[1];
    const float* w1    = (const float*)d_in[2];
    const float* b1    = (const float*)d_in[3];
    const float* w2    = (const float*)d_in[4];
    const float* b2    = (const float*)d_in[5];
    const float* w_om  = (const float*)d_in[6];
    const float* b_om  = (const float*)d_in[7];
    const float* w_dcn = (const float*)d_in[8];
    const float* b_dcn = (const float*)d_in[9];
    const float* w_rq  = (const float*)d_in[10];
    const float* b_rq  = (const float*)d_in[11];
    float* out = (float*)d_out;

    float *om, *wp1, *wp2, *wpom, *wprq, *wtp, *dinf, *t1f, *t2f, *q0f, *feaf, *r1px;
    cudaGetSymbolAddress((void**)&om,   g_om);
    cudaGetSymbolAddress((void**)&wp1,  g_wp1);
    cudaGetSymbolAddress((void**)&wp2,  g_wp2);
    cudaGetSymbolAddress((void**)&wpom, g_wpom);
    cudaGetSymbolAddress((void**)&wprq, g_wprq);
    cudaGetSymbolAddress((void**)&wtp,  g_wtp);
    cudaGetSymbolAddress((void**)&dinf, g_din98);
    cudaGetSymbolAddress((void**)&t1f,  g_t1b98);
    cudaGetSymbolAddress((void**)&t2f,  g_t2b98);
    cudaGetSymbolAddress((void**)&q0f,  g_q098);
    cudaGetSymbolAddress((void**)&feaf, g_fea98);
    cudaGetSymbolAddress((void**)&r1px, g_R1px);
    __nv_bfloat16* din  = (__nv_bfloat16*)dinf;
    __nv_bfloat16* t1b  = (__nv_bfloat16*)t1f;
    __nv_bfloat16* t2b  = (__nv_bfloat16*)t2f;
    __nv_bfloat16* q0p  = (__nv_bfloat16*)q0f;
    __nv_bfloat16* feap = (__nv_bfloat16*)feaf;

    cudaFuncSetAttribute(convPX_k<true ,1>, cudaFuncAttributeMaxDynamicSharedMemorySize, CONVPX_SMEM);
    cudaFuncSetAttribute(convPX_k<false,0>, cudaFuncAttributeMaxDynamicSharedMemorySize, CONVPX_SMEM);
    cudaFuncSetAttribute(convPX_k<true ,0>, cudaFuncAttributeMaxDynamicSharedMemorySize, CONVPX_SMEM);
    cudaFuncSetAttribute(dcnMMA_k, cudaFuncAttributeMaxDynamicSharedMemorySize, DCN_SMEM);

    // all prep in one launch
    prepack_all_k<<<884, 256>>>(R1, Q0, w1, w2, w_om, w_rq, w_dcn,
                                wp1, wp2, wpom, wprq, wtp,
                                din, t1b, t2b, q0p, feap, r1px);

    // conv1: relu(conv(R1-Q0)) -> t1 (px-major bf16)
    convPX_k<true ,1><<<dim3(12,12,2), 256, CONVPX_SMEM>>>(din, din, wp1, b1, nullptr, t1b, 128, 1, 4);
    // conv2: relu(conv(t1)) -> t2 (px-major bf16)
    convPX_k<true ,1><<<dim3(12,12,2), 256, CONVPX_SMEM>>>(t1b, t1b, wp2, b2, nullptr, t2b, 128, 1, 4);
    // conv_om: conv(t2) -> om (fp32 planar, 216 ch)
    convPX_k<false,0><<<dim3(12,12,4), 256, CONVPX_SMEM>>>(t2b, t2b, wpom, b_om, om, nullptr, 216, 2, 4);
    // deformable conv v2 + relu -> fea (px-major bf16)
    dcnMMA_k<<<dim3(12,12,2), 256, DCN_SMEM>>>(r1px, om, wtp, b_dcn, feap);
    // conv_rq: relu(conv(concat(fea, Q0))) -> out (fp32 planar)
    convPX_k<true ,0><<<dim3(12,12,2), 256, CONVPX_SMEM>>>(feap, q0p, wprq, b_rq, out, nullptr, 128, 1, 8);
}

// round 16
// speedup vs baseline: 3.4144x; 1.0224x over previous
#include <cuda_runtime.h>
#include <cuda_bf16.h>
#include <math.h>
#include <cstdint>

#define HH 96
#define WW 96
#define HW (HH*WW)

// padded pixel-major bf16 tensor: [b][plane(hi/lo)][98*98 px][128 ch]
#define PLANE98 (9604*128)
#define PXB98   (2*PLANE98)

// ======================= helpers =======================
__device__ __forceinline__ uint32_t smem_u32(const void* p) {
    uint32_t a;
    asm("{ .reg .u64 t; cvta.to.shared.u64 t, %1; cvt.u32.u64 %0, t; }" : "=r"(a) : "l"(p));
    return a;
}
__device__ __forceinline__ void cp_async16(uint32_t saddr, const void* g) {
    asm volatile("cp.async.cg.shared.global [%0], [%1], 16;" :: "r"(saddr), "l"(g));
}
__device__ __forceinline__ void ldsm_x4(uint32_t* r, uint32_t a) {
    asm volatile("ldmatrix.sync.aligned.m8n8.x4.shared.b16 {%0,%1,%2,%3}, [%4];"
        : "=r"(r[0]), "=r"(r[1]), "=r"(r[2]), "=r"(r[3]) : "r"(a));
}
__device__ __forceinline__ void mma_bf16(float* c, const uint32_t* a, const uint32_t* b) {
    asm volatile("mma.sync.aligned.m16n8k16.row.col.f32.bf16.bf16.f32 "
        "{%0,%1,%2,%3}, {%4,%5,%6,%7}, {%8,%9}, {%0,%1,%2,%3};"
        : "+f"(c[0]), "+f"(c[1]), "+f"(c[2]), "+f"(c[3])
        : "r"(a[0]), "r"(a[1]), "r"(a[2]), "r"(a[3]), "r"(b[0]), "r"(b[1]));
}

// ======================= scratch globals =======================
__device__ float g_om[2*216*HW];                    // conv_om out (fp32 planar)
__device__ __align__(128) float g_R1px[2*HW*128];   // R1 pixel-major fp32
// padded px-major bf16 tensors (float-backed)
__device__ __align__(128) float g_din98[PXB98];
__device__ __align__(128) float g_t1b98[PXB98];
__device__ __align__(128) float g_t2b98[PXB98];
__device__ __align__(128) float g_q098 [PXB98];
__device__ __align__(128) float g_fea98[PXB98];
// packed conv weights: per (chunk,tap) block 20480 B: [hi 128co x 80B][lo same]
__device__ __align__(128) float g_wp1[36*5120];
__device__ __align__(128) float g_wp2[36*5120];
__device__ __align__(128) float g_wpom[72*5120];
__device__ __align__(128) float g_wprq[72*5120];
// packed DCN weights: per (g,k) block 12288 B: [hi 128co x 48B][lo at +6144]
__device__ __align__(128) float g_wtp[72*3072];

// ============================================================================
// Merged prep (884 blocks).
// conv_om tile2 uses the NNF=3 row remap: channel v -> row (v/24)*32 + (v%24).
// ============================================================================
__device__ __forceinline__ void pack_block(const float* __restrict__ w,
                                           float* __restrict__ dst,
                                           int CIN, int COUT, int co0,
                                           int cb, int tap, bool remap)
{
    char* d = (char*)dst;
    for (int e = threadIdx.x; e < 128*40; e += 256) {
        int co = e / 40;
        int cl = e - co * 40;
        float v = 0.f;
        if (cl < 32) {
            int src = co;
            bool ok;
            if (remap) {
                ok = (co & 31) < 24;
                src = (co >> 5) * 24 + (co & 31);
                ok = ok && (co0 + src) < COUT;
            } else {
                ok = (co0 + co) < COUT;
            }
            if (ok) v = w[((size_t)(co0 + src) * CIN + cb * 32 + cl) * 9 + tap];
        }
        __nv_bfloat16 hi = __float2bfloat16(v);
        __nv_bfloat16 lo = __float2bfloat16(v - __bfloat162float(hi));
        *(__nv_bfloat16*)(d +         co * 80 + cl * 2) = hi;
        *(__nv_bfloat16*)(d + 10240 + co * 80 + cl * 2) = lo;
    }
}

__device__ __forceinline__ void transpose_px98(float ts[64][97],
                                               const float* __restrict__ srcA,
                                               const float* __restrict__ srcB,
                                               __nv_bfloat16* __restrict__ dst,
                                               int b, int y, bool diff)
{
    for (int half = 0; half < 2; half++) {
        for (int e = threadIdx.x; e < 64*96; e += 256) {
            int ci = e / 96;
            int x  = e - ci * 96;
            size_t idx = ((size_t)(b*128 + half*64 + ci)*96 + y)*96 + x;
            ts[ci][x] = diff ? (srcA[idx] - srcB[idx]) : srcA[idx];
        }
        __syncthreads();
        for (int e = threadIdx.x; e < 96*64; e += 256) {
            int x  = e / 64;
            int ci = e - x * 64;
            float v = ts[ci][x];
            __nv_bfloat16 hi = __float2bfloat16(v);
            __nv_bfloat16 lo = __float2bfloat16(v - __bfloat162float(hi));
            size_t o = (size_t)b*PXB98 + (size_t)((y+1)*98 + (x+1))*128 + half*64 + ci;
            dst[o]           = hi;
            dst[o + PLANE98] = lo;
        }
        __syncthreads();
    }
}

__global__ void prepack_all_k(const float* __restrict__ R1,
                              const float* __restrict__ Q0,
                              const float* __restrict__ w1,
                              const float* __restrict__ w2,
                              const float* __restrict__ w_om,
                              const float* __restrict__ w_rq,
                              const float* __restrict__ w_dcn,
                              float* __restrict__ wp1, float* __restrict__ wp2,
                              float* __restrict__ wpom, float* __restrict__ wprq,
                              float* __restrict__ wtp,
                              __nv_bfloat16* __restrict__ din,
                              __nv_bfloat16* __restrict__ t1b,
                              __nv_bfloat16* __restrict__ t2b,
                              __nv_bfloat16* __restrict__ q0p,
                              __nv_bfloat16* __restrict__ feap,
                              float* __restrict__ r1px)
{
    __shared__ float ts[64][97];
    const int blk = blockIdx.x;
    if (blk < 36) {
        pack_block(w1, wp1 + (size_t)blk*5120, 128, 128, 0, blk/9, blk%9, false);
    } else if (blk < 72) {
        int b2 = blk - 36;
        pack_block(w2, wp2 + (size_t)b2*5120, 128, 128, 0, b2/9, b2%9, false);
    } else if (blk < 108) {
        int b2 = blk - 72;
        pack_block(w_om, wpom + (size_t)b2*5120, 128, 216, 0, b2/9, b2%9, false);
    } else if (blk < 144) {
        int b2 = blk - 108;
        pack_block(w_om, wpom + (size_t)(36 + b2)*5120, 128, 216, 128, b2/9, b2%9, true);
    } else if (blk < 216) {
        int b2 = blk - 144;
        pack_block(w_rq, wprq + (size_t)b2*5120, 256, 128, 0, b2/9, b2%9, false);
    } else if (blk < 288) {
        int b2 = blk - 216;
        int g = b2 / 9, k = b2 % 9;
        char* d = (char*)wtp + (size_t)b2 * 12288;
        for (int e = threadIdx.x; e < 2048; e += 256) {
            int co = e >> 4;
            int c  = e & 15;
            float v = w_dcn[(co*128 + g*16 + c)*9 + k];
            __nv_bfloat16 hi = __float2bfloat16(v);
            __nv_bfloat16 lo = __float2bfloat16(v - __bfloat162float(hi));
            *(__nv_bfloat16*)(d +        co * 48 + c * 2) = hi;
            *(__nv_bfloat16*)(d + 6144 + co * 48 + c * 2) = lo;
        }
    } else if (blk < 480) {
        int tb = blk - 288;
        transpose_px98(ts, R1, Q0, din, tb / 96, tb % 96, true);
    } else if (blk < 672) {
        int tb = blk - 480;
        int b  = tb / 96;
        int y  = tb % 96;
        for (int half = 0; half < 2; half++) {
            for (int e = threadIdx.x; e < 64*96; e += 256) {
                int ci = e / 96;
                int x  = e - ci * 96;
                ts[ci][x] = R1[((size_t)(b*128 + half*64 + ci)*96 + y)*96 + x];
            }
            __syncthreads();
            for (int e = threadIdx.x; e < 96*64; e += 256) {
                int x  = e / 64;
                int ci = e - x * 64;
                r1px[((size_t)b*HW + y*96 + x)*128 + half*64 + ci] = ts[ci][x];
            }
            __syncthreads();
        }
    } else if (blk < 864) {
        int tb = blk - 672;
        transpose_px98(ts, Q0, nullptr, q0p, tb / 96, tb % 96, false);
    } else {
        int idx = blk - 864;
        int tensor = idx >> 2;
        int b      = (idx >> 1) & 1;
        int plane  = idx & 1;
        uint32_t* dst = (uint32_t*)(tensor == 0 ? (void*)din :
                                    tensor == 1 ? (void*)t1b :
                                    tensor == 2 ? (void*)t2b :
                                    tensor == 3 ? (void*)q0p : (void*)feap);
        size_t base32 = ((size_t)b*PXB98 + (size_t)plane*PLANE98) >> 1;
        for (int e = threadIdx.x; e < 388*64; e += 256) {
            int pxi = e >> 6;
            int w   = e & 63;
            int y, x;
            if      (pxi < 98)  { y = 0;         x = pxi; }
            else if (pxi < 196) { y = 97;        x = pxi - 98; }
            else if (pxi < 292) { y = pxi-196+1; x = 0; }
            else                { y = pxi-292+1; x = 97; }
            dst[base32 + (size_t)(y*98 + x)*64 + w] = 0u;
        }
    }
}

// ============================================================================
// convPX_k: 2-tap windows, 4-stage B ring, one barrier per window.
// NNF: number of 8-co fragments per warp (4 normal; 3 = remapped conv_om tile2).
// ============================================================================
#define SMA_BUF 16000
#define SMBX_OFF 32000
#define SMBX_ST  20480
#define CONVPX_SMEM (32000 + 4*20480)   // 113920

__device__ __forceinline__ void loadA98(uint32_t sbase, int buf,
                                        const __nv_bfloat16* __restrict__ tA,
                                        const __nv_bfloat16* __restrict__ tB,
                                        int cbn, int b, int x0, int y0, int tid)
{
    const __nv_bfloat16* t = (cbn < 4) ? tA : tB;
    const int cbc = (cbn < 4) ? cbn : cbn - 4;
    const uint32_t abase = sbase + (uint32_t)buf * SMA_BUF;
#pragma unroll
    for (int i = 0; i < 4; i++) {
        int e = tid + i*256;
        if (e < 800) {
            int plane = e >= 400;
            int rr  = e - plane*400;
            int px  = rr >> 2;
            int seg = rr & 3;
            int gy  = y0 + px / 10;
            int gx  = x0 + px % 10;
            const __nv_bfloat16* src = t + (size_t)b*PXB98 + (size_t)plane*PLANE98
                                     + (size_t)(gy*98 + gx)*128 + cbc*32 + seg*8;
            cp_async16(abase + (uint32_t)(plane*8000 + px*80 + seg*16), src);
        }
    }
}

__device__ __forceinline__ void loadB(uint32_t smB, const float* wpack, int it, int tid)
{
    const char* src = (const char*)wpack + (size_t)it * 20480;
    uint32_t dstb = smB + (uint32_t)(it & 3) * SMBX_ST;
#pragma unroll
    for (int i = 0; i < 5; i++)
        cp_async16(dstb + (uint32_t)(tid + i*256)*16u, src + (tid + i*256)*16);
}

template<bool RELU, int OUTFMT, int NNF>
__global__ __launch_bounds__(256, 2)
void convPX_k(const __nv_bfloat16* __restrict__ inA,
              const __nv_bfloat16* __restrict__ inB,
              const float* __restrict__ wpack, const float* __restrict__ bias,
              float* __restrict__ out_f, __nv_bfloat16* __restrict__ out_b,
              int COUT, int co0, int nchunk)
{
    extern __shared__ char sm[];
    const int tid    = threadIdx.x;
    const int lane   = tid & 31;
    const int wid    = tid >> 5;
    const int warp_m = wid & 1;
    const int warp_n = wid >> 1;
    const int x0     = blockIdx.x * 8;
    const int y0     = blockIdx.y * 8;
    const int b      = blockIdx.z;

    const uint32_t sbase = smem_u32(sm);
    const uint32_t smB   = sbase + SMBX_OFF;

    const int dyL  = (lane >> 3) & 1;
    const int xL   = lane & 7;
    const int kAL  = (lane & 16) ? 16 : 0;
    const uint32_t aoffL = (uint32_t)((dyL*10 + xL)*80 + kAL) + (uint32_t)warp_m*3200u;
    const int colL = (lane & 7) + ((lane & 16) ? 8 : 0);
    const int kBL  = (lane & 8) ? 16 : 0;
    const uint32_t boffL = (uint32_t)((warp_n*32 + colL)*80 + kBL);

    float acc[2][NNF][4];
#pragma unroll
    for (int i = 0; i < 2; i++)
#pragma unroll
        for (int j = 0; j < NNF; j++)
#pragma unroll
            for (int k = 0; k < 4; k++) acc[i][j][k] = 0.f;

    const int niter = nchunk * 9;
    const int nwin  = niter >> 1;

    // prologue: A(chunk0) + B(0)->s0 + B(1)->s1, one group
    loadA98(sbase, 0, inA, inB, 0, b, x0, y0, tid);
    loadB(smB, wpack, 0, tid);
    loadB(smB, wpack, 1, tid);
    asm volatile("cp.async.commit_group;");

    for (int w = 0; w < nwin; w++) {
        const int i0 = w * 2;

        asm volatile("cp.async.wait_group 0;");   // group(w-1): data for i0, i0+1
        __syncthreads();                          // publish + WAR

        if (i0 + 2 < niter) loadB(smB, wpack, i0 + 2, tid);
        if (i0 + 3 < niter) loadB(smB, wpack, i0 + 3, tid);
#pragma unroll
        for (int j = 0; j < 2; j++) {
            const int i = i0 + j;
            if (i % 9 == 2 && i / 9 + 1 < nchunk)
                loadA98(sbase, (i/9 + 1) & 1, inA, inB, i/9 + 1, b, x0, y0, tid);
        }
        asm volatile("cp.async.commit_group;");

#pragma unroll
        for (int j = 0; j < 2; j++) {
            const int i  = i0 + j;
            const int cb = i / 9;
            const int tap = i - cb * 9;
            const int ky = tap / 3, kx = tap % 3;
            const uint32_t abase  = sbase + (uint32_t)(cb & 1) * SMA_BUF;
            const uint32_t bstage = smB + (uint32_t)(i & 3) * SMBX_ST;
            const uint32_t atap   = abase + aoffL + (uint32_t)((ky*10 + kx)*80);

#pragma unroll
            for (int ks = 0; ks < 2; ks++) {
                uint32_t bh[2][4], bl[2][4];
#pragma unroll
                for (int nfp = 0; nfp < 2; nfp++) {
                    uint32_t ba = bstage + boffL + (uint32_t)(nfp*16*80 + ks*32);
                    ldsm_x4(bh[nfp], ba);
                    ldsm_x4(bl[nfp], ba + 10240u);
                }
#pragma unroll
                for (int mf = 0; mf < 2; mf++) {
                    uint32_t ar = atap + (uint32_t)(mf*1600 + ks*32);
                    uint32_t ah[4], al[4];
                    ldsm_x4(ah, ar);
                    ldsm_x4(al, ar + 8000u);
#pragma unroll
                    for (int nf = 0; nf < NNF; nf++) {
                        const uint32_t* bhp = &bh[nf >> 1][(nf & 1) * 2];
                        const uint32_t* blp = &bl[nf >> 1][(nf & 1) * 2];
                        mma_bf16(acc[mf][nf], ah, bhp);
                        mma_bf16(acc[mf][nf], ah, blp);
                        mma_bf16(acc[mf][nf], al, bhp);
                    }
                }
            }
        }
    }

    // ---- epilogue ----
    const int xr = lane >> 2;
#pragma unroll
    for (int nf = 0; nf < NNF; nf++) {
        int co_t = warp_n*32 + nf*8 + (lane & 3)*2;
        int co_a;
        if (NNF == 3) co_a = co0 + (co_t >> 5)*24 + (co_t & 31);   // remapped rows
        else          co_a = co0 + co_t;
        const int co_b = co_a + 1;
        const float ba_ = (co_a < COUT) ? bias[co_a] : 0.f;
        const float bb_ = (co_b < COUT) ? bias[co_b] : 0.f;
#pragma unroll
        for (int mf = 0; mf < 2; mf++) {
            const int ya = y0 + warp_m*4 + mf*2;
            float v0 = acc[mf][nf][0] + ba_;
            float v1 = acc[mf][nf][1] + bb_;
            float v2 = acc[mf][nf][2] + ba_;
            float v3 = acc[mf][nf][3] + bb_;
            if (RELU) {
                v0 = fmaxf(v0, 0.f); v1 = fmaxf(v1, 0.f);
                v2 = fmaxf(v2, 0.f); v3 = fmaxf(v3, 0.f);
            }
            if (OUTFMT == 1) {
                size_t o1 = (size_t)b*PXB98
                          + (size_t)((ya+1)*98 + x0 + xr + 1)*128 + (co_a - co0);
                size_t o2 = o1 + 98*128;
                __nv_bfloat16 h0 = __float2bfloat16(v0);
                __nv_bfloat16 h1 = __float2bfloat16(v1);
                __nv_bfloat16 h2 = __float2bfloat16(v2);
                __nv_bfloat16 h3 = __float2bfloat16(v3);
                *(uint32_t*)&out_b[o1] = (uint32_t)*(uint16_t*)&h0 | ((uint32_t)*(uint16_t*)&h1 << 16);
                *(uint32_t*)&out_b[o2] = (uint32_t)*(uint16_t*)&h2 | ((uint32_t)*(uint16_t*)&h3 << 16);
                __nv_bfloat16 l0 = __float2bfloat16(v0 - __bfloat162float(h0));
                __nv_bfloat16 l1 = __float2bfloat16(v1 - __bfloat162float(h1));
                __nv_bfloat16 l2 = __float2bfloat16(v2 - __bfloat162float(h2));
                __nv_bfloat16 l3 = __float2bfloat16(v3 - __bfloat162float(h3));
                *(uint32_t*)&out_b[o1 + PLANE98] = (uint32_t)*(uint16_t*)&l0 | ((uint32_t)*(uint16_t*)&l1 << 16);
                *(uint32_t*)&out_b[o2 + PLANE98] = (uint32_t)*(uint16_t*)&l2 | ((uint32_t)*(uint16_t*)&l3 << 16);
            } else {
                if (co_a < COUT) {
                    out_f[((size_t)(b*COUT + co_a)*HH + ya    )*WW + x0 + xr] = v0;
                    out_f[((size_t)(b*COUT + co_a)*HH + ya + 1)*WW + x0 + xr] = v2;
                }
                if (co_b < COUT) {
                    out_f[((size_t)(b*COUT + co_b)*HH + ya    )*WW + x0 + xr] = v1;
                    out_f[((size_t)(b*COUT + co_b)*HH + ya + 1)*WW + x0 + xr] = v3;
                }
            }
        }
    }
}

// ============================================================================
// DCNv2: software-pipelined sampling + quad-shfl param dedup (R15-verbatim).
// ============================================================================
#define DCN_A_ST  6144
#define DCN_WT    12288
#define DCN_WT_ST 12288
#define DCN_SMEM  (12288 + 3*12288)   // 49152

__global__ __launch_bounds__(256, 2)
void dcnMMA_k(const float* __restrict__ R1px, const float* __restrict__ om,
              const float* __restrict__ wtp, const float* __restrict__ bias,
              __nv_bfloat16* __restrict__ feap)
{
    extern __shared__ char sm[];
    const int tid    = threadIdx.x;
    const int lane   = tid & 31;
    const int wid    = tid >> 5;
    const int warp_m = wid & 1;
    const int warp_n = wid >> 1;
    const int x0     = blockIdx.x * 8;
    const int y0     = blockIdx.y * 8;
    const int b      = blockIdx.z;

    const uint32_t sbase = smem_u32(sm);
    const uint32_t smWT  = sbase + DCN_WT;

    const int px_s = tid >> 2;
    const int cq   = tid & 3;
    const int hs   = y0 + (px_s >> 3);
    const int gxs  = x0 + (px_s & 7);
    const unsigned srcl = (unsigned)(lane & ~3);
    const int obase = (b*216)*HW + hs*WW + gxs;

    const uint32_t aoffL = (uint32_t)((lane & 15) * 48 + ((lane & 16) ? 16 : 0))
                         + (uint32_t)warp_m * (32*48);
    const int colL = (lane & 7) + ((lane & 16) ? 8 : 0);
    const int kBL  = (lane & 8) ? 16 : 0;
    const uint32_t boffL = (uint32_t)((warp_n*32 + colL)*48 + kBL);

    float acc[2][4][4];
#pragma unroll
    for (int i = 0; i < 2; i++)
#pragma unroll
        for (int j = 0; j < 4; j++)
#pragma unroll
            for (int k = 0; k < 4; k++) acc[i][j][k] = 0.f;

#pragma unroll
    for (int it = 0; it < 2; it++) {
        const char* src = (const char*)wtp + (size_t)it * 12288;
        uint32_t dstb = smWT + (uint32_t)it * DCN_WT_ST;
#pragma unroll
        for (int i = 0; i < 3; i++)
            cp_async16(dstb + (uint32_t)(tid + i*256)*16u, src + (tid + i*256)*16);
        asm volatile("cp.async.commit_group;");
    }

    float om_dy = 0.f, om_dx = 0.f, om_mr = 0.f;
    if (cq == 0) {
        om_dy = om[obase + (18*0 + 2*0    ) * HW];
        om_dx = om[obase + (18*0 + 2*0 + 1) * HW];
        om_mr = om[obase + (144 + 9*0 + 0 ) * HW];
    }

    // full sample(0) + STS stage 0
    {
        float w00, w01, w10, w11; int yi, xi;
        if (cq == 0) {
            float m  = 1.f / (1.f + __expf(-om_mr));
            float py  = om_dy + (float)(0 + hs - 1);
            float pxx = om_dx + (float)(0 + gxs - 1);
            float fy = floorf(py), fx = floorf(pxx);
            float ly = py - fy,  lx = pxx - fx;
            yi = (int)fy; xi = (int)fx;
            w00 = (1.f-ly)*(1.f-lx)*m; w01 = (1.f-ly)*lx*m;
            w10 = ly*(1.f-lx)*m;       w11 = ly*lx*m;
        }
        w00 = __shfl_sync(0xffffffffu, w00, srcl);
        w01 = __shfl_sync(0xffffffffu, w01, srcl);
        w10 = __shfl_sync(0xffffffffu, w10, srcl);
        w11 = __shfl_sync(0xffffffffu, w11, srcl);
        yi  = __shfl_sync(0xffffffffu, yi,  srcl);
        xi  = __shfl_sync(0xffffffffu, xi,  srcl);
        bool iy0 = (unsigned)yi < HH, iy1 = (unsigned)(yi+1) < HH;
        bool ix0 = (unsigned)xi < WW, ix1 = (unsigned)(xi+1) < WW;
        const float* pg = R1px + (size_t)b*HW*128 + 0*16 + cq*4;
        float4 z = make_float4(0.f,0.f,0.f,0.f);
        float4 a00 = (iy0&&ix0) ? *(const float4*)(pg + (size_t)(yi*WW+xi)*128)       : z;
        float4 a01 = (iy0&&ix1) ? *(const float4*)(pg + (size_t)(yi*WW+xi+1)*128)     : z;
        float4 a10 = (iy1&&ix0) ? *(const float4*)(pg + (size_t)((yi+1)*WW+xi)*128)   : z;
        float4 a11 = (iy1&&ix1) ? *(const float4*)(pg + (size_t)((yi+1)*WW+xi+1)*128) : z;
        float vv0 = w00*a00.x + w01*a01.x + w10*a10.x + w11*a11.x;
        float vv1 = w00*a00.y + w01*a01.y + w10*a10.y + w11*a11.y;
        float vv2 = w00*a00.z + w01*a01.z + w10*a10.z + w11*a11.z;
        float vv3 = w00*a00.w + w01*a01.w + w10*a10.w + w11*a11.w;
        __nv_bfloat16 h0=__float2bfloat16(vv0), h1=__float2bfloat16(vv1);
        __nv_bfloat16 h2=__float2bfloat16(vv2), h3=__float2bfloat16(vv3);
        uint32_t hp0 = (uint32_t)*(uint16_t*)&h0 | ((uint32_t)*(uint16_t*)&h1 << 16);
        uint32_t hp1 = (uint32_t)*(uint16_t*)&h2 | ((uint32_t)*(uint16_t*)&h3 << 16);
        __nv_bfloat16 l0=__float2bfloat16(vv0-__bfloat162float(h0));
        __nv_bfloat16 l1=__float2bfloat16(vv1-__bfloat162float(h1));
        __nv_bfloat16 l2=__float2bfloat16(vv2-__bfloat162float(h2));
        __nv_bfloat16 l3=__float2bfloat16(vv3-__bfloat162float(h3));
        uint32_t lp0 = (uint32_t)*(uint16_t*)&l0 | ((uint32_t)*(uint16_t*)&l1 << 16);
        uint32_t lp1 = (uint32_t)*(uint16_t*)&l2 | ((uint32_t)*(uint16_t*)&l3 << 16);
        *(uint2*)(sm +        px_s*48 + cq*8) = make_uint2(hp0, hp1);
        *(uint2*)(sm + 3072 + px_s*48 + cq*8) = make_uint2(lp0, lp1);
    }
    if (cq == 0) {
        om_dy = om[obase + (18*0 + 2*1    ) * HW];
        om_dx = om[obase + (18*0 + 2*1 + 1) * HW];
        om_mr = om[obase + (144 + 9*0 + 1 ) * HW];
    }

    for (int iter = 0; iter < 72; iter++) {
        float w00, w01, w10, w11;
        float4 a00, a01, a10, a11;
        const int in1 = iter + 1;
        if (in1 < 72) {
            const int g1 = in1 / 9;
            const int k1 = in1 - g1 * 9;
            int yi, xi;
            if (cq == 0) {
                float m  = 1.f / (1.f + __expf(-om_mr));
                float py  = om_dy + (float)(k1/3 + hs - 1);
                float pxx = om_dx + (float)(k1%3 + gxs - 1);
                float fy = floorf(py), fx = floorf(pxx);
                float ly = py - fy,  lx = pxx - fx;
                yi = (int)fy; xi = (int)fx;
                w00 = (1.f-ly)*(1.f-lx)*m; w01 = (1.f-ly)*lx*m;
                w10 = ly*(1.f-lx)*m;       w11 = ly*lx*m;
            }
            w00 = __shfl_sync(0xffffffffu, w00, srcl);
            w01 = __shfl_sync(0xffffffffu, w01, srcl);
            w10 = __shfl_sync(0xffffffffu, w10, srcl);
            w11 = __shfl_sync(0xffffffffu, w11, srcl);
            yi  = __shfl_sync(0xffffffffu, yi,  srcl);
            xi  = __shfl_sync(0xffffffffu, xi,  srcl);
            bool iy0 = (unsigned)yi < HH, iy1 = (unsigned)(yi+1) < HH;
            bool ix0 = (unsigned)xi < WW, ix1 = (unsigned)(xi+1) < WW;
            const float* pg = R1px + (size_t)b*HW*128 + g1*16 + cq*4;
            float4 z = make_float4(0.f,0.f,0.f,0.f);
            a00 = (iy0&&ix0) ? *(const float4*)(pg + (size_t)(yi*WW+xi)*128)       : z;
            a01 = (iy0&&ix1) ? *(const float4*)(pg + (size_t)(yi*WW+xi+1)*128)     : z;
            a10 = (iy1&&ix0) ? *(const float4*)(pg + (size_t)((yi+1)*WW+xi)*128)   : z;
            a11 = (iy1&&ix1) ? *(const float4*)(pg + (size_t)((yi+1)*WW+xi+1)*128) : z;
            const int in2 = iter + 2;
            if (in2 < 72 && cq == 0) {
                const int g2 = in2 / 9;
                const int k2 = in2 - g2 * 9;
                om_dy = om[obase + (18*g2 + 2*k2    ) * HW];
                om_dx = om[obase + (18*g2 + 2*k2 + 1) * HW];
                om_mr = om[obase + (144 + 9*g2 + k2 ) * HW];
            }
        }

        asm volatile("cp.async.wait_group 1;");
        __syncthreads();

        if (iter + 2 < 72) {
            const char* src = (const char*)wtp + (size_t)(iter + 2) * 12288;
            uint32_t dstb = smWT + (uint32_t)((iter + 2) % 3) * DCN_WT_ST;
#pragma unroll
            for (int i = 0; i < 3; i++)
                cp_async16(dstb + (uint32_t)(tid + i*256)*16u, src + (tid + i*256)*16);
        }
        asm volatile("cp.async.commit_group;");

        const uint32_t astage = sbase + (uint32_t)(iter & 1) * DCN_A_ST;
        const uint32_t wstage = smWT + (uint32_t)(iter % 3) * DCN_WT_ST;

        uint32_t bh[2][4], bl[2][4];
#pragma unroll
        for (int nfp = 0; nfp < 2; nfp++) {
            uint32_t ba = wstage + boffL + (uint32_t)(nfp*16*48);
            ldsm_x4(bh[nfp], ba);
            ldsm_x4(bl[nfp], ba + 6144u);
        }
#pragma unroll
        for (int mf = 0; mf < 2; mf++) {
            uint32_t ar = aoffL + astage + (uint32_t)(mf*16*48);
            uint32_t ah[4], al[4];
            ldsm_x4(ah, ar);
            ldsm_x4(al, ar + 3072u);
#pragma unroll
            for (int nf = 0; nf < 4; nf++) {
                const uint32_t* bhp = &bh[nf >> 1][(nf & 1) * 2];
                const uint32_t* blp = &bl[nf >> 1][(nf & 1) * 2];
                mma_bf16(acc[mf][nf], ah, bhp);
                mma_bf16(acc[mf][nf], ah, blp);
                mma_bf16(acc[mf][nf], al, bhp);
            }
        }

        if (in1 < 72) {
            float vv0 = w00*a00.x + w01*a01.x + w10*a10.x + w11*a11.x;
            float vv1 = w00*a00.y + w01*a01.y + w10*a10.y + w11*a11.y;
            float vv2 = w00*a00.z + w01*a01.z + w10*a10.z + w11*a11.z;
            float vv3 = w00*a00.w + w01*a01.w + w10*a10.w + w11*a11.w;
            __nv_bfloat16 h0=__float2bfloat16(vv0), h1=__float2bfloat16(vv1);
            __nv_bfloat16 h2=__float2bfloat16(vv2), h3=__float2bfloat16(vv3);
            uint32_t hp0 = (uint32_t)*(uint16_t*)&h0 | ((uint32_t)*(uint16_t*)&h1 << 16);
            uint32_t hp1 = (uint32_t)*(uint16_t*)&h2 | ((uint32_t)*(uint16_t*)&h3 << 16);
            __nv_bfloat16 l0=__float2bfloat16(vv0-__bfloat162float(h0));
            __nv_bfloat16 l1=__float2bfloat16(vv1-__bfloat162float(h1));
            __nv_bfloat16 l2=__float2bfloat16(vv2-__bfloat162float(h2));
            __nv_bfloat16 l3=__float2bfloat16(vv3-__bfloat162float(h3));
            uint32_t lp0 = (uint32_t)*(uint16_t*)&l0 | ((uint32_t)*(uint16_t*)&l1 << 16);
            uint32_t lp1 = (uint32_t)*(uint16_t*)&l2 | ((uint32_t)*(uint16_t*)&l3 << 16);
            char* asb = sm + (in1 & 1) * DCN_A_ST;
            *(uint2*)(asb +        px_s*48 + cq*8) = make_uint2(hp0, hp1);
            *(uint2*)(asb + 3072 + px_s*48 + cq*8) = make_uint2(lp0, lp1);
        }
    }

    // ---- epilogue: bias + relu -> padded px-major bf16 hi/lo ----
    const int r0 = warp_m*32 + (lane >> 2);
#pragma unroll
    for (int nf = 0; nf < 4; nf++) {
        const int co_a = warp_n*32 + nf*8 + (lane & 3)*2;
        const float ba_ = bias[co_a];
        const float bb_ = bias[co_a + 1];
#pragma unroll
        for (int mf = 0; mf < 2; mf++) {
            const int p1 = r0 + mf*16;
            const int p2 = p1 + 8;
            const int y1 = y0 + (p1 >> 3), x1 = x0 + (p1 & 7);
            const int y2 = y0 + (p2 >> 3), x2 = x0 + (p2 & 7);
            float v0 = fmaxf(acc[mf][nf][0] + ba_, 0.f);
            float v1 = fmaxf(acc[mf][nf][1] + bb_, 0.f);
            float v2 = fmaxf(acc[mf][nf][2] + ba_, 0.f);
            float v3 = fmaxf(acc[mf][nf][3] + bb_, 0.f);
            size_t o1 = (size_t)b*PXB98 + (size_t)((y1+1)*98 + x1 + 1)*128 + co_a;
            size_t o2 = (size_t)b*PXB98 + (size_t)((y2+1)*98 + x2 + 1)*128 + co_a;
            __nv_bfloat16 h0 = __float2bfloat16(v0);
            __nv_bfloat16 h1 = __float2bfloat16(v1);
            __nv_bfloat16 h2 = __float2bfloat16(v2);
            __nv_bfloat16 h3 = __float2bfloat16(v3);
            *(uint32_t*)&feap[o1] = (uint32_t)*(uint16_t*)&h0 | ((uint32_t)*(uint16_t*)&h1 << 16);
            *(uint32_t*)&feap[o2] = (uint32_t)*(uint16_t*)&h2 | ((uint32_t)*(uint16_t*)&h3 << 16);
            __nv_bfloat16 l0 = __float2bfloat16(v0 - __bfloat162float(h0));
            __nv_bfloat16 l1 = __float2bfloat16(v1 - __bfloat162float(h1));
            __nv_bfloat16 l2 = __float2bfloat16(v2 - __bfloat162float(h2));
            __nv_bfloat16 l3 = __float2bfloat16(v3 - __bfloat162float(h3));
            *(uint32_t*)&feap[o1 + PLANE98] = (uint32_t)*(uint16_t*)&l0 | ((uint32_t)*(uint16_t*)&l1 << 16);
            *(uint32_t*)&feap[o2 + PLANE98] = (uint32_t)*(uint16_t*)&l2 | ((uint32_t)*(uint16_t*)&l3 << 16);
        }
    }
}

// ============================================================================
extern "C" void kernel_launch(void* const* d_in, const int* in_sizes, int n_in,
                              void* d_out, int out_size)
{
    (void)in_sizes; (void)n_in; (void)out_size;
    const float* R1    = (const float*)d_in[0];
    const float* Q0    = (const float*)d_in[1];
    const float* w1    = (const float*)d_in[2];
    const float* b1    = (const float*)d_in[3];
    const float* w2    = (const float*)d_in[4];
    const float* b2    = (const float*)d_in[5];
    const float* w_om  = (const float*)d_in[6];
    const float* b_om  = (const float*)d_in[7];
    const float* w_dcn = (const float*)d_in[8];
    const float* b_dcn = (const float*)d_in[9];
    const float* w_rq  = (const float*)d_in[10];
    const float* b_rq  = (const float*)d_in[11];
    float* out = (float*)d_out;

    float *om, *wp1, *wp2, *wpom, *wprq, *wtp, *dinf, *t1f, *t2f, *q0f, *feaf, *r1px;
    cudaGetSymbolAddress((void**)&om,   g_om);
    cudaGetSymbolAddress((void**)&wp1,  g_wp1);
    cudaGetSymbolAddress((void**)&wp2,  g_wp2);
    cudaGetSymbolAddress((void**)&wpom, g_wpom);
    cudaGetSymbolAddress((void**)&wprq, g_wprq);
    cudaGetSymbolAddress((void**)&wtp,  g_wtp);
    cudaGetSymbolAddress((void**)&dinf, g_din98);
    cudaGetSymbolAddress((void**)&t1f,  g_t1b98);
    cudaGetSymbolAddress((void**)&t2f,  g_t2b98);
    cudaGetSymbolAddress((void**)&q0f,  g_q098);
    cudaGetSymbolAddress((void**)&feaf, g_fea98);
    cudaGetSymbolAddress((void**)&r1px, g_R1px);
    __nv_bfloat16* din  = (__nv_bfloat16*)dinf;
    __nv_bfloat16* t1b  = (__nv_bfloat16*)t1f;
    __nv_bfloat16* t2b  = (__nv_bfloat16*)t2f;
    __nv_bfloat16* q0p  = (__nv_bfloat16*)q0f;
    __nv_bfloat16* feap = (__nv_bfloat16*)feaf;

    cudaFuncSetAttribute(convPX_k<true ,1,4>, cudaFuncAttributeMaxDynamicSharedMemorySize, CONVPX_SMEM);
    cudaFuncSetAttribute(convPX_k<false,0,4>, cudaFuncAttributeMaxDynamicSharedMemorySize, CONVPX_SMEM);
    cudaFuncSetAttribute(convPX_k<false,0,3>, cudaFuncAttributeMaxDynamicSharedMemorySize, CONVPX_SMEM);
    cudaFuncSetAttribute(convPX_k<true ,0,4>, cudaFuncAttributeMaxDynamicSharedMemorySize, CONVPX_SMEM);
    cudaFuncSetAttribute(dcnMMA_k, cudaFuncAttributeMaxDynamicSharedMemorySize, DCN_SMEM);

    // all prep in one launch
    prepack_all_k<<<884, 256>>>(R1, Q0, w1, w2, w_om, w_rq, w_dcn,
                                wp1, wp2, wpom, wprq, wtp,
                                din, t1b, t2b, q0p, feap, r1px);

    // conv1: relu(conv(R1-Q0)) -> t1 (px-major bf16)
    convPX_k<true ,1,4><<<dim3(12,12,2), 256, CONVPX_SMEM>>>(din, din, wp1, b1, nullptr, t1b, 128, 0, 4);
    // conv2: relu(conv(t1)) -> t2 (px-major bf16)
    convPX_k<true ,1,4><<<dim3(12,12,2), 256, CONVPX_SMEM>>>(t1b, t1b, wp2, b2, nullptr, t2b, 128, 0, 4);
    // conv_om tile0: co 0-127
    convPX_k<false,0,4><<<dim3(12,12,2), 256, CONVPX_SMEM>>>(t2b, t2b, wpom, b_om, om, nullptr, 216, 0, 4);
    // conv_om tile1: co 128-215 (remapped rows, 25% fewer MMAs)
    convPX_k<false,0,3><<<dim3(12,12,2), 256, CONVPX_SMEM>>>(t2b, t2b, wpom + 36*5120, b_om, om, nullptr, 216, 128, 4);
    // deformable conv v2 + relu -> fea (px-major bf16)
    dcnMMA_k<<<dim3(12,12,2), 256, DCN_SMEM>>>(r1px, om, wtp, b_dcn, feap);
    // conv_rq: relu(conv(concat(fea, Q0))) -> out (fp32 planar)
    convPX_k<true ,0,4><<<dim3(12,12,2), 256, CONVPX_SMEM>>>(feap, q0p, wprq, b_rq, out, nullptr, 128, 0, 8);
}